// round 1
// baseline (speedup 1.0000x reference)
#include <cuda_runtime.h>
#include <math.h>

#define H   1024
#define H3  3072
#define NREL 4096
#define NATT 4096
#define NCL  8192
#define V    256

// ---------------- scratch (device globals; no allocations) ----------------
__device__ float g_emb_proj[V * H];
__device__ float g_gi_table[V * H3];
__device__ float g_gh1[H3];
__device__ float g_h1[V * H];
__device__ float g_gh2[V * H3];
__device__ float g_h2rel[NREL * H];
__device__ float g_gh3[NREL * H3];
__device__ float g_clause[NCL * H];
__device__ float g_x1[NCL * H];
__device__ float g_x2[NCL * H];
__device__ float g_logits[NCL];

// ---------------- fp32 NT SGEMM: C[M,N] = A[M,K] @ B[N,K]^T + bias ----------------
// 128x128 block, BK=16, 256 threads, 8x8 per thread. Requires M%128==0, N%128==0, K%16==0.
template <bool RELU>
__global__ void __launch_bounds__(256)
sgemm_nt(const float* __restrict__ A, const float* __restrict__ B,
         const float* __restrict__ bias, float* __restrict__ C,
         int M, int N, int K)
{
    __shared__ float As[16][128];
    __shared__ float Bs[16][128];

    const int bm  = blockIdx.y * 128;
    const int bn  = blockIdx.x * 128;
    const int tid = threadIdx.x;
    const int tx  = tid & 15;    // 0..15 -> n
    const int ty  = tid >> 4;    // 0..15 -> m
    const int lrow = tid >> 1;        // 0..127
    const int lk   = (tid & 1) * 8;   // 0 or 8

    const float* Ap = A + (size_t)(bm + lrow) * K + lk;
    const float* Bp = B + (size_t)(bn + lrow) * K + lk;

    float acc[8][8];
#pragma unroll
    for (int i = 0; i < 8; i++)
#pragma unroll
        for (int j = 0; j < 8; j++) acc[i][j] = 0.f;

    for (int k0 = 0; k0 < K; k0 += 16) {
        float4 a0 = *(const float4*)(Ap + k0);
        float4 a1 = *(const float4*)(Ap + k0 + 4);
        float4 b0 = *(const float4*)(Bp + k0);
        float4 b1 = *(const float4*)(Bp + k0 + 4);
        __syncthreads();
        As[lk + 0][lrow] = a0.x; As[lk + 1][lrow] = a0.y;
        As[lk + 2][lrow] = a0.z; As[lk + 3][lrow] = a0.w;
        As[lk + 4][lrow] = a1.x; As[lk + 5][lrow] = a1.y;
        As[lk + 6][lrow] = a1.z; As[lk + 7][lrow] = a1.w;
        Bs[lk + 0][lrow] = b0.x; Bs[lk + 1][lrow] = b0.y;
        Bs[lk + 2][lrow] = b0.z; Bs[lk + 3][lrow] = b0.w;
        Bs[lk + 4][lrow] = b1.x; Bs[lk + 5][lrow] = b1.y;
        Bs[lk + 6][lrow] = b1.z; Bs[lk + 7][lrow] = b1.w;
        __syncthreads();
#pragma unroll
        for (int kk = 0; kk < 16; kk++) {
            float4 av0 = *(const float4*)&As[kk][ty * 4];
            float4 av1 = *(const float4*)&As[kk][ty * 4 + 64];
            float4 bv0 = *(const float4*)&Bs[kk][tx * 4];
            float4 bv1 = *(const float4*)&Bs[kk][tx * 4 + 64];
            float am[8] = {av0.x, av0.y, av0.z, av0.w, av1.x, av1.y, av1.z, av1.w};
            float bb[8] = {bv0.x, bv0.y, bv0.z, bv0.w, bv1.x, bv1.y, bv1.z, bv1.w};
#pragma unroll
            for (int i = 0; i < 8; i++)
#pragma unroll
                for (int j = 0; j < 8; j++)
                    acc[i][j] = fmaf(am[i], bb[j], acc[i][j]);
        }
    }

#pragma unroll
    for (int i = 0; i < 8; i++) {
        int m = bm + ((i < 4) ? (ty * 4 + i) : (64 + ty * 4 + (i - 4)));
#pragma unroll
        for (int g = 0; g < 2; g++) {
            int c = bn + g * 64 + tx * 4;
            float4 v;
            v.x = acc[i][g * 4 + 0] + bias[c + 0];
            v.y = acc[i][g * 4 + 1] + bias[c + 1];
            v.z = acc[i][g * 4 + 2] + bias[c + 2];
            v.w = acc[i][g * 4 + 3] + bias[c + 3];
            if (RELU) {
                v.x = fmaxf(v.x, 0.f); v.y = fmaxf(v.y, 0.f);
                v.z = fmaxf(v.z, 0.f); v.w = fmaxf(v.w, 0.f);
            }
            *(float4*)(C + (size_t)m * N + c) = v;
        }
    }
}

// ---------------- GEMV: out[n] = dot(x, W[n,:]) + b[n], warp per output row ----------------
__global__ void gemv_rows(const float* __restrict__ x, const float* __restrict__ W,
                          const float* __restrict__ b, float* __restrict__ out, int Nout)
{
    int n = blockIdx.x * 8 + (threadIdx.x >> 5);
    if (n >= Nout) return;
    int lane = threadIdx.x & 31;
    const float* w = W + (size_t)n * H;
    float s = 0.f;
#pragma unroll
    for (int k = lane * 4; k < H; k += 128) {
        float4 wv = *(const float4*)(w + k);
        float4 xv = *(const float4*)(x + k);
        s = fmaf(wv.x, xv.x, s); s = fmaf(wv.y, xv.y, s);
        s = fmaf(wv.z, xv.z, s); s = fmaf(wv.w, xv.w, s);
    }
#pragma unroll
    for (int o = 16; o; o >>= 1) s += __shfl_xor_sync(0xffffffffu, s, o);
    if (lane == 0) out[n] = s + b[n];
}

// logits[n] = dot(X[n,:], w3) + b3[0], warp per clause row
__global__ void logits_kernel(const float* __restrict__ X, const float* __restrict__ w3,
                              const float* __restrict__ b3)
{
    int n = blockIdx.x * 8 + (threadIdx.x >> 5);
    int lane = threadIdx.x & 31;
    const float* x = X + (size_t)n * H;
    float s = 0.f;
#pragma unroll
    for (int k = lane * 4; k < H; k += 128) {
        float4 xv = *(const float4*)(x + k);
        float4 wv = *(const float4*)(w3 + k);
        s = fmaf(wv.x, xv.x, s); s = fmaf(wv.y, xv.y, s);
        s = fmaf(wv.z, xv.z, s); s = fmaf(wv.w, xv.w, s);
    }
#pragma unroll
    for (int o = 16; o; o >>= 1) s += __shfl_xor_sync(0xffffffffu, s, o);
    if (lane == 0) g_logits[n] = s + b3[0];
}

// ---------------- GRU combine ----------------
__device__ __forceinline__ float gru1(float ir, float iz, float inn,
                                      float hr, float hz, float hn, float h)
{
    float r = 1.f / (1.f + __expf(-(ir + hr)));
    float z = 1.f / (1.f + __expf(-(iz + hz)));
    float n = tanhf(fmaf(r, hn, inn));
    return fmaf(z, h - n, n);   // (1-z)*n + z*h
}

__device__ __forceinline__ float4 gru4(const float* __restrict__ gi,
                                       const float* __restrict__ gh,
                                       const float* __restrict__ h, int j)
{
    float4 ir  = *(const float4*)(gi + j);
    float4 iz  = *(const float4*)(gi + H + j);
    float4 inn = *(const float4*)(gi + 2 * H + j);
    float4 hr  = *(const float4*)(gh + j);
    float4 hz  = *(const float4*)(gh + H + j);
    float4 hn  = *(const float4*)(gh + 2 * H + j);
    float4 hv  = *(const float4*)(h + j);
    float4 o;
    o.x = gru1(ir.x, iz.x, inn.x, hr.x, hz.x, hn.x, hv.x);
    o.y = gru1(ir.y, iz.y, inn.y, hr.y, hz.y, hn.y, hv.y);
    o.z = gru1(ir.z, iz.z, inn.z, hr.z, hz.z, hn.z, hv.z);
    o.w = gru1(ir.w, iz.w, inn.w, hr.w, hz.w, hn.w, hv.w);
    return o;
}

// step 1: h1_table[v] = GRU(gi_table[v], gh1, state) for all v in [0,256)
__global__ void gru_h1_kernel(const float* __restrict__ state)
{
    int v = blockIdx.x;
    int j = threadIdx.x * 4;
    *(float4*)(g_h1 + v * H + j) = gru4(g_gi_table + v * H3, g_gh1, state, j);
}

// step 2: out[n] = GRU(gi_table[t1], gh2_table[t0], h1_table[t0])
__global__ void gru_step2_kernel(const int* __restrict__ tokens, int stride,
                                 float* __restrict__ out)
{
    int n  = blockIdx.x;
    int t0 = tokens[n * stride + 0];
    int t1 = tokens[n * stride + 1];
    int j  = threadIdx.x * 4;
    *(float4*)(out + (size_t)n * H + j) =
        gru4(g_gi_table + t1 * H3, g_gh2 + t0 * H3, g_h1 + t0 * H, j);
}

// step 3 (rel only): clause[n] = GRU(gi_table[t2], gh3[n], h2rel[n])
__global__ void gru_step3_kernel(const int* __restrict__ rel_tokens)
{
    int n  = blockIdx.x;
    int t2 = rel_tokens[n * 3 + 2];
    int j  = threadIdx.x * 4;
    *(float4*)(g_clause + (size_t)n * H + j) =
        gru4(g_gi_table + t2 * H3, g_gh3 + (size_t)n * H3, g_h2rel + (size_t)n * H, j);
}

// ---------------- softmax over 8192 logits with eps smoothing ----------------
__global__ void softmax_kernel(const float* __restrict__ eps, float* __restrict__ out)
{
    const int N = NCL;
    __shared__ float shm[32];
    __shared__ float shs[32];
    int tid = threadIdx.x;

    float m = -1e30f;
    for (int i = tid; i < N; i += 1024) m = fmaxf(m, g_logits[i]);
#pragma unroll
    for (int o = 16; o; o >>= 1) m = fmaxf(m, __shfl_xor_sync(0xffffffffu, m, o));
    if ((tid & 31) == 0) shm[tid >> 5] = m;
    __syncthreads();
    if (tid < 32) {
        float v = shm[tid];
#pragma unroll
        for (int o = 16; o; o >>= 1) v = fmaxf(v, __shfl_xor_sync(0xffffffffu, v, o));
        shm[tid] = v;
    }
    __syncthreads();
    float M = shm[0];

    float s = 0.f;
    for (int i = tid; i < N; i += 1024) s += __expf(g_logits[i] - M);
#pragma unroll
    for (int o = 16; o; o >>= 1) s += __shfl_xor_sync(0xffffffffu, s, o);
    if ((tid & 31) == 0) shs[tid >> 5] = s;
    __syncthreads();
    if (tid < 32) {
        float v = shs[tid];
#pragma unroll
        for (int o = 16; o; o >>= 1) v += __shfl_xor_sync(0xffffffffu, v, o);
        shs[tid] = v;
    }
    __syncthreads();
    float S = shs[0];
    float e = eps[0];
    float inv = (1.f - e) / S;
    float add = e / (float)N;
    for (int i = tid; i < N; i += 1024)
        out[i] = __expf(g_logits[i] - M) * inv + add;
}

// ---------------- launch ----------------
extern "C" void kernel_launch(void* const* d_in, const int* in_sizes, int n_in,
                              void* d_out, int out_size)
{
    const float* state       = (const float*)d_in[0];
    const int*   rel_tokens  = (const int*)d_in[1];
    const int*   attr_tokens = (const int*)d_in[2];
    const float* table       = (const float*)d_in[3];
    const float* W_emb       = (const float*)d_in[4];
    const float* b_emb       = (const float*)d_in[5];
    const float* W_ih        = (const float*)d_in[6];
    const float* W_hh        = (const float*)d_in[7];
    const float* b_ih        = (const float*)d_in[8];
    const float* b_hh        = (const float*)d_in[9];
    const float* W1          = (const float*)d_in[10];
    const float* b1          = (const float*)d_in[11];
    const float* W2          = (const float*)d_in[12];
    const float* b2          = (const float*)d_in[13];
    const float* W3          = (const float*)d_in[14];
    const float* b3          = (const float*)d_in[15];
    const float* eps         = (const float*)d_in[16];
    float* out = (float*)d_out;

    float *p_emb, *p_gi, *p_gh1, *p_h1, *p_gh2, *p_h2rel, *p_gh3, *p_clause, *p_x1, *p_x2;
    cudaGetSymbolAddress((void**)&p_emb,    g_emb_proj);
    cudaGetSymbolAddress((void**)&p_gi,     g_gi_table);
    cudaGetSymbolAddress((void**)&p_gh1,    g_gh1);
    cudaGetSymbolAddress((void**)&p_h1,     g_h1);
    cudaGetSymbolAddress((void**)&p_gh2,    g_gh2);
    cudaGetSymbolAddress((void**)&p_h2rel,  g_h2rel);
    cudaGetSymbolAddress((void**)&p_gh3,    g_gh3);
    cudaGetSymbolAddress((void**)&p_clause, g_clause);
    cudaGetSymbolAddress((void**)&p_x1,     g_x1);
    cudaGetSymbolAddress((void**)&p_x2,     g_x2);

    // 1. emb_proj[V,H] = table @ W_emb^T + b_emb
    sgemm_nt<false><<<dim3(H / 128, V / 128), 256>>>(table, W_emb, b_emb, p_emb, V, H, H);
    // 2. gi_table[V,3H] = emb_proj @ W_ih^T + b_ih
    sgemm_nt<false><<<dim3(H3 / 128, V / 128), 256>>>(p_emb, W_ih, b_ih, p_gi, V, H3, H);
    // 3. gh1[3H] = state @ W_hh^T + b_hh
    gemv_rows<<<H3 / 8, 256>>>(state, W_hh, b_hh, p_gh1, H3);
    // 4. h1_table[V,H]
    gru_h1_kernel<<<V, 256>>>(state);
    // 5. gh2_table[V,3H] = h1_table @ W_hh^T + b_hh
    sgemm_nt<false><<<dim3(H3 / 128, V / 128), 256>>>(p_h1, W_hh, b_hh, p_gh2, V, H3, H);
    // 6. h2_rel[Nr,H]   (rel step 2)
    gru_step2_kernel<<<NREL, 256>>>(rel_tokens, 3, p_h2rel);
    // 7. attr_h -> clause[4096..8191]   (attr step 2 == final attr output)
    gru_step2_kernel<<<NATT, 256>>>(attr_tokens, 2, p_clause + (size_t)NREL * H);
    // 8. gh3[Nr,3H] = h2_rel @ W_hh^T + b_hh  (the only per-row GRU GEMM)
    sgemm_nt<false><<<dim3(H3 / 128, NREL / 128), 256>>>(p_h2rel, W_hh, b_hh, p_gh3, NREL, H3, H);
    // 9. rel_h -> clause[0..4095]   (rel step 3)
    gru_step3_kernel<<<NREL, 256>>>(rel_tokens);
    // 10. x1 = relu(clause @ W1^T + b1)
    sgemm_nt<true><<<dim3(H / 128, NCL / 128), 256>>>(p_clause, W1, b1, p_x1, NCL, H, H);
    // 11. x2 = relu(x1 @ W2^T + b2)
    sgemm_nt<true><<<dim3(H / 128, NCL / 128), 256>>>(p_x1, W2, b2, p_x2, NCL, H, H);
    // 12. logits[n] = x2[n] . W3 + b3
    logits_kernel<<<NCL / 8, 256>>>(p_x2, W3, b3);
    // 13. softmax + eps smoothing -> out[1,8192]
    softmax_kernel<<<1, 1024>>>(eps, out);
}

// round 3
// speedup vs baseline: 2.1557x; 2.1557x over previous
#include <cuda_runtime.h>
#include <cuda_bf16.h>
#include <math.h>
#include <stdint.h>

#define H    1024
#define H3   3072
#define NREL 4096
#define NATT 4096
#define NCL  8192
#define V    256
#define K2   2048     // split row stride: hi[0:1024) | lo[1024:2048)

// ===================== scratch (device globals; no allocations) =====================
__device__ __align__(256) __nv_bfloat16 g2_table[V * K2];
__device__ __align__(256) __nv_bfloat16 g2_Wemb[H * K2];
__device__ __align__(256) __nv_bfloat16 g2_Wih[H3 * K2];
__device__ __align__(256) __nv_bfloat16 g2_Whh[H3 * K2];
__device__ __align__(256) __nv_bfloat16 g2_W1[H * K2];
__device__ __align__(256) __nv_bfloat16 g2_W2[H * K2];
__device__ __align__(256) __nv_bfloat16 g2_emb[V * K2];
__device__ __align__(256) __nv_bfloat16 g2_h1[V * K2];
__device__ __align__(256) __nv_bfloat16 g2_h2rel[NREL * K2];
__device__ __align__(256) __nv_bfloat16 g2_clause[NCL * K2];
__device__ __align__(256) __nv_bfloat16 g2_x1[NCL * K2];
__device__ float g_gi[V * H3];
__device__ float g_gh1[H3];
__device__ float g_h1[V * H];
__device__ float g_gh2[V * H3];
__device__ float g_h2rel[NREL * H];
__device__ float g_gh3[NREL * H3];
__device__ float g_x2[NCL * H];
__device__ float g_logits[NCL];

// ===================== PTX helpers (all valid at compute_103, no 'a' features) ============
__device__ __forceinline__ uint32_t smem_u32(const void* p) {
    uint32_t a;
    asm("{ .reg .u64 t; cvta.to.shared.u64 t, %1; cvt.u32.u64 %0, t; }" : "=r"(a) : "l"(p));
    return a;
}
__device__ __forceinline__ void cp16(uint32_t dst, const void* src) {
    asm volatile("cp.async.cg.shared.global [%0], [%1], 16;" :: "r"(dst), "l"(src));
}
__device__ __forceinline__ void cp_commit() {
    asm volatile("cp.async.commit_group;" ::: "memory");
}
template <int N>
__device__ __forceinline__ void cp_wait() {
    asm volatile("cp.async.wait_group %0;" :: "n"(N) : "memory");
}
__device__ __forceinline__ void ldm_x4(uint32_t& r0, uint32_t& r1, uint32_t& r2, uint32_t& r3,
                                       uint32_t addr) {
    asm volatile("ldmatrix.sync.aligned.m8n8.x4.shared.b16 {%0,%1,%2,%3}, [%4];"
                 : "=r"(r0), "=r"(r1), "=r"(r2), "=r"(r3) : "r"(addr));
}
__device__ __forceinline__ void mma16816(float* c, uint32_t a0, uint32_t a1, uint32_t a2,
                                         uint32_t a3, uint32_t b0, uint32_t b1) {
    asm volatile(
        "mma.sync.aligned.m16n8k16.row.col.f32.bf16.bf16.f32 "
        "{%0,%1,%2,%3}, {%4,%5,%6,%7}, {%8,%9}, {%0,%1,%2,%3};"
        : "+f"(c[0]), "+f"(c[1]), "+f"(c[2]), "+f"(c[3])
        : "r"(a0), "r"(a1), "r"(a2), "r"(a3), "r"(b0), "r"(b1));
}

// ===================== split-precision HMMA GEMM ==============================
// C[M,N] = A[M,1024] @ B[N,1024]^T + bias; A,B stored split bf16 [rows, 2048].
// 3 K-passes (hi*hi, hi*lo, lo*hi). CTA 128x128, BK=32, 4-stage cp.async pipeline.
#define APITCH   80                     // bytes per 32-elem bf16 row (64B data + 16B pad)
#define ATILE_B  (128 * APITCH)         // 10240
#define STAGE_B  (2 * ATILE_B)          // 20480 (A then B)
#define NSTAGE   4
#define SMEM_DYN_H (NSTAGE * STAGE_B)   // 81920
#define NIT      96                     // 3 passes * 32 chunks of K=32

__device__ __forceinline__ void cp_stage(const __nv_bfloat16* __restrict__ A,
                                         const __nv_bfloat16* __restrict__ B,
                                         int bm, int bn, uint32_t sbase, int tid,
                                         int it)
{
    const int pass = it >> 5, kk = (it & 31) * 32;
    const int ao = kk + (pass == 2 ? 1024 : 0);
    const int bo = kk + (pass == 1 ? 1024 : 0);
#pragma unroll
    for (int h = 0; h < 2; h++) {
        int c = tid + h * 256;          // 512 chunks of 16B for A
        int row = c >> 2, kc = c & 3;
        cp16(sbase + row * APITCH + kc * 16,
             A + (size_t)(bm + row) * K2 + ao + kc * 8);
    }
#pragma unroll
    for (int h = 0; h < 2; h++) {
        int c = tid + h * 256;          // 512 chunks for B
        int row = c >> 2, kc = c & 3;
        cp16(sbase + ATILE_B + row * APITCH + kc * 16,
             B + (size_t)(bn + row) * K2 + bo + kc * 8);
    }
}

template <bool RELU, bool OUTF, bool OUTS>
__global__ void __launch_bounds__(256)
gemm_hmma(const __nv_bfloat16* __restrict__ A, const __nv_bfloat16* __restrict__ B,
          const float* __restrict__ bias, float* __restrict__ Cf,
          __nv_bfloat16* __restrict__ Cs, int N)
{
    extern __shared__ char sm[];
    const uint32_t sbase = smem_u32(sm);
    const int tid = threadIdx.x, lane = tid & 31, w = tid >> 5;
    const int bm = blockIdx.y * 128, bn = blockIdx.x * 128;
    const int wm = w & 3, wn = w >> 2;          // warp tile: rows [wm*32,+32), cols [wn*64,+64)

    // prologue: fill 3 stages
#pragma unroll
    for (int s = 0; s < 3; s++) {
        cp_stage(A, B, bm, bn, sbase + s * STAGE_B, tid, s);
        cp_commit();
    }

    float acc[2][8][4];
#pragma unroll
    for (int mb = 0; mb < 2; mb++)
#pragma unroll
        for (int nb = 0; nb < 8; nb++)
#pragma unroll
            for (int q = 0; q < 4; q++) acc[mb][nb][q] = 0.f;

    const int quad = lane >> 3, li = lane & 7;
    // A ldmatrix per-lane address (block m16k16): quads -> (rowblk, kblk)
    const uint32_t aAddr = sbase +
        (uint32_t)((wm * 32 + (quad & 1) * 8 + li) * APITCH + (quad >> 1) * 16);
    // B ldmatrix per-lane address (block n16k16): quads -> (kblk, nblk)
    const uint32_t bAddr = sbase + ATILE_B +
        (uint32_t)((wn * 64 + (quad >> 1) * 8 + li) * APITCH + (quad & 1) * 16);

    for (int i = 0; i < NIT; i++) {
        cp_wait<2>();
        __syncthreads();
        if (i + 3 < NIT)
            cp_stage(A, B, bm, bn, sbase + ((i + 3) & 3) * STAGE_B, tid, i + 3);
        cp_commit();

        const uint32_t sa = aAddr + (i & 3) * STAGE_B;
        const uint32_t sb = bAddr + (i & 3) * STAGE_B;
#pragma unroll
        for (int kh = 0; kh < 2; kh++) {
            uint32_t a[2][4];
            ldm_x4(a[0][0], a[0][1], a[0][2], a[0][3], sa + kh * 32);
            ldm_x4(a[1][0], a[1][1], a[1][2], a[1][3], sa + kh * 32 + 16 * APITCH);
            uint32_t b[8][2];
#pragma unroll
            for (int n2 = 0; n2 < 4; n2++)
                ldm_x4(b[2 * n2][0], b[2 * n2][1], b[2 * n2 + 1][0], b[2 * n2 + 1][1],
                       sb + kh * 32 + n2 * 16 * APITCH);
#pragma unroll
            for (int mb = 0; mb < 2; mb++)
#pragma unroll
                for (int nb = 0; nb < 8; nb++)
                    mma16816(acc[mb][nb], a[mb][0], a[mb][1], a[mb][2], a[mb][3],
                             b[nb][0], b[nb][1]);
        }
    }

    // epilogue
    const int g = lane >> 2, t = lane & 3;
#pragma unroll
    for (int mb = 0; mb < 2; mb++) {
        const int r0 = bm + wm * 32 + mb * 16 + g;
#pragma unroll
        for (int nb = 0; nb < 8; nb++) {
            const int col = bn + wn * 64 + nb * 8 + t * 2;
            const float b0 = bias[col], b1 = bias[col + 1];
            float v00 = acc[mb][nb][0] + b0, v01 = acc[mb][nb][1] + b1;
            float v10 = acc[mb][nb][2] + b0, v11 = acc[mb][nb][3] + b1;
            if (RELU) {
                v00 = fmaxf(v00, 0.f); v01 = fmaxf(v01, 0.f);
                v10 = fmaxf(v10, 0.f); v11 = fmaxf(v11, 0.f);
            }
            if (OUTF) {
                *(float2*)(Cf + (size_t)r0 * N + col)       = make_float2(v00, v01);
                *(float2*)(Cf + (size_t)(r0 + 8) * N + col) = make_float2(v10, v11);
            }
            if (OUTS) {
                __nv_bfloat16 h00 = __float2bfloat16(v00), h01 = __float2bfloat16(v01);
                __nv_bfloat16 h10 = __float2bfloat16(v10), h11 = __float2bfloat16(v11);
                __nv_bfloat16* o0 = Cs + (size_t)r0 * (2 * N) + col;
                __nv_bfloat16* o1 = Cs + (size_t)(r0 + 8) * (2 * N) + col;
                *(__nv_bfloat162*)o0 = __halves2bfloat162(h00, h01);
                *(__nv_bfloat162*)o1 = __halves2bfloat162(h10, h11);
                *(__nv_bfloat162*)(o0 + N) = __halves2bfloat162(
                    __float2bfloat16(v00 - __bfloat162float(h00)),
                    __float2bfloat16(v01 - __bfloat162float(h01)));
                *(__nv_bfloat162*)(o1 + N) = __halves2bfloat162(
                    __float2bfloat16(v10 - __bfloat162float(h10)),
                    __float2bfloat16(v11 - __bfloat162float(h11)));
            }
        }
    }
}

// ===================== fp32 -> split bf16 (K=1024 rows) =====================
__global__ void split_f32(const float* __restrict__ in, __nv_bfloat16* __restrict__ out,
                          int total4)
{
    int idx = blockIdx.x * 256 + threadIdx.x;
    if (idx >= total4) return;
    int r = idx >> 8;            // H/4 = 256 float4 per row
    int c4 = (idx & 255) * 4;
    float4 x = ((const float4*)in)[idx];
    __nv_bfloat16 a0 = __float2bfloat16(x.x), a1 = __float2bfloat16(x.y);
    __nv_bfloat16 a2 = __float2bfloat16(x.z), a3 = __float2bfloat16(x.w);
    __nv_bfloat16* o = out + (size_t)r * K2 + c4;
    *(__nv_bfloat162*)(o)     = __halves2bfloat162(a0, a1);
    *(__nv_bfloat162*)(o + 2) = __halves2bfloat162(a2, a3);
    *(__nv_bfloat162*)(o + H) = __halves2bfloat162(
        __float2bfloat16(x.x - __bfloat162float(a0)),
        __float2bfloat16(x.y - __bfloat162float(a1)));
    *(__nv_bfloat162*)(o + H + 2) = __halves2bfloat162(
        __float2bfloat16(x.z - __bfloat162float(a2)),
        __float2bfloat16(x.w - __bfloat162float(a3)));
}

// ===================== GEMV (gh1 / logits) =====================
__global__ void gemv_rows(const float* __restrict__ x, const float* __restrict__ W,
                          const float* __restrict__ b, float* __restrict__ out, int Nout)
{
    int n = blockIdx.x * 8 + (threadIdx.x >> 5);
    if (n >= Nout) return;
    int lane = threadIdx.x & 31;
    const float* w = W + (size_t)n * H;
    float s = 0.f;
#pragma unroll
    for (int k = lane * 4; k < H; k += 128) {
        float4 wv = *(const float4*)(w + k);
        float4 xv = *(const float4*)(x + k);
        s = fmaf(wv.x, xv.x, s); s = fmaf(wv.y, xv.y, s);
        s = fmaf(wv.z, xv.z, s); s = fmaf(wv.w, xv.w, s);
    }
#pragma unroll
    for (int o = 16; o; o >>= 1) s += __shfl_xor_sync(0xffffffffu, s, o);
    if (lane == 0) out[n] = s + b[n];
}

__global__ void logits_kernel(const float* __restrict__ X, const float* __restrict__ w3,
                              const float* __restrict__ b3)
{
    int n = blockIdx.x * 8 + (threadIdx.x >> 5);
    int lane = threadIdx.x & 31;
    const float* x = X + (size_t)n * H;
    float s = 0.f;
#pragma unroll
    for (int k = lane * 4; k < H; k += 128) {
        float4 xv = *(const float4*)(x + k);
        float4 wv = *(const float4*)(w3 + k);
        s = fmaf(wv.x, xv.x, s); s = fmaf(wv.y, xv.y, s);
        s = fmaf(wv.z, xv.z, s); s = fmaf(wv.w, xv.w, s);
    }
#pragma unroll
    for (int o = 16; o; o >>= 1) s += __shfl_xor_sync(0xffffffffu, s, o);
    if (lane == 0) g_logits[n] = s + b3[0];
}

// ===================== GRU combine (+ fused split output) =====================
__device__ __forceinline__ float gru1(float ir, float iz, float inn,
                                      float hr, float hz, float hn, float h)
{
    float r = 1.f / (1.f + __expf(-(ir + hr)));
    float z = 1.f / (1.f + __expf(-(iz + hz)));
    float n = tanhf(fmaf(r, hn, inn));
    return fmaf(z, h - n, n);
}
__device__ __forceinline__ float4 gru4(const float* __restrict__ gi,
                                       const float* __restrict__ gh,
                                       const float* __restrict__ h, int j)
{
    float4 ir  = *(const float4*)(gi + j);
    float4 iz  = *(const float4*)(gi + H + j);
    float4 inn = *(const float4*)(gi + 2 * H + j);
    float4 hr  = *(const float4*)(gh + j);
    float4 hz  = *(const float4*)(gh + H + j);
    float4 hn  = *(const float4*)(gh + 2 * H + j);
    float4 hv  = *(const float4*)(h + j);
    float4 o;
    o.x = gru1(ir.x, iz.x, inn.x, hr.x, hz.x, hn.x, hv.x);
    o.y = gru1(ir.y, iz.y, inn.y, hr.y, hz.y, hn.y, hv.y);
    o.z = gru1(ir.z, iz.z, inn.z, hr.z, hz.z, hn.z, hv.z);
    o.w = gru1(ir.w, iz.w, inn.w, hr.w, hz.w, hn.w, hv.w);
    return o;
}
__device__ __forceinline__ void split_store(__nv_bfloat16* o, float4 v)
{
    __nv_bfloat16 a0 = __float2bfloat16(v.x), a1 = __float2bfloat16(v.y);
    __nv_bfloat16 a2 = __float2bfloat16(v.z), a3 = __float2bfloat16(v.w);
    *(__nv_bfloat162*)(o)     = __halves2bfloat162(a0, a1);
    *(__nv_bfloat162*)(o + 2) = __halves2bfloat162(a2, a3);
    *(__nv_bfloat162*)(o + H) = __halves2bfloat162(
        __float2bfloat16(v.x - __bfloat162float(a0)),
        __float2bfloat16(v.y - __bfloat162float(a1)));
    *(__nv_bfloat162*)(o + H + 2) = __halves2bfloat162(
        __float2bfloat16(v.z - __bfloat162float(a2)),
        __float2bfloat16(v.w - __bfloat162float(a3)));
}

__global__ void gru_h1_kernel(const float* __restrict__ state)
{
    int v = blockIdx.x;
    int j = threadIdx.x * 4;
    float4 o = gru4(g_gi + (size_t)v * H3, g_gh1, state, j);
    *(float4*)(g_h1 + (size_t)v * H + j) = o;
    split_store(g2_h1 + (size_t)v * K2 + j, o);
}

__global__ void gru_step2_kernel(const int* __restrict__ tokens, int stride,
                                 float* __restrict__ outf, __nv_bfloat16* __restrict__ outs)
{
    int n  = blockIdx.x;
    int t0 = tokens[n * stride + 0];
    int t1 = tokens[n * stride + 1];
    int j  = threadIdx.x * 4;
    float4 o = gru4(g_gi + (size_t)t1 * H3, g_gh2 + (size_t)t0 * H3, g_h1 + (size_t)t0 * H, j);
    if (outf) *(float4*)(outf + (size_t)n * H + j) = o;
    if (outs) split_store(outs + (size_t)n * K2 + j, o);
}

__global__ void gru_step3_kernel(const int* __restrict__ rel_tokens)
{
    int n  = blockIdx.x;
    int t2 = rel_tokens[n * 3 + 2];
    int j  = threadIdx.x * 4;
    float4 o = gru4(g_gi + (size_t)t2 * H3, g_gh3 + (size_t)n * H3, g_h2rel + (size_t)n * H, j);
    split_store(g2_clause + (size_t)n * K2 + j, o);
}

// ===================== softmax + eps smoothing =====================
__global__ void softmax_kernel(const float* __restrict__ eps, float* __restrict__ out)
{
    const int N = NCL;
    __shared__ float shm[32], shs[32];
    int tid = threadIdx.x;

    float m = -1e30f;
    for (int i = tid; i < N; i += 1024) m = fmaxf(m, g_logits[i]);
#pragma unroll
    for (int o = 16; o; o >>= 1) m = fmaxf(m, __shfl_xor_sync(0xffffffffu, m, o));
    if ((tid & 31) == 0) shm[tid >> 5] = m;
    __syncthreads();
    if (tid < 32) {
        float v = shm[tid];
#pragma unroll
        for (int o = 16; o; o >>= 1) v = fmaxf(v, __shfl_xor_sync(0xffffffffu, v, o));
        shm[tid] = v;
    }
    __syncthreads();
    float M = shm[0];

    float s = 0.f;
    for (int i = tid; i < N; i += 1024) s += __expf(g_logits[i] - M);
#pragma unroll
    for (int o = 16; o; o >>= 1) s += __shfl_xor_sync(0xffffffffu, s, o);
    if ((tid & 31) == 0) shs[tid >> 5] = s;
    __syncthreads();
    if (tid < 32) {
        float v = shs[tid];
#pragma unroll
        for (int o = 16; o; o >>= 1) v += __shfl_xor_sync(0xffffffffu, v, o);
        shs[tid] = v;
    }
    __syncthreads();
    float S = shs[0];
    float e = eps[0];
    float inv = (1.f - e) / S;
    float add = e / (float)N;
    for (int i = tid; i < N; i += 1024)
        out[i] = __expf(g_logits[i] - M) * inv + add;
}

// ===================== launch =====================
extern "C" void kernel_launch(void* const* d_in, const int* in_sizes, int n_in,
                              void* d_out, int out_size)
{
    const float* state       = (const float*)d_in[0];
    const int*   rel_tokens  = (const int*)d_in[1];
    const int*   attr_tokens = (const int*)d_in[2];
    const float* table       = (const float*)d_in[3];
    const float* W_emb       = (const float*)d_in[4];
    const float* b_emb       = (const float*)d_in[5];
    const float* W_ih        = (const float*)d_in[6];
    const float* W_hh        = (const float*)d_in[7];
    const float* b_ih        = (const float*)d_in[8];
    const float* b_hh        = (const float*)d_in[9];
    const float* W1          = (const float*)d_in[10];
    const float* b1          = (const float*)d_in[11];
    const float* W2          = (const float*)d_in[12];
    const float* b2          = (const float*)d_in[13];
    const float* W3          = (const float*)d_in[14];
    const float* b3          = (const float*)d_in[15];
    const float* eps         = (const float*)d_in[16];
    float* out = (float*)d_out;

    __nv_bfloat16 *p2_table, *p2_Wemb, *p2_Wih, *p2_Whh, *p2_W1, *p2_W2;
    __nv_bfloat16 *p2_emb, *p2_h1, *p2_h2rel, *p2_clause, *p2_x1;
    float *p_gi, *p_gh1, *p_gh2, *p_h2rel, *p_gh3, *p_x2;
    cudaGetSymbolAddress((void**)&p2_table,  g2_table);
    cudaGetSymbolAddress((void**)&p2_Wemb,   g2_Wemb);
    cudaGetSymbolAddress((void**)&p2_Wih,    g2_Wih);
    cudaGetSymbolAddress((void**)&p2_Whh,    g2_Whh);
    cudaGetSymbolAddress((void**)&p2_W1,     g2_W1);
    cudaGetSymbolAddress((void**)&p2_W2,     g2_W2);
    cudaGetSymbolAddress((void**)&p2_emb,    g2_emb);
    cudaGetSymbolAddress((void**)&p2_h1,     g2_h1);
    cudaGetSymbolAddress((void**)&p2_h2rel,  g2_h2rel);
    cudaGetSymbolAddress((void**)&p2_clause, g2_clause);
    cudaGetSymbolAddress((void**)&p2_x1,     g2_x1);
    cudaGetSymbolAddress((void**)&p_gi,      g_gi);
    cudaGetSymbolAddress((void**)&p_gh1,     g_gh1);
    cudaGetSymbolAddress((void**)&p_gh2,     g_gh2);
    cudaGetSymbolAddress((void**)&p_h2rel,   g_h2rel);
    cudaGetSymbolAddress((void**)&p_gh3,     g_gh3);
    cudaGetSymbolAddress((void**)&p_x2,      g_x2);

    cudaFuncSetAttribute(gemm_hmma<false, false, true>,
                         cudaFuncAttributeMaxDynamicSharedMemorySize, SMEM_DYN_H);
    cudaFuncSetAttribute(gemm_hmma<false, true, false>,
                         cudaFuncAttributeMaxDynamicSharedMemorySize, SMEM_DYN_H);
    cudaFuncSetAttribute(gemm_hmma<true, false, true>,
                         cudaFuncAttributeMaxDynamicSharedMemorySize, SMEM_DYN_H);
    cudaFuncSetAttribute(gemm_hmma<true, true, false>,
                         cudaFuncAttributeMaxDynamicSharedMemorySize, SMEM_DYN_H);

    // 0. split fp32 operands feeding tensor GEMMs
    split_f32<<<(V  * 256 + 255) / 256, 256>>>(table, p2_table, V  * 256);
    split_f32<<<(H  * 256 + 255) / 256, 256>>>(W_emb, p2_Wemb,  H  * 256);
    split_f32<<<(H3 * 256 + 255) / 256, 256>>>(W_ih,  p2_Wih,   H3 * 256);
    split_f32<<<(H3 * 256 + 255) / 256, 256>>>(W_hh,  p2_Whh,   H3 * 256);
    split_f32<<<(H  * 256 + 255) / 256, 256>>>(W1,    p2_W1,    H  * 256);
    split_f32<<<(H  * 256 + 255) / 256, 256>>>(W2,    p2_W2,    H  * 256);

    // 1. emb_proj[V,H] (split bf16 out)
    gemm_hmma<false, false, true><<<dim3(H / 128, V / 128), 256, SMEM_DYN_H>>>(
        p2_table, p2_Wemb, b_emb, nullptr, p2_emb, H);
    // 2. gi_table[V,3H] (fp32 out)
    gemm_hmma<false, true, false><<<dim3(H3 / 128, V / 128), 256, SMEM_DYN_H>>>(
        p2_emb, p2_Wih, b_ih, p_gi, nullptr, H3);
    // 3. gh1 = state @ W_hh^T + b_hh (exact fp32 GEMV)
    gemv_rows<<<H3 / 8, 256>>>(state, W_hh, b_hh, p_gh1, H3);
    // 4. h1_table (fp32 + split)
    gru_h1_kernel<<<V, 256>>>(state);
    // 5. gh2_table[V,3H] (fp32 out)
    gemm_hmma<false, true, false><<<dim3(H3 / 128, V / 128), 256, SMEM_DYN_H>>>(
        p2_h1, p2_Whh, b_hh, p_gh2, nullptr, H3);
    // 6. rel step 2 -> h2rel (fp32 + split)
    gru_step2_kernel<<<NREL, 256>>>(rel_tokens, 3, p_h2rel, p2_h2rel);
    // 7. attr step 2 -> clause split rows [4096, 8192)
    gru_step2_kernel<<<NATT, 256>>>(attr_tokens, 2, nullptr, p2_clause + (size_t)NREL * K2);
    // 8. gh3[Nr,3H] (fp32 out)
    gemm_hmma<false, true, false><<<dim3(H3 / 128, NREL / 128), 256, SMEM_DYN_H>>>(
        p2_h2rel, p2_Whh, b_hh, p_gh3, nullptr, H3);
    // 9. rel step 3 -> clause split rows [0, 4096)
    gru_step3_kernel<<<NREL, 256>>>(rel_tokens);
    // 10. x1 = relu(clause @ W1^T + b1) (split out)
    gemm_hmma<true, false, true><<<dim3(H / 128, NCL / 128), 256, SMEM_DYN_H>>>(
        p2_clause, p2_W1, b1, nullptr, p2_x1, H);
    // 11. x2 = relu(x1 @ W2^T + b2) (fp32 out)
    gemm_hmma<true, true, false><<<dim3(H / 128, NCL / 128), 256, SMEM_DYN_H>>>(
        p2_x1, p2_W2, b2, p_x2, nullptr, H);
    // 12. logits
    logits_kernel<<<NCL / 8, 256>>>(p_x2, W3, b3);
    // 13. softmax + smoothing
    softmax_kernel<<<1, 1024>>>(eps, out);
}

// round 4
// speedup vs baseline: 2.2264x; 1.0328x over previous
#include <cuda_runtime.h>
#include <cuda_bf16.h>
#include <math.h>
#include <stdint.h>

#define H    1024
#define H3   3072
#define NREL 4096
#define NATT 4096
#define NCL  8192
#define V    256
#define K2   2048     // split row stride: hi[0:1024) | lo[1024:2048)

// ===================== scratch (device globals; no allocations) =====================
__device__ __align__(256) __nv_bfloat16 g2_table[V * K2];
__device__ __align__(256) __nv_bfloat16 g2_Wemb[H * K2];
__device__ __align__(256) __nv_bfloat16 g2_Wih[H3 * K2];
__device__ __align__(256) __nv_bfloat16 g2_Whh[H3 * K2];
__device__ __align__(256) __nv_bfloat16 g2_W1[H * K2];
__device__ __align__(256) __nv_bfloat16 g2_W2[H * K2];
__device__ __align__(256) __nv_bfloat16 g2_emb[V * K2];
__device__ __align__(256) __nv_bfloat16 g2_h1[V * K2];
__device__ __align__(256) __nv_bfloat16 g2_h2rel[NREL * K2];
__device__ __align__(256) __nv_bfloat16 g2_clause[NCL * K2];
__device__ __align__(256) __nv_bfloat16 g2_x1[NCL * K2];
__device__ float g_gi[V * H3];
__device__ float g_gh1[H3];
__device__ float g_h1[V * H];
__device__ float g_gh2[V * H3];
__device__ float g_h2rel[NREL * H];
__device__ float g_gh3[NREL * H3];
__device__ float g_x2[NCL * H];
__device__ float g_logits[NCL];

// ===================== PTX helpers (valid at compute_103, no 'a' features) ============
__device__ __forceinline__ uint32_t smem_u32(const void* p) {
    uint32_t a;
    asm("{ .reg .u64 t; cvta.to.shared.u64 t, %1; cvt.u32.u64 %0, t; }" : "=r"(a) : "l"(p));
    return a;
}
__device__ __forceinline__ void cp16(uint32_t dst, const void* src) {
    asm volatile("cp.async.cg.shared.global [%0], [%1], 16;" :: "r"(dst), "l"(src));
}
__device__ __forceinline__ void cp_commit() {
    asm volatile("cp.async.commit_group;" ::: "memory");
}
template <int N>
__device__ __forceinline__ void cp_wait() {
    asm volatile("cp.async.wait_group %0;" :: "n"(N) : "memory");
}
__device__ __forceinline__ void ldm_x4(uint32_t& r0, uint32_t& r1, uint32_t& r2, uint32_t& r3,
                                       uint32_t addr) {
    asm volatile("ldmatrix.sync.aligned.m8n8.x4.shared.b16 {%0,%1,%2,%3}, [%4];"
                 : "=r"(r0), "=r"(r1), "=r"(r2), "=r"(r3) : "r"(addr));
}
__device__ __forceinline__ void mma16816(float* c, uint32_t a0, uint32_t a1, uint32_t a2,
                                         uint32_t a3, uint32_t b0, uint32_t b1) {
    asm volatile(
        "mma.sync.aligned.m16n8k16.row.col.f32.bf16.bf16.f32 "
        "{%0,%1,%2,%3}, {%4,%5,%6,%7}, {%8,%9}, {%0,%1,%2,%3};"
        : "+f"(c[0]), "+f"(c[1]), "+f"(c[2]), "+f"(c[3])
        : "r"(a0), "r"(a1), "r"(a2), "r"(a3), "r"(b0), "r"(b1));
}

// ===================== split-precision HMMA GEMM ==============================
// C[M,N] = A[M,1024] @ B[N,1024]^T + bias; A,B stored split bf16 [rows, 2048].
// 3 K-passes (hi*hi, hi*lo, lo*hi). CTA 128x128, BK=32, 4-stage cp.async pipeline.
// 2 CTAs/SM so co-resident CTA hides barrier + cp.async-wait stalls.
#define APITCH   80                     // bytes per 32-elem bf16 row (64B data + 16B pad)
#define ATILE_B  (128 * APITCH)         // 10240
#define STAGE_B  (2 * ATILE_B)          // 20480 (A then B)
#define NSTAGE   4
#define SMEM_DYN_H (NSTAGE * STAGE_B)   // 81920
#define NIT      96                     // 3 passes * 32 chunks of K=32

__device__ __forceinline__ void cp_stage(const __nv_bfloat16* __restrict__ A,
                                         const __nv_bfloat16* __restrict__ B,
                                         int bm, int bn, uint32_t sbase, int tid,
                                         int it)
{
    const int pass = it >> 5, kk = (it & 31) * 32;
    const int ao = kk + (pass == 2 ? 1024 : 0);
    const int bo = kk + (pass == 1 ? 1024 : 0);
#pragma unroll
    for (int h = 0; h < 2; h++) {
        int c = tid + h * 256;
        int row = c >> 2, kc = c & 3;
        cp16(sbase + row * APITCH + kc * 16,
             A + (size_t)(bm + row) * K2 + ao + kc * 8);
    }
#pragma unroll
    for (int h = 0; h < 2; h++) {
        int c = tid + h * 256;
        int row = c >> 2, kc = c & 3;
        cp16(sbase + ATILE_B + row * APITCH + kc * 16,
             B + (size_t)(bn + row) * K2 + bo + kc * 8);
    }
}

template <bool RELU, bool OUTF, bool OUTS>
__global__ void __launch_bounds__(256, 2)
gemm_hmma(const __nv_bfloat16* __restrict__ A, const __nv_bfloat16* __restrict__ B,
          const float* __restrict__ bias, float* __restrict__ Cf,
          __nv_bfloat16* __restrict__ Cs, int N)
{
    extern __shared__ char sm[];
    const uint32_t sbase = smem_u32(sm);
    const int tid = threadIdx.x, lane = tid & 31, w = tid >> 5;
    const int bm = blockIdx.y * 128, bn = blockIdx.x * 128;
    const int wm = w & 3, wn = w >> 2;          // warp tile: rows [wm*32,+32), cols [wn*64,+64)

#pragma unroll
    for (int s = 0; s < 3; s++) {
        cp_stage(A, B, bm, bn, sbase + s * STAGE_B, tid, s);
        cp_commit();
    }

    float acc[2][8][4];
#pragma unroll
    for (int mb = 0; mb < 2; mb++)
#pragma unroll
        for (int nb = 0; nb < 8; nb++)
#pragma unroll
            for (int q = 0; q < 4; q++) acc[mb][nb][q] = 0.f;

    const int quad = lane >> 3, li = lane & 7;
    const uint32_t aAddr = sbase +
        (uint32_t)((wm * 32 + (quad & 1) * 8 + li) * APITCH + (quad >> 1) * 16);
    const uint32_t bAddr = sbase + ATILE_B +
        (uint32_t)((wn * 64 + (quad >> 1) * 8 + li) * APITCH + (quad & 1) * 16);

    for (int i = 0; i < NIT; i++) {
        cp_wait<2>();
        __syncthreads();
        if (i + 3 < NIT)
            cp_stage(A, B, bm, bn, sbase + ((i + 3) & 3) * STAGE_B, tid, i + 3);
        cp_commit();

        const uint32_t sa = aAddr + (i & 3) * STAGE_B;
        const uint32_t sb = bAddr + (i & 3) * STAGE_B;
#pragma unroll
        for (int kh = 0; kh < 2; kh++) {
            uint32_t a[2][4];
            ldm_x4(a[0][0], a[0][1], a[0][2], a[0][3], sa + kh * 32);
            ldm_x4(a[1][0], a[1][1], a[1][2], a[1][3], sa + kh * 32 + 16 * APITCH);
            uint32_t b[8][2];
#pragma unroll
            for (int n2 = 0; n2 < 4; n2++)
                ldm_x4(b[2 * n2][0], b[2 * n2][1], b[2 * n2 + 1][0], b[2 * n2 + 1][1],
                       sb + kh * 32 + n2 * 16 * APITCH);
#pragma unroll
            for (int mb = 0; mb < 2; mb++)
#pragma unroll
                for (int nb = 0; nb < 8; nb++)
                    mma16816(acc[mb][nb], a[mb][0], a[mb][1], a[mb][2], a[mb][3],
                             b[nb][0], b[nb][1]);
        }
    }

    const int g = lane >> 2, t = lane & 3;
#pragma unroll
    for (int mb = 0; mb < 2; mb++) {
        const int r0 = bm + wm * 32 + mb * 16 + g;
#pragma unroll
        for (int nb = 0; nb < 8; nb++) {
            const int col = bn + wn * 64 + nb * 8 + t * 2;
            const float b0 = bias[col], b1 = bias[col + 1];
            float v00 = acc[mb][nb][0] + b0, v01 = acc[mb][nb][1] + b1;
            float v10 = acc[mb][nb][2] + b0, v11 = acc[mb][nb][3] + b1;
            if (RELU) {
                v00 = fmaxf(v00, 0.f); v01 = fmaxf(v01, 0.f);
                v10 = fmaxf(v10, 0.f); v11 = fmaxf(v11, 0.f);
            }
            if (OUTF) {
                *(float2*)(Cf + (size_t)r0 * N + col)       = make_float2(v00, v01);
                *(float2*)(Cf + (size_t)(r0 + 8) * N + col) = make_float2(v10, v11);
            }
            if (OUTS) {
                __nv_bfloat16 h00 = __float2bfloat16(v00), h01 = __float2bfloat16(v01);
                __nv_bfloat16 h10 = __float2bfloat16(v10), h11 = __float2bfloat16(v11);
                __nv_bfloat16* o0 = Cs + (size_t)r0 * (2 * N) + col;
                __nv_bfloat16* o1 = Cs + (size_t)(r0 + 8) * (2 * N) + col;
                *(__nv_bfloat162*)o0 = __halves2bfloat162(h00, h01);
                *(__nv_bfloat162*)o1 = __halves2bfloat162(h10, h11);
                *(__nv_bfloat162*)(o0 + N) = __halves2bfloat162(
                    __float2bfloat16(v00 - __bfloat162float(h00)),
                    __float2bfloat16(v01 - __bfloat162float(h01)));
                *(__nv_bfloat162*)(o1 + N) = __halves2bfloat162(
                    __float2bfloat16(v10 - __bfloat162float(h10)),
                    __float2bfloat16(v11 - __bfloat162float(h11)));
            }
        }
    }
}

// ===================== fused fp32 -> split bf16 for ALL 6 operands =====================
// segments (rows of 1024 f32): table 256 | Wemb 1024 | Wih 3072 | Whh 3072 | W1 1024 | W2 1024
#define SPLIT_ROWS (256 + 1024 + 3072 + 3072 + 1024 + 1024)   // 9472
__global__ void __launch_bounds__(256)
split_all(const float* __restrict__ s0, const float* __restrict__ s1,
          const float* __restrict__ s2, const float* __restrict__ s3,
          const float* __restrict__ s4, const float* __restrict__ s5,
          __nv_bfloat16* __restrict__ d0, __nv_bfloat16* __restrict__ d1,
          __nv_bfloat16* __restrict__ d2, __nv_bfloat16* __restrict__ d3,
          __nv_bfloat16* __restrict__ d4, __nv_bfloat16* __restrict__ d5)
{
    int row = blockIdx.x;   // one block per 1024-float row
    const float* src; __nv_bfloat16* dst; int r = row;
    if      (r < 256)        { src = s0; dst = d0; }
    else if ((r -= 256)  < 1024) { src = s1; dst = d1; }
    else if ((r -= 1024) < 3072) { src = s2; dst = d2; }
    else if ((r -= 3072) < 3072) { src = s3; dst = d3; }
    else if ((r -= 3072) < 1024) { src = s4; dst = d4; }
    else     { r -= 1024;      src = s5; dst = d5; }

    int c4 = threadIdx.x * 4;
    float4 x = *(const float4*)(src + (size_t)r * H + c4);
    __nv_bfloat16 a0 = __float2bfloat16(x.x), a1 = __float2bfloat16(x.y);
    __nv_bfloat16 a2 = __float2bfloat16(x.z), a3 = __float2bfloat16(x.w);
    __nv_bfloat16* o = dst + (size_t)r * K2 + c4;
    *(__nv_bfloat162*)(o)     = __halves2bfloat162(a0, a1);
    *(__nv_bfloat162*)(o + 2) = __halves2bfloat162(a2, a3);
    *(__nv_bfloat162*)(o + H) = __halves2bfloat162(
        __float2bfloat16(x.x - __bfloat162float(a0)),
        __float2bfloat16(x.y - __bfloat162float(a1)));
    *(__nv_bfloat162*)(o + H + 2) = __halves2bfloat162(
        __float2bfloat16(x.z - __bfloat162float(a2)),
        __float2bfloat16(x.w - __bfloat162float(a3)));
}

// ===================== GEMV (gh1 / logits) =====================
__global__ void gemv_rows(const float* __restrict__ x, const float* __restrict__ W,
                          const float* __restrict__ b, float* __restrict__ out, int Nout)
{
    int n = blockIdx.x * 8 + (threadIdx.x >> 5);
    if (n >= Nout) return;
    int lane = threadIdx.x & 31;
    const float* w = W + (size_t)n * H;
    float s = 0.f;
#pragma unroll
    for (int k = lane * 4; k < H; k += 128) {
        float4 wv = *(const float4*)(w + k);
        float4 xv = *(const float4*)(x + k);
        s = fmaf(wv.x, xv.x, s); s = fmaf(wv.y, xv.y, s);
        s = fmaf(wv.z, xv.z, s); s = fmaf(wv.w, xv.w, s);
    }
#pragma unroll
    for (int o = 16; o; o >>= 1) s += __shfl_xor_sync(0xffffffffu, s, o);
    if (lane == 0) out[n] = s + b[n];
}

__global__ void logits_kernel(const float* __restrict__ X, const float* __restrict__ w3,
                              const float* __restrict__ b3)
{
    int n = blockIdx.x * 8 + (threadIdx.x >> 5);
    int lane = threadIdx.x & 31;
    const float* x = X + (size_t)n * H;
    float s = 0.f;
#pragma unroll
    for (int k = lane * 4; k < H; k += 128) {
        float4 xv = *(const float4*)(x + k);
        float4 wv = *(const float4*)(w3 + k);
        s = fmaf(wv.x, xv.x, s); s = fmaf(wv.y, xv.y, s);
        s = fmaf(wv.z, xv.z, s); s = fmaf(wv.w, xv.w, s);
    }
#pragma unroll
    for (int o = 16; o; o >>= 1) s += __shfl_xor_sync(0xffffffffu, s, o);
    if (lane == 0) g_logits[n] = s + b3[0];
}

// ===================== GRU combine (+ fused split output) =====================
__device__ __forceinline__ float gru1(float ir, float iz, float inn,
                                      float hr, float hz, float hn, float h)
{
    float r = 1.f / (1.f + __expf(-(ir + hr)));
    float z = 1.f / (1.f + __expf(-(iz + hz)));
    float n = tanhf(fmaf(r, hn, inn));
    return fmaf(z, h - n, n);
}
__device__ __forceinline__ float4 gru4(const float* __restrict__ gi,
                                       const float* __restrict__ gh,
                                       const float* __restrict__ h, int j)
{
    float4 ir  = *(const float4*)(gi + j);
    float4 iz  = *(const float4*)(gi + H + j);
    float4 inn = *(const float4*)(gi + 2 * H + j);
    float4 hr  = *(const float4*)(gh + j);
    float4 hz  = *(const float4*)(gh + H + j);
    float4 hn  = *(const float4*)(gh + 2 * H + j);
    float4 hv  = *(const float4*)(h + j);
    float4 o;
    o.x = gru1(ir.x, iz.x, inn.x, hr.x, hz.x, hn.x, hv.x);
    o.y = gru1(ir.y, iz.y, inn.y, hr.y, hz.y, hn.y, hv.y);
    o.z = gru1(ir.z, iz.z, inn.z, hr.z, hz.z, hn.z, hv.z);
    o.w = gru1(ir.w, iz.w, inn.w, hr.w, hz.w, hn.w, hv.w);
    return o;
}
__device__ __forceinline__ void split_store(__nv_bfloat16* o, float4 v)
{
    __nv_bfloat16 a0 = __float2bfloat16(v.x), a1 = __float2bfloat16(v.y);
    __nv_bfloat16 a2 = __float2bfloat16(v.z), a3 = __float2bfloat16(v.w);
    *(__nv_bfloat162*)(o)     = __halves2bfloat162(a0, a1);
    *(__nv_bfloat162*)(o + 2) = __halves2bfloat162(a2, a3);
    *(__nv_bfloat162*)(o + H) = __halves2bfloat162(
        __float2bfloat16(v.x - __bfloat162float(a0)),
        __float2bfloat16(v.y - __bfloat162float(a1)));
    *(__nv_bfloat162*)(o + H + 2) = __halves2bfloat162(
        __float2bfloat16(v.z - __bfloat162float(a2)),
        __float2bfloat16(v.w - __bfloat162float(a3)));
}

__global__ void gru_h1_kernel(const float* __restrict__ state)
{
    int v = blockIdx.x;
    int j = threadIdx.x * 4;
    float4 o = gru4(g_gi + (size_t)v * H3, g_gh1, state, j);
    *(float4*)(g_h1 + (size_t)v * H + j) = o;
    split_store(g2_h1 + (size_t)v * K2 + j, o);
}

// merged rel+attr step 2. blocks [0,NREL): rel -> g_h2rel + g2_h2rel.
// blocks [NREL, NREL+NATT): attr -> g2_clause rows [NREL, NCL).
__global__ void gru_step2_all(const int* __restrict__ rel_tokens,
                              const int* __restrict__ attr_tokens)
{
    int blk = blockIdx.x;
    int j = threadIdx.x * 4;
    if (blk < NREL) {
        int t0 = rel_tokens[blk * 3 + 0];
        int t1 = rel_tokens[blk * 3 + 1];
        float4 o = gru4(g_gi + (size_t)t1 * H3, g_gh2 + (size_t)t0 * H3,
                        g_h1 + (size_t)t0 * H, j);
        *(float4*)(g_h2rel + (size_t)blk * H + j) = o;
        split_store(g2_h2rel + (size_t)blk * K2 + j, o);
    } else {
        int n = blk - NREL;
        int t0 = attr_tokens[n * 2 + 0];
        int t1 = attr_tokens[n * 2 + 1];
        float4 o = gru4(g_gi + (size_t)t1 * H3, g_gh2 + (size_t)t0 * H3,
                        g_h1 + (size_t)t0 * H, j);
        split_store(g2_clause + (size_t)(NREL + n) * K2 + j, o);
    }
}

__global__ void gru_step3_kernel(const int* __restrict__ rel_tokens)
{
    int n  = blockIdx.x;
    int t2 = rel_tokens[n * 3 + 2];
    int j  = threadIdx.x * 4;
    float4 o = gru4(g_gi + (size_t)t2 * H3, g_gh3 + (size_t)n * H3, g_h2rel + (size_t)n * H, j);
    split_store(g2_clause + (size_t)n * K2 + j, o);
}

// ===================== softmax + eps smoothing =====================
__global__ void softmax_kernel(const float* __restrict__ eps, float* __restrict__ out)
{
    const int N = NCL;
    __shared__ float shm[32], shs[32];
    int tid = threadIdx.x;

    float m = -1e30f;
    for (int i = tid; i < N; i += 1024) m = fmaxf(m, g_logits[i]);
#pragma unroll
    for (int o = 16; o; o >>= 1) m = fmaxf(m, __shfl_xor_sync(0xffffffffu, m, o));
    if ((tid & 31) == 0) shm[tid >> 5] = m;
    __syncthreads();
    if (tid < 32) {
        float v = shm[tid];
#pragma unroll
        for (int o = 16; o; o >>= 1) v = fmaxf(v, __shfl_xor_sync(0xffffffffu, v, o));
        shm[tid] = v;
    }
    __syncthreads();
    float M = shm[0];

    float s = 0.f;
    for (int i = tid; i < N; i += 1024) s += __expf(g_logits[i] - M);
#pragma unroll
    for (int o = 16; o; o >>= 1) s += __shfl_xor_sync(0xffffffffu, s, o);
    if ((tid & 31) == 0) shs[tid >> 5] = s;
    __syncthreads();
    if (tid < 32) {
        float v = shs[tid];
#pragma unroll
        for (int o = 16; o; o >>= 1) v += __shfl_xor_sync(0xffffffffu, v, o);
        shs[tid] = v;
    }
    __syncthreads();
    float S = shs[0];
    float e = eps[0];
    float inv = (1.f - e) / S;
    float add = e / (float)N;
    for (int i = tid; i < N; i += 1024)
        out[i] = __expf(g_logits[i] - M) * inv + add;
}

// ===================== launch =====================
extern "C" void kernel_launch(void* const* d_in, const int* in_sizes, int n_in,
                              void* d_out, int out_size)
{
    const float* state       = (const float*)d_in[0];
    const int*   rel_tokens  = (const int*)d_in[1];
    const int*   attr_tokens = (const int*)d_in[2];
    const float* table       = (const float*)d_in[3];
    const float* W_emb       = (const float*)d_in[4];
    const float* b_emb       = (const float*)d_in[5];
    const float* W_ih        = (const float*)d_in[6];
    const float* W_hh        = (const float*)d_in[7];
    const float* b_ih        = (const float*)d_in[8];
    const float* b_hh        = (const float*)d_in[9];
    const float* W1          = (const float*)d_in[10];
    const float* b1          = (const float*)d_in[11];
    const float* W2          = (const float*)d_in[12];
    const float* b2          = (const float*)d_in[13];
    const float* W3          = (const float*)d_in[14];
    const float* b3          = (const float*)d_in[15];
    const float* eps         = (const float*)d_in[16];
    float* out = (float*)d_out;

    __nv_bfloat16 *p2_table, *p2_Wemb, *p2_Wih, *p2_Whh, *p2_W1, *p2_W2;
    __nv_bfloat16 *p2_emb, *p2_h1, *p2_h2rel, *p2_clause, *p2_x1;
    float *p_gi, *p_gh1, *p_gh2, *p_h2rel, *p_gh3, *p_x2;
    cudaGetSymbolAddress((void**)&p2_table,  g2_table);
    cudaGetSymbolAddress((void**)&p2_Wemb,   g2_Wemb);
    cudaGetSymbolAddress((void**)&p2_Wih,    g2_Wih);
    cudaGetSymbolAddress((void**)&p2_Whh,    g2_Whh);
    cudaGetSymbolAddress((void**)&p2_W1,     g2_W1);
    cudaGetSymbolAddress((void**)&p2_W2,     g2_W2);
    cudaGetSymbolAddress((void**)&p2_emb,    g2_emb);
    cudaGetSymbolAddress((void**)&p2_h1,     g2_h1);
    cudaGetSymbolAddress((void**)&p2_h2rel,  g2_h2rel);
    cudaGetSymbolAddress((void**)&p2_clause, g2_clause);
    cudaGetSymbolAddress((void**)&p2_x1,     g2_x1);
    cudaGetSymbolAddress((void**)&p_gi,      g_gi);
    cudaGetSymbolAddress((void**)&p_gh1,     g_gh1);
    cudaGetSymbolAddress((void**)&p_gh2,     g_gh2);
    cudaGetSymbolAddress((void**)&p_h2rel,   g_h2rel);
    cudaGetSymbolAddress((void**)&p_gh3,     g_gh3);
    cudaGetSymbolAddress((void**)&p_x2,      g_x2);

    cudaFuncSetAttribute(gemm_hmma<false, false, true>,
                         cudaFuncAttributeMaxDynamicSharedMemorySize, SMEM_DYN_H);
    cudaFuncSetAttribute(gemm_hmma<false, true, false>,
                         cudaFuncAttributeMaxDynamicSharedMemorySize, SMEM_DYN_H);
    cudaFuncSetAttribute(gemm_hmma<true, false, true>,
                         cudaFuncAttributeMaxDynamicSharedMemorySize, SMEM_DYN_H);
    cudaFuncSetAttribute(gemm_hmma<true, true, false>,
                         cudaFuncAttributeMaxDynamicSharedMemorySize, SMEM_DYN_H);

    // 0. split all fp32 operands in one launch
    split_all<<<SPLIT_ROWS, 256>>>(table, W_emb, W_ih, W_hh, W1, W2,
                                   p2_table, p2_Wemb, p2_Wih, p2_Whh, p2_W1, p2_W2);

    // 1. emb_proj[V,H] (split bf16 out)
    gemm_hmma<false, false, true><<<dim3(H / 128, V / 128), 256, SMEM_DYN_H>>>(
        p2_table, p2_Wemb, b_emb, nullptr, p2_emb, H);
    // 2. gi_table[V,3H] (fp32 out)
    gemm_hmma<false, true, false><<<dim3(H3 / 128, V / 128), 256, SMEM_DYN_H>>>(
        p2_emb, p2_Wih, b_ih, p_gi, nullptr, H3);
    // 3. gh1 = state @ W_hh^T + b_hh (exact fp32 GEMV)
    gemv_rows<<<H3 / 8, 256>>>(state, W_hh, b_hh, p_gh1, H3);
    // 4. h1_table (fp32 + split)
    gru_h1_kernel<<<V, 256>>>(state);
    // 5. gh2_table[V,3H] (fp32 out)
    gemm_hmma<false, true, false><<<dim3(H3 / 128, V / 128), 256, SMEM_DYN_H>>>(
        p2_h1, p2_Whh, b_hh, p_gh2, nullptr, H3);
    // 6+7. merged step-2 (rel + attr)
    gru_step2_all<<<NREL + NATT, 256>>>(rel_tokens, attr_tokens);
    // 8. gh3[Nr,3H] (fp32 out)
    gemm_hmma<false, true, false><<<dim3(H3 / 128, NREL / 128), 256, SMEM_DYN_H>>>(
        p2_h2rel, p2_Whh, b_hh, p_gh3, nullptr, H3);
    // 9. rel step 3 -> clause split rows [0, 4096)
    gru_step3_kernel<<<NREL, 256>>>(rel_tokens);
    // 10. x1 = relu(clause @ W1^T + b1) (split out)
    gemm_hmma<true, false, true><<<dim3(H / 128, NCL / 128), 256, SMEM_DYN_H>>>(
        p2_clause, p2_W1, b1, nullptr, p2_x1, H);
    // 11. x2 = relu(x1 @ W2^T + b2) (fp32 out)
    gemm_hmma<true, true, false><<<dim3(H / 128, NCL / 128), 256, SMEM_DYN_H>>>(
        p2_x1, p2_W2, b2, p_x2, nullptr, H);
    // 12. logits
    logits_kernel<<<NCL / 8, 256>>>(p_x2, W3, b3);
    // 13. softmax + smoothing
    softmax_kernel<<<1, 1024>>>(eps, out);
}

// round 5
// speedup vs baseline: 3.1613x; 1.4199x over previous
#include <cuda_runtime.h>
#include <cuda_fp16.h>
#include <math.h>
#include <stdint.h>

#define H    1024
#define H3   3072
#define NREL 4096
#define NATT 4096
#define NCL  8192
#define V    256
#define K2   2048     // split row stride: hi[0:1024) | lo[1024:2048)

// ===================== scratch (device globals; no allocations) =====================
__device__ __align__(256) __half g2_table[V * K2];
__device__ __align__(256) __half g2_Wemb[H * K2];
__device__ __align__(256) __half g2_Wih[H3 * K2];
__device__ __align__(256) __half g2_Whh[H3 * K2];
__device__ __align__(256) __half g2_W1[H * K2];
__device__ __align__(256) __half g2_W2[H * K2];
__device__ __align__(256) __half g2_emb[V * K2];
__device__ __align__(256) __half g2_h1[V * K2];
__device__ __align__(256) __half g2_h2rel[NREL * K2];
__device__ __align__(256) __half g2_clause[NCL * K2];
__device__ __align__(256) __half g2_x1[NCL * K2];
__device__ float g_gi[V * H3];
__device__ float g_gh1[H3];
__device__ float g_h1[V * H];
__device__ float g_gh2[V * H3];
__device__ float g_h2rel[NREL * H];
__device__ float g_gh3[NREL * H3];
__device__ float g_x2[NCL * H];
__device__ float g_logits[NCL];

// ===================== PTX helpers (valid at compute_103, no 'a' features) ============
__device__ __forceinline__ uint32_t smem_u32(const void* p) {
    uint32_t a;
    asm("{ .reg .u64 t; cvta.to.shared.u64 t, %1; cvt.u32.u64 %0, t; }" : "=r"(a) : "l"(p));
    return a;
}
__device__ __forceinline__ void cp16(uint32_t dst, const void* src) {
    asm volatile("cp.async.cg.shared.global [%0], [%1], 16;" :: "r"(dst), "l"(src));
}
__device__ __forceinline__ void cp_commit() {
    asm volatile("cp.async.commit_group;" ::: "memory");
}
template <int N>
__device__ __forceinline__ void cp_wait() {
    asm volatile("cp.async.wait_group %0;" :: "n"(N) : "memory");
}
__device__ __forceinline__ void ldm_x4(uint32_t& r0, uint32_t& r1, uint32_t& r2, uint32_t& r3,
                                       uint32_t addr) {
    asm volatile("ldmatrix.sync.aligned.m8n8.x4.shared.b16 {%0,%1,%2,%3}, [%4];"
                 : "=r"(r0), "=r"(r1), "=r"(r2), "=r"(r3) : "r"(addr));
}
__device__ __forceinline__ void mma16816(float* c, uint32_t a0, uint32_t a1, uint32_t a2,
                                         uint32_t a3, uint32_t b0, uint32_t b1) {
    asm volatile(
        "mma.sync.aligned.m16n8k16.row.col.f32.f16.f16.f32 "
        "{%0,%1,%2,%3}, {%4,%5,%6,%7}, {%8,%9}, {%0,%1,%2,%3};"
        : "+f"(c[0]), "+f"(c[1]), "+f"(c[2]), "+f"(c[3])
        : "r"(a0), "r"(a1), "r"(a2), "r"(a3), "r"(b0), "r"(b1));
}

// ===================== split-precision HMMA GEMM ==============================
// C[M,N] = A[M,1024] @ B[N,1024]^T + bias; A,B stored split fp16 [rows, 2048].
// 2 K-passes: A_hi*B_hi + A_hi*B_lo  (residual A_lo*B ~ 2^-12 rel, under tolerance).
// CTA 128x128, BK=32, 4-stage cp.async pipeline.
#define APITCH   80                     // bytes per 32-elem fp16 row (64B data + 16B pad)
#define ATILE_B  (128 * APITCH)         // 10240
#define STAGE_B  (2 * ATILE_B)          // 20480 (A then B)
#define NSTAGE   4
#define SMEM_DYN_H (NSTAGE * STAGE_B)   // 81920
#define NIT      64                     // 2 passes * 32 chunks of K=32

__device__ __forceinline__ void cp_stage(const __half* __restrict__ A,
                                         const __half* __restrict__ B,
                                         int bm, int bn, uint32_t sbase, int tid,
                                         int it)
{
    const int pass = it >> 5, kk = (it & 31) * 32;
    const int ao = kk;                         // A always hi
    const int bo = kk + (pass ? 1024 : 0);     // B: pass0 hi, pass1 lo
#pragma unroll
    for (int h = 0; h < 2; h++) {
        int c = tid + h * 256;
        int row = c >> 2, kc = c & 3;
        cp16(sbase + row * APITCH + kc * 16,
             A + (size_t)(bm + row) * K2 + ao + kc * 8);
    }
#pragma unroll
    for (int h = 0; h < 2; h++) {
        int c = tid + h * 256;
        int row = c >> 2, kc = c & 3;
        cp16(sbase + ATILE_B + row * APITCH + kc * 16,
             B + (size_t)(bn + row) * K2 + bo + kc * 8);
    }
}

template <bool RELU, bool OUTF, bool OUTS>
__global__ void __launch_bounds__(256, 2)
gemm_hmma(const __half* __restrict__ A, const __half* __restrict__ B,
          const float* __restrict__ bias, float* __restrict__ Cf,
          __half* __restrict__ Cs, int N)
{
    extern __shared__ char sm[];
    const uint32_t sbase = smem_u32(sm);
    const int tid = threadIdx.x, lane = tid & 31, w = tid >> 5;
    const int bm = blockIdx.y * 128, bn = blockIdx.x * 128;
    const int wm = w & 3, wn = w >> 2;          // warp tile: rows [wm*32,+32), cols [wn*64,+64)

#pragma unroll
    for (int s = 0; s < 3; s++) {
        cp_stage(A, B, bm, bn, sbase + s * STAGE_B, tid, s);
        cp_commit();
    }

    float acc[2][8][4];
#pragma unroll
    for (int mb = 0; mb < 2; mb++)
#pragma unroll
        for (int nb = 0; nb < 8; nb++)
#pragma unroll
            for (int q = 0; q < 4; q++) acc[mb][nb][q] = 0.f;

    const int quad = lane >> 3, li = lane & 7;
    const uint32_t aAddr = sbase +
        (uint32_t)((wm * 32 + (quad & 1) * 8 + li) * APITCH + (quad >> 1) * 16);
    const uint32_t bAddr = sbase + ATILE_B +
        (uint32_t)((wn * 64 + (quad >> 1) * 8 + li) * APITCH + (quad & 1) * 16);

    for (int i = 0; i < NIT; i++) {
        cp_wait<2>();
        __syncthreads();
        if (i + 3 < NIT)
            cp_stage(A, B, bm, bn, sbase + ((i + 3) & 3) * STAGE_B, tid, i + 3);
        cp_commit();

        const uint32_t sa = aAddr + (i & 3) * STAGE_B;
        const uint32_t sb = bAddr + (i & 3) * STAGE_B;
#pragma unroll
        for (int kh = 0; kh < 2; kh++) {
            uint32_t a[2][4];
            ldm_x4(a[0][0], a[0][1], a[0][2], a[0][3], sa + kh * 32);
            ldm_x4(a[1][0], a[1][1], a[1][2], a[1][3], sa + kh * 32 + 16 * APITCH);
            uint32_t b[8][2];
#pragma unroll
            for (int n2 = 0; n2 < 4; n2++)
                ldm_x4(b[2 * n2][0], b[2 * n2][1], b[2 * n2 + 1][0], b[2 * n2 + 1][1],
                       sb + kh * 32 + n2 * 16 * APITCH);
#pragma unroll
            for (int mb = 0; mb < 2; mb++)
#pragma unroll
                for (int nb = 0; nb < 8; nb++)
                    mma16816(acc[mb][nb], a[mb][0], a[mb][1], a[mb][2], a[mb][3],
                             b[nb][0], b[nb][1]);
        }
    }

    const int g = lane >> 2, t = lane & 3;
#pragma unroll
    for (int mb = 0; mb < 2; mb++) {
        const int r0 = bm + wm * 32 + mb * 16 + g;
#pragma unroll
        for (int nb = 0; nb < 8; nb++) {
            const int col = bn + wn * 64 + nb * 8 + t * 2;
            const float b0 = bias[col], b1 = bias[col + 1];
            float v00 = acc[mb][nb][0] + b0, v01 = acc[mb][nb][1] + b1;
            float v10 = acc[mb][nb][2] + b0, v11 = acc[mb][nb][3] + b1;
            if (RELU) {
                v00 = fmaxf(v00, 0.f); v01 = fmaxf(v01, 0.f);
                v10 = fmaxf(v10, 0.f); v11 = fmaxf(v11, 0.f);
            }
            if (OUTF) {
                *(float2*)(Cf + (size_t)r0 * N + col)       = make_float2(v00, v01);
                *(float2*)(Cf + (size_t)(r0 + 8) * N + col) = make_float2(v10, v11);
            }
            if (OUTS) {
                __half h00 = __float2half(v00), h01 = __float2half(v01);
                __half h10 = __float2half(v10), h11 = __float2half(v11);
                __half* o0 = Cs + (size_t)r0 * (2 * N) + col;
                __half* o1 = Cs + (size_t)(r0 + 8) * (2 * N) + col;
                *(__half2*)o0 = __halves2half2(h00, h01);
                *(__half2*)o1 = __halves2half2(h10, h11);
                *(__half2*)(o0 + N) = __halves2half2(
                    __float2half(v00 - __half2float(h00)),
                    __float2half(v01 - __half2float(h01)));
                *(__half2*)(o1 + N) = __halves2half2(
                    __float2half(v10 - __half2float(h10)),
                    __float2half(v11 - __half2float(h11)));
            }
        }
    }
}

// ===================== fused fp32 -> split fp16 for ALL 6 operands =====================
#define SPLIT_ROWS (256 + 1024 + 3072 + 3072 + 1024 + 1024)   // 9472
__global__ void __launch_bounds__(256)
split_all(const float* __restrict__ s0, const float* __restrict__ s1,
          const float* __restrict__ s2, const float* __restrict__ s3,
          const float* __restrict__ s4, const float* __restrict__ s5,
          __half* __restrict__ d0, __half* __restrict__ d1,
          __half* __restrict__ d2, __half* __restrict__ d3,
          __half* __restrict__ d4, __half* __restrict__ d5)
{
    int row = blockIdx.x;
    const float* src; __half* dst; int r = row;
    if      (r < 256)        { src = s0; dst = d0; }
    else if ((r -= 256)  < 1024) { src = s1; dst = d1; }
    else if ((r -= 1024) < 3072) { src = s2; dst = d2; }
    else if ((r -= 3072) < 3072) { src = s3; dst = d3; }
    else if ((r -= 3072) < 1024) { src = s4; dst = d4; }
    else     { r -= 1024;      src = s5; dst = d5; }

    int c4 = threadIdx.x * 4;
    float4 x = *(const float4*)(src + (size_t)r * H + c4);
    __half a0 = __float2half(x.x), a1 = __float2half(x.y);
    __half a2 = __float2half(x.z), a3 = __float2half(x.w);
    __half* o = dst + (size_t)r * K2 + c4;
    *(__half2*)(o)     = __halves2half2(a0, a1);
    *(__half2*)(o + 2) = __halves2half2(a2, a3);
    *(__half2*)(o + H) = __halves2half2(
        __float2half(x.x - __half2float(a0)),
        __float2half(x.y - __half2float(a1)));
    *(__half2*)(o + H + 2) = __halves2half2(
        __float2half(x.z - __half2float(a2)),
        __float2half(x.w - __half2float(a3)));
}

// ===================== GEMV (gh1 / logits) =====================
__global__ void gemv_rows(const float* __restrict__ x, const float* __restrict__ W,
                          const float* __restrict__ b, float* __restrict__ out, int Nout)
{
    int n = blockIdx.x * 8 + (threadIdx.x >> 5);
    if (n >= Nout) return;
    int lane = threadIdx.x & 31;
    const float* w = W + (size_t)n * H;
    float s = 0.f;
#pragma unroll
    for (int k = lane * 4; k < H; k += 128) {
        float4 wv = *(const float4*)(w + k);
        float4 xv = *(const float4*)(x + k);
        s = fmaf(wv.x, xv.x, s); s = fmaf(wv.y, xv.y, s);
        s = fmaf(wv.z, xv.z, s); s = fmaf(wv.w, xv.w, s);
    }
#pragma unroll
    for (int o = 16; o; o >>= 1) s += __shfl_xor_sync(0xffffffffu, s, o);
    if (lane == 0) out[n] = s + b[n];
}

__global__ void logits_kernel(const float* __restrict__ X, const float* __restrict__ w3,
                              const float* __restrict__ b3)
{
    int n = blockIdx.x * 8 + (threadIdx.x >> 5);
    int lane = threadIdx.x & 31;
    const float* x = X + (size_t)n * H;
    float s = 0.f;
#pragma unroll
    for (int k = lane * 4; k < H; k += 128) {
        float4 xv = *(const float4*)(x + k);
        float4 wv = *(const float4*)(w3 + k);
        s = fmaf(wv.x, xv.x, s); s = fmaf(wv.y, xv.y, s);
        s = fmaf(wv.z, xv.z, s); s = fmaf(wv.w, xv.w, s);
    }
#pragma unroll
    for (int o = 16; o; o >>= 1) s += __shfl_xor_sync(0xffffffffu, s, o);
    if (lane == 0) g_logits[n] = s + b3[0];
}

// ===================== GRU combine (+ fused split output) =====================
__device__ __forceinline__ float gru1(float ir, float iz, float inn,
                                      float hr, float hz, float hn, float h)
{
    float r = 1.f / (1.f + __expf(-(ir + hr)));
    float z = 1.f / (1.f + __expf(-(iz + hz)));
    float n = tanhf(fmaf(r, hn, inn));
    return fmaf(z, h - n, n);
}
__device__ __forceinline__ float4 gru4(const float* __restrict__ gi,
                                       const float* __restrict__ gh,
                                       const float* __restrict__ h, int j)
{
    float4 ir  = *(const float4*)(gi + j);
    float4 iz  = *(const float4*)(gi + H + j);
    float4 inn = *(const float4*)(gi + 2 * H + j);
    float4 hr  = *(const float4*)(gh + j);
    float4 hz  = *(const float4*)(gh + H + j);
    float4 hn  = *(const float4*)(gh + 2 * H + j);
    float4 hv  = *(const float4*)(h + j);
    float4 o;
    o.x = gru1(ir.x, iz.x, inn.x, hr.x, hz.x, hn.x, hv.x);
    o.y = gru1(ir.y, iz.y, inn.y, hr.y, hz.y, hn.y, hv.y);
    o.z = gru1(ir.z, iz.z, inn.z, hr.z, hz.z, hn.z, hv.z);
    o.w = gru1(ir.w, iz.w, inn.w, hr.w, hz.w, hn.w, hv.w);
    return o;
}
__device__ __forceinline__ void split_store(__half* o, float4 v)
{
    __half a0 = __float2half(v.x), a1 = __float2half(v.y);
    __half a2 = __float2half(v.z), a3 = __float2half(v.w);
    *(__half2*)(o)     = __halves2half2(a0, a1);
    *(__half2*)(o + 2) = __halves2half2(a2, a3);
    *(__half2*)(o + H) = __halves2half2(
        __float2half(v.x - __half2float(a0)),
        __float2half(v.y - __half2float(a1)));
    *(__half2*)(o + H + 2) = __halves2half2(
        __float2half(v.z - __half2float(a2)),
        __float2half(v.w - __half2float(a3)));
}

__global__ void gru_h1_kernel(const float* __restrict__ state)
{
    int v = blockIdx.x;
    int j = threadIdx.x * 4;
    float4 o = gru4(g_gi + (size_t)v * H3, g_gh1, state, j);
    *(float4*)(g_h1 + (size_t)v * H + j) = o;
    split_store(g2_h1 + (size_t)v * K2 + j, o);
}

// merged rel+attr step 2
__global__ void gru_step2_all(const int* __restrict__ rel_tokens,
                              const int* __restrict__ attr_tokens)
{
    int blk = blockIdx.x;
    int j = threadIdx.x * 4;
    if (blk < NREL) {
        int t0 = rel_tokens[blk * 3 + 0];
        int t1 = rel_tokens[blk * 3 + 1];
        float4 o = gru4(g_gi + (size_t)t1 * H3, g_gh2 + (size_t)t0 * H3,
                        g_h1 + (size_t)t0 * H, j);
        *(float4*)(g_h2rel + (size_t)blk * H + j) = o;
        split_store(g2_h2rel + (size_t)blk * K2 + j, o);
    } else {
        int n = blk - NREL;
        int t0 = attr_tokens[n * 2 + 0];
        int t1 = attr_tokens[n * 2 + 1];
        float4 o = gru4(g_gi + (size_t)t1 * H3, g_gh2 + (size_t)t0 * H3,
                        g_h1 + (size_t)t0 * H, j);
        split_store(g2_clause + (size_t)(NREL + n) * K2 + j, o);
    }
}

__global__ void gru_step3_kernel(const int* __restrict__ rel_tokens)
{
    int n  = blockIdx.x;
    int t2 = rel_tokens[n * 3 + 2];
    int j  = threadIdx.x * 4;
    float4 o = gru4(g_gi + (size_t)t2 * H3, g_gh3 + (size_t)n * H3, g_h2rel + (size_t)n * H, j);
    split_store(g2_clause + (size_t)n * K2 + j, o);
}

// ===================== softmax + eps smoothing =====================
__global__ void softmax_kernel(const float* __restrict__ eps, float* __restrict__ out)
{
    const int N = NCL;
    __shared__ float shm[32], shs[32];
    int tid = threadIdx.x;

    float m = -1e30f;
    for (int i = tid; i < N; i += 1024) m = fmaxf(m, g_logits[i]);
#pragma unroll
    for (int o = 16; o; o >>= 1) m = fmaxf(m, __shfl_xor_sync(0xffffffffu, m, o));
    if ((tid & 31) == 0) shm[tid >> 5] = m;
    __syncthreads();
    if (tid < 32) {
        float v = shm[tid];
#pragma unroll
        for (int o = 16; o; o >>= 1) v = fmaxf(v, __shfl_xor_sync(0xffffffffu, v, o));
        shm[tid] = v;
    }
    __syncthreads();
    float M = shm[0];

    float s = 0.f;
    for (int i = tid; i < N; i += 1024) s += __expf(g_logits[i] - M);
#pragma unroll
    for (int o = 16; o; o >>= 1) s += __shfl_xor_sync(0xffffffffu, s, o);
    if ((tid & 31) == 0) shs[tid >> 5] = s;
    __syncthreads();
    if (tid < 32) {
        float v = shs[tid];
#pragma unroll
        for (int o = 16; o; o >>= 1) v += __shfl_xor_sync(0xffffffffu, v, o);
        shs[tid] = v;
    }
    __syncthreads();
    float S = shs[0];
    float e = eps[0];
    float inv = (1.f - e) / S;
    float add = e / (float)N;
    for (int i = tid; i < N; i += 1024)
        out[i] = __expf(g_logits[i] - M) * inv + add;
}

// ===================== launch =====================
extern "C" void kernel_launch(void* const* d_in, const int* in_sizes, int n_in,
                              void* d_out, int out_size)
{
    const float* state       = (const float*)d_in[0];
    const int*   rel_tokens  = (const int*)d_in[1];
    const int*   attr_tokens = (const int*)d_in[2];
    const float* table       = (const float*)d_in[3];
    const float* W_emb       = (const float*)d_in[4];
    const float* b_emb       = (const float*)d_in[5];
    const float* W_ih        = (const float*)d_in[6];
    const float* W_hh        = (const float*)d_in[7];
    const float* b_ih        = (const float*)d_in[8];
    const float* b_hh        = (const float*)d_in[9];
    const float* W1          = (const float*)d_in[10];
    const float* b1          = (const float*)d_in[11];
    const float* W2          = (const float*)d_in[12];
    const float* b2          = (const float*)d_in[13];
    const float* W3          = (const float*)d_in[14];
    const float* b3          = (const float*)d_in[15];
    const float* eps         = (const float*)d_in[16];
    float* out = (float*)d_out;

    __half *p2_table, *p2_Wemb, *p2_Wih, *p2_Whh, *p2_W1, *p2_W2;
    __half *p2_emb, *p2_h1, *p2_h2rel, *p2_clause, *p2_x1;
    float *p_gi, *p_gh1, *p_gh2, *p_h2rel, *p_gh3, *p_x2;
    cudaGetSymbolAddress((void**)&p2_table,  g2_table);
    cudaGetSymbolAddress((void**)&p2_Wemb,   g2_Wemb);
    cudaGetSymbolAddress((void**)&p2_Wih,    g2_Wih);
    cudaGetSymbolAddress((void**)&p2_Whh,    g2_Whh);
    cudaGetSymbolAddress((void**)&p2_W1,     g2_W1);
    cudaGetSymbolAddress((void**)&p2_W2,     g2_W2);
    cudaGetSymbolAddress((void**)&p2_emb,    g2_emb);
    cudaGetSymbolAddress((void**)&p2_h1,     g2_h1);
    cudaGetSymbolAddress((void**)&p2_h2rel,  g2_h2rel);
    cudaGetSymbolAddress((void**)&p2_clause, g2_clause);
    cudaGetSymbolAddress((void**)&p2_x1,     g2_x1);
    cudaGetSymbolAddress((void**)&p_gi,      g_gi);
    cudaGetSymbolAddress((void**)&p_gh1,     g_gh1);
    cudaGetSymbolAddress((void**)&p_gh2,     g_gh2);
    cudaGetSymbolAddress((void**)&p_h2rel,   g_h2rel);
    cudaGetSymbolAddress((void**)&p_gh3,     g_gh3);
    cudaGetSymbolAddress((void**)&p_x2,      g_x2);

    cudaFuncSetAttribute(gemm_hmma<false, false, true>,
                         cudaFuncAttributeMaxDynamicSharedMemorySize, SMEM_DYN_H);
    cudaFuncSetAttribute(gemm_hmma<false, true, false>,
                         cudaFuncAttributeMaxDynamicSharedMemorySize, SMEM_DYN_H);
    cudaFuncSetAttribute(gemm_hmma<true, false, true>,
                         cudaFuncAttributeMaxDynamicSharedMemorySize, SMEM_DYN_H);
    cudaFuncSetAttribute(gemm_hmma<true, true, false>,
                         cudaFuncAttributeMaxDynamicSharedMemorySize, SMEM_DYN_H);

    // 0. split all fp32 operands in one launch
    split_all<<<SPLIT_ROWS, 256>>>(table, W_emb, W_ih, W_hh, W1, W2,
                                   p2_table, p2_Wemb, p2_Wih, p2_Whh, p2_W1, p2_W2);

    // 1. emb_proj[V,H] (split fp16 out)
    gemm_hmma<false, false, true><<<dim3(H / 128, V / 128), 256, SMEM_DYN_H>>>(
        p2_table, p2_Wemb, b_emb, nullptr, p2_emb, H);
    // 2. gi_table[V,3H] (fp32 out)
    gemm_hmma<false, true, false><<<dim3(H3 / 128, V / 128), 256, SMEM_DYN_H>>>(
        p2_emb, p2_Wih, b_ih, p_gi, nullptr, H3);
    // 3. gh1 = state @ W_hh^T + b_hh (exact fp32 GEMV)
    gemv_rows<<<H3 / 8, 256>>>(state, W_hh, b_hh, p_gh1, H3);
    // 4. h1_table (fp32 + split)
    gru_h1_kernel<<<V, 256>>>(state);
    // 5. gh2_table[V,3H] (fp32 out)
    gemm_hmma<false, true, false><<<dim3(H3 / 128, V / 128), 256, SMEM_DYN_H>>>(
        p2_h1, p2_Whh, b_hh, p_gh2, nullptr, H3);
    // 6+7. merged step-2 (rel + attr)
    gru_step2_all<<<NREL + NATT, 256>>>(rel_tokens, attr_tokens);
    // 8. gh3[Nr,3H] (fp32 out)
    gemm_hmma<false, true, false><<<dim3(H3 / 128, NREL / 128), 256, SMEM_DYN_H>>>(
        p2_h2rel, p2_Whh, b_hh, p_gh3, nullptr, H3);
    // 9. rel step 3 -> clause split rows [0, 4096)
    gru_step3_kernel<<<NREL, 256>>>(rel_tokens);
    // 10. x1 = relu(clause @ W1^T + b1) (split out)
    gemm_hmma<true, false, true><<<dim3(H / 128, NCL / 128), 256, SMEM_DYN_H>>>(
        p2_clause, p2_W1, b1, nullptr, p2_x1, H);
    // 11. x2 = relu(x1 @ W2^T + b2) (fp32 out)
    gemm_hmma<true, true, false><<<dim3(H / 128, NCL / 128), 256, SMEM_DYN_H>>>(
        p2_x1, p2_W2, b2, p_x2, nullptr, H);
    // 12. logits
    logits_kernel<<<NCL / 8, 256>>>(p_x2, W3, b3);
    // 13. softmax + smoothing
    softmax_kernel<<<1, 1024>>>(eps, out);
}

// round 6
// speedup vs baseline: 5.4646x; 1.7286x over previous
#include <cuda_runtime.h>
#include <cuda_fp16.h>
#include <math.h>
#include <stdint.h>

#define H    1024
#define H3   3072
#define NREL 4096
#define NATT 4096
#define NCL  8192
#define V    256

// ===================== scratch (device globals; no allocations) =====================
__device__ __align__(256) __half g2_table[V * H];
__device__ __align__(256) __half g2_Wemb[H * H];
__device__ __align__(256) __half g2_Wih[H3 * H];
__device__ __align__(256) __half g2_Whh[H3 * H];
__device__ __align__(256) __half g2_W1[H * H];
__device__ __align__(256) __half g2_W2[H * H];
__device__ __align__(256) __half g2_emb[V * H];
__device__ __align__(256) __half g2_h1[V * H];
__device__ __align__(256) __half g2_h2rel[NREL * H];
__device__ __align__(256) __half g2_clause[NCL * H];
__device__ __align__(256) __half g2_x1[NCL * H];
__device__ float g_gi[V * H3];
__device__ float g_gh1[H3];
__device__ float g_h1[V * H];
__device__ float g_gh2[V * H3];
__device__ float g_h2rel[NREL * H];
__device__ float g_gh3[NREL * H3];
__device__ float g_x2[NCL * H];
__device__ float g_logits[NCL];

// ===================== PTX helpers (valid at compute_103, no 'a' features) ============
__device__ __forceinline__ uint32_t smem_u32(const void* p) {
    uint32_t a;
    asm("{ .reg .u64 t; cvta.to.shared.u64 t, %1; cvt.u32.u64 %0, t; }" : "=r"(a) : "l"(p));
    return a;
}
__device__ __forceinline__ void cp16(uint32_t dst, const void* src) {
    asm volatile("cp.async.cg.shared.global [%0], [%1], 16;" :: "r"(dst), "l"(src));
}
__device__ __forceinline__ void cp_commit() {
    asm volatile("cp.async.commit_group;" ::: "memory");
}
template <int N>
__device__ __forceinline__ void cp_wait() {
    asm volatile("cp.async.wait_group %0;" :: "n"(N) : "memory");
}
__device__ __forceinline__ void ldm_x4(uint32_t& r0, uint32_t& r1, uint32_t& r2, uint32_t& r3,
                                       uint32_t addr) {
    asm volatile("ldmatrix.sync.aligned.m8n8.x4.shared.b16 {%0,%1,%2,%3}, [%4];"
                 : "=r"(r0), "=r"(r1), "=r"(r2), "=r"(r3) : "r"(addr));
}
__device__ __forceinline__ void mma16816(float* c, uint32_t a0, uint32_t a1, uint32_t a2,
                                         uint32_t a3, uint32_t b0, uint32_t b1) {
    asm volatile(
        "mma.sync.aligned.m16n8k16.row.col.f32.f16.f16.f32 "
        "{%0,%1,%2,%3}, {%4,%5,%6,%7}, {%8,%9}, {%0,%1,%2,%3};"
        : "+f"(c[0]), "+f"(c[1]), "+f"(c[2]), "+f"(c[3])
        : "r"(a0), "r"(a1), "r"(a2), "r"(a3), "r"(b0), "r"(b1));
}

// ===================== single-pass fp16 HMMA GEMM ==============================
// C[M,N] = A[M,1024] @ B[N,1024]^T + bias; A,B plain fp16 [rows, 1024].
// CTA 128x128, BK=32, 4-stage cp.async pipeline, 32 iterations.
#define APITCH   80                     // bytes per 32-elem fp16 row (64B data + 16B pad)
#define ATILE_B  (128 * APITCH)         // 10240
#define STAGE_B  (2 * ATILE_B)          // 20480 (A then B)
#define NSTAGE   4
#define SMEM_DYN_H (NSTAGE * STAGE_B)   // 81920
#define NIT      32                     // 32 chunks of K=32

__device__ __forceinline__ void cp_stage(const __half* __restrict__ A,
                                         const __half* __restrict__ B,
                                         int bm, int bn, uint32_t sbase, int tid,
                                         int it)
{
    const int kk = it * 32;
#pragma unroll
    for (int h = 0; h < 2; h++) {
        int c = tid + h * 256;
        int row = c >> 2, kc = c & 3;
        cp16(sbase + row * APITCH + kc * 16,
             A + (size_t)(bm + row) * H + kk + kc * 8);
    }
#pragma unroll
    for (int h = 0; h < 2; h++) {
        int c = tid + h * 256;
        int row = c >> 2, kc = c & 3;
        cp16(sbase + ATILE_B + row * APITCH + kc * 16,
             B + (size_t)(bn + row) * H + kk + kc * 8);
    }
}

template <bool RELU, bool OUTF, bool OUTS>
__global__ void __launch_bounds__(256, 2)
gemm_hmma(const __half* __restrict__ A, const __half* __restrict__ B,
          const float* __restrict__ bias, float* __restrict__ Cf,
          __half* __restrict__ Cs, int N)
{
    extern __shared__ char sm[];
    const uint32_t sbase = smem_u32(sm);
    const int tid = threadIdx.x, lane = tid & 31, w = tid >> 5;
    const int bm = blockIdx.y * 128, bn = blockIdx.x * 128;
    const int wm = w & 3, wn = w >> 2;          // warp tile: rows [wm*32,+32), cols [wn*64,+64)

#pragma unroll
    for (int s = 0; s < 3; s++) {
        cp_stage(A, B, bm, bn, sbase + s * STAGE_B, tid, s);
        cp_commit();
    }

    float acc[2][8][4];
#pragma unroll
    for (int mb = 0; mb < 2; mb++)
#pragma unroll
        for (int nb = 0; nb < 8; nb++)
#pragma unroll
            for (int q = 0; q < 4; q++) acc[mb][nb][q] = 0.f;

    const int quad = lane >> 3, li = lane & 7;
    const uint32_t aAddr = sbase +
        (uint32_t)((wm * 32 + (quad & 1) * 8 + li) * APITCH + (quad >> 1) * 16);
    const uint32_t bAddr = sbase + ATILE_B +
        (uint32_t)((wn * 64 + (quad >> 1) * 8 + li) * APITCH + (quad & 1) * 16);

    for (int i = 0; i < NIT; i++) {
        cp_wait<2>();
        __syncthreads();
        if (i + 3 < NIT)
            cp_stage(A, B, bm, bn, sbase + ((i + 3) & 3) * STAGE_B, tid, i + 3);
        cp_commit();

        const uint32_t sa = aAddr + (i & 3) * STAGE_B;
        const uint32_t sb = bAddr + (i & 3) * STAGE_B;
#pragma unroll
        for (int kh = 0; kh < 2; kh++) {
            uint32_t a[2][4];
            ldm_x4(a[0][0], a[0][1], a[0][2], a[0][3], sa + kh * 32);
            ldm_x4(a[1][0], a[1][1], a[1][2], a[1][3], sa + kh * 32 + 16 * APITCH);
            uint32_t b[8][2];
#pragma unroll
            for (int n2 = 0; n2 < 4; n2++)
                ldm_x4(b[2 * n2][0], b[2 * n2][1], b[2 * n2 + 1][0], b[2 * n2 + 1][1],
                       sb + kh * 32 + n2 * 16 * APITCH);
#pragma unroll
            for (int mb = 0; mb < 2; mb++)
#pragma unroll
                for (int nb = 0; nb < 8; nb++)
                    mma16816(acc[mb][nb], a[mb][0], a[mb][1], a[mb][2], a[mb][3],
                             b[nb][0], b[nb][1]);
        }
    }

    const int g = lane >> 2, t = lane & 3;
#pragma unroll
    for (int mb = 0; mb < 2; mb++) {
        const int r0 = bm + wm * 32 + mb * 16 + g;
#pragma unroll
        for (int nb = 0; nb < 8; nb++) {
            const int col = bn + wn * 64 + nb * 8 + t * 2;
            const float b0 = bias[col], b1 = bias[col + 1];
            float v00 = acc[mb][nb][0] + b0, v01 = acc[mb][nb][1] + b1;
            float v10 = acc[mb][nb][2] + b0, v11 = acc[mb][nb][3] + b1;
            if (RELU) {
                v00 = fmaxf(v00, 0.f); v01 = fmaxf(v01, 0.f);
                v10 = fmaxf(v10, 0.f); v11 = fmaxf(v11, 0.f);
            }
            if (OUTF) {
                *(float2*)(Cf + (size_t)r0 * N + col)       = make_float2(v00, v01);
                *(float2*)(Cf + (size_t)(r0 + 8) * N + col) = make_float2(v10, v11);
            }
            if (OUTS) {
                *(__half2*)(Cs + (size_t)r0 * N + col) =
                    __halves2half2(__float2half(v00), __float2half(v01));
                *(__half2*)(Cs + (size_t)(r0 + 8) * N + col) =
                    __halves2half2(__float2half(v10), __float2half(v11));
            }
        }
    }
}

// ===================== fused fp32 -> fp16 convert for ALL 6 operands =====================
#define CVT_ROWS (256 + 1024 + 3072 + 3072 + 1024 + 1024)   // 9472
__global__ void __launch_bounds__(256)
cvt_all(const float* __restrict__ s0, const float* __restrict__ s1,
        const float* __restrict__ s2, const float* __restrict__ s3,
        const float* __restrict__ s4, const float* __restrict__ s5,
        __half* __restrict__ d0, __half* __restrict__ d1,
        __half* __restrict__ d2, __half* __restrict__ d3,
        __half* __restrict__ d4, __half* __restrict__ d5)
{
    int row = blockIdx.x;
    const float* src; __half* dst; int r = row;
    if      (r < 256)        { src = s0; dst = d0; }
    else if ((r -= 256)  < 1024) { src = s1; dst = d1; }
    else if ((r -= 1024) < 3072) { src = s2; dst = d2; }
    else if ((r -= 3072) < 3072) { src = s3; dst = d3; }
    else if ((r -= 3072) < 1024) { src = s4; dst = d4; }
    else     { r -= 1024;      src = s5; dst = d5; }

    int c4 = threadIdx.x * 4;
    float4 x = *(const float4*)(src + (size_t)r * H + c4);
    __half* o = dst + (size_t)r * H + c4;
    *(__half2*)(o)     = __halves2half2(__float2half(x.x), __float2half(x.y));
    *(__half2*)(o + 2) = __halves2half2(__float2half(x.z), __float2half(x.w));
}

// ===================== GEMV (gh1 / logits) =====================
__global__ void gemv_rows(const float* __restrict__ x, const float* __restrict__ W,
                          const float* __restrict__ b, float* __restrict__ out, int Nout)
{
    int n = blockIdx.x * 8 + (threadIdx.x >> 5);
    if (n >= Nout) return;
    int lane = threadIdx.x & 31;
    const float* w = W + (size_t)n * H;
    float s = 0.f;
#pragma unroll
    for (int k = lane * 4; k < H; k += 128) {
        float4 wv = *(const float4*)(w + k);
        float4 xv = *(const float4*)(x + k);
        s = fmaf(wv.x, xv.x, s); s = fmaf(wv.y, xv.y, s);
        s = fmaf(wv.z, xv.z, s); s = fmaf(wv.w, xv.w, s);
    }
#pragma unroll
    for (int o = 16; o; o >>= 1) s += __shfl_xor_sync(0xffffffffu, s, o);
    if (lane == 0) out[n] = s + b[n];
}

__global__ void logits_kernel(const float* __restrict__ X, const float* __restrict__ w3,
                              const float* __restrict__ b3)
{
    int n = blockIdx.x * 8 + (threadIdx.x >> 5);
    int lane = threadIdx.x & 31;
    const float* x = X + (size_t)n * H;
    float s = 0.f;
#pragma unroll
    for (int k = lane * 4; k < H; k += 128) {
        float4 xv = *(const float4*)(x + k);
        float4 wv = *(const float4*)(w3 + k);
        s = fmaf(wv.x, xv.x, s); s = fmaf(wv.y, xv.y, s);
        s = fmaf(wv.z, xv.z, s); s = fmaf(wv.w, xv.w, s);
    }
#pragma unroll
    for (int o = 16; o; o >>= 1) s += __shfl_xor_sync(0xffffffffu, s, o);
    if (lane == 0) g_logits[n] = s + b3[0];
}

// ===================== GRU combine (+ fused fp16 output) =====================
__device__ __forceinline__ float gru1(float ir, float iz, float inn,
                                      float hr, float hz, float hn, float h)
{
    float r = 1.f / (1.f + __expf(-(ir + hr)));
    float z = 1.f / (1.f + __expf(-(iz + hz)));
    float n = tanhf(fmaf(r, hn, inn));
    return fmaf(z, h - n, n);
}
__device__ __forceinline__ float4 gru4(const float* __restrict__ gi,
                                       const float* __restrict__ gh,
                                       const float* __restrict__ h, int j)
{
    float4 ir  = *(const float4*)(gi + j);
    float4 iz  = *(const float4*)(gi + H + j);
    float4 inn = *(const float4*)(gi + 2 * H + j);
    float4 hr  = *(const float4*)(gh + j);
    float4 hz  = *(const float4*)(gh + H + j);
    float4 hn  = *(const float4*)(gh + 2 * H + j);
    float4 hv  = *(const float4*)(h + j);
    float4 o;
    o.x = gru1(ir.x, iz.x, inn.x, hr.x, hz.x, hn.x, hv.x);
    o.y = gru1(ir.y, iz.y, inn.y, hr.y, hz.y, hn.y, hv.y);
    o.z = gru1(ir.z, iz.z, inn.z, hr.z, hz.z, hn.z, hv.z);
    o.w = gru1(ir.w, iz.w, inn.w, hr.w, hz.w, hn.w, hv.w);
    return o;
}
__device__ __forceinline__ void cvt_store(__half* o, float4 v)
{
    *(__half2*)(o)     = __halves2half2(__float2half(v.x), __float2half(v.y));
    *(__half2*)(o + 2) = __halves2half2(__float2half(v.z), __float2half(v.w));
}

__global__ void gru_h1_kernel(const float* __restrict__ state)
{
    int v = blockIdx.x;
    int j = threadIdx.x * 4;
    float4 o = gru4(g_gi + (size_t)v * H3, g_gh1, state, j);
    *(float4*)(g_h1 + (size_t)v * H + j) = o;
    cvt_store(g2_h1 + (size_t)v * H + j, o);
}

// merged rel+attr step 2
__global__ void gru_step2_all(const int* __restrict__ rel_tokens,
                              const int* __restrict__ attr_tokens)
{
    int blk = blockIdx.x;
    int j = threadIdx.x * 4;
    if (blk < NREL) {
        int t0 = rel_tokens[blk * 3 + 0];
        int t1 = rel_tokens[blk * 3 + 1];
        float4 o = gru4(g_gi + (size_t)t1 * H3, g_gh2 + (size_t)t0 * H3,
                        g_h1 + (size_t)t0 * H, j);
        *(float4*)(g_h2rel + (size_t)blk * H + j) = o;
        cvt_store(g2_h2rel + (size_t)blk * H + j, o);
    } else {
        int n = blk - NREL;
        int t0 = attr_tokens[n * 2 + 0];
        int t1 = attr_tokens[n * 2 + 1];
        float4 o = gru4(g_gi + (size_t)t1 * H3, g_gh2 + (size_t)t0 * H3,
                        g_h1 + (size_t)t0 * H, j);
        cvt_store(g2_clause + (size_t)(NREL + n) * H + j, o);
    }
}

__global__ void gru_step3_kernel(const int* __restrict__ rel_tokens)
{
    int n  = blockIdx.x;
    int t2 = rel_tokens[n * 3 + 2];
    int j  = threadIdx.x * 4;
    float4 o = gru4(g_gi + (size_t)t2 * H3, g_gh3 + (size_t)n * H3, g_h2rel + (size_t)n * H, j);
    cvt_store(g2_clause + (size_t)n * H + j, o);
}

// ===================== softmax + eps smoothing =====================
__global__ void softmax_kernel(const float* __restrict__ eps, float* __restrict__ out)
{
    const int N = NCL;
    __shared__ float shm[32], shs[32];
    int tid = threadIdx.x;

    float m = -1e30f;
    for (int i = tid; i < N; i += 1024) m = fmaxf(m, g_logits[i]);
#pragma unroll
    for (int o = 16; o; o >>= 1) m = fmaxf(m, __shfl_xor_sync(0xffffffffu, m, o));
    if ((tid & 31) == 0) shm[tid >> 5] = m;
    __syncthreads();
    if (tid < 32) {
        float v = shm[tid];
#pragma unroll
        for (int o = 16; o; o >>= 1) v = fmaxf(v, __shfl_xor_sync(0xffffffffu, v, o));
        shm[tid] = v;
    }
    __syncthreads();
    float M = shm[0];

    float s = 0.f;
    for (int i = tid; i < N; i += 1024) s += __expf(g_logits[i] - M);
#pragma unroll
    for (int o = 16; o; o >>= 1) s += __shfl_xor_sync(0xffffffffu, s, o);
    if ((tid & 31) == 0) shs[tid >> 5] = s;
    __syncthreads();
    if (tid < 32) {
        float v = shs[tid];
#pragma unroll
        for (int o = 16; o; o >>= 1) v += __shfl_xor_sync(0xffffffffu, v, o);
        shs[tid] = v;
    }
    __syncthreads();
    float S = shs[0];
    float e = eps[0];
    float inv = (1.f - e) / S;
    float add = e / (float)N;
    for (int i = tid; i < N; i += 1024)
        out[i] = __expf(g_logits[i] - M) * inv + add;
}

// ===================== launch =====================
extern "C" void kernel_launch(void* const* d_in, const int* in_sizes, int n_in,
                              void* d_out, int out_size)
{
    const float* state       = (const float*)d_in[0];
    const int*   rel_tokens  = (const int*)d_in[1];
    const int*   attr_tokens = (const int*)d_in[2];
    const float* table       = (const float*)d_in[3];
    const float* W_emb       = (const float*)d_in[4];
    const float* b_emb       = (const float*)d_in[5];
    const float* W_ih        = (const float*)d_in[6];
    const float* W_hh        = (const float*)d_in[7];
    const float* b_ih        = (const float*)d_in[8];
    const float* b_hh        = (const float*)d_in[9];
    const float* W1          = (const float*)d_in[10];
    const float* b1          = (const float*)d_in[11];
    const float* W2          = (const float*)d_in[12];
    const float* b2          = (const float*)d_in[13];
    const float* W3          = (const float*)d_in[14];
    const float* b3          = (const float*)d_in[15];
    const float* eps         = (const float*)d_in[16];
    float* out = (float*)d_out;

    __half *p2_table, *p2_Wemb, *p2_Wih, *p2_Whh, *p2_W1, *p2_W2;
    __half *p2_emb, *p2_h1, *p2_h2rel, *p2_clause, *p2_x1;
    float *p_gi, *p_gh1, *p_gh2, *p_h2rel, *p_gh3, *p_x2;
    cudaGetSymbolAddress((void**)&p2_table,  g2_table);
    cudaGetSymbolAddress((void**)&p2_Wemb,   g2_Wemb);
    cudaGetSymbolAddress((void**)&p2_Wih,    g2_Wih);
    cudaGetSymbolAddress((void**)&p2_Whh,    g2_Whh);
    cudaGetSymbolAddress((void**)&p2_W1,     g2_W1);
    cudaGetSymbolAddress((void**)&p2_W2,     g2_W2);
    cudaGetSymbolAddress((void**)&p2_emb,    g2_emb);
    cudaGetSymbolAddress((void**)&p2_h1,     g2_h1);
    cudaGetSymbolAddress((void**)&p2_h2rel,  g2_h2rel);
    cudaGetSymbolAddress((void**)&p2_clause, g2_clause);
    cudaGetSymbolAddress((void**)&p2_x1,     g2_x1);
    cudaGetSymbolAddress((void**)&p_gi,      g_gi);
    cudaGetSymbolAddress((void**)&p_gh1,     g_gh1);
    cudaGetSymbolAddress((void**)&p_gh2,     g_gh2);
    cudaGetSymbolAddress((void**)&p_h2rel,   g_h2rel);
    cudaGetSymbolAddress((void**)&p_gh3,     g_gh3);
    cudaGetSymbolAddress((void**)&p_x2,      g_x2);

    cudaFuncSetAttribute(gemm_hmma<false, false, true>,
                         cudaFuncAttributeMaxDynamicSharedMemorySize, SMEM_DYN_H);
    cudaFuncSetAttribute(gemm_hmma<false, true, false>,
                         cudaFuncAttributeMaxDynamicSharedMemorySize, SMEM_DYN_H);
    cudaFuncSetAttribute(gemm_hmma<true, false, true>,
                         cudaFuncAttributeMaxDynamicSharedMemorySize, SMEM_DYN_H);
    cudaFuncSetAttribute(gemm_hmma<true, true, false>,
                         cudaFuncAttributeMaxDynamicSharedMemorySize, SMEM_DYN_H);

    // 0. convert all fp32 operands to fp16 in one launch
    cvt_all<<<CVT_ROWS, 256>>>(table, W_emb, W_ih, W_hh, W1, W2,
                               p2_table, p2_Wemb, p2_Wih, p2_Whh, p2_W1, p2_W2);

    // 1. emb_proj[V,H] (fp16 out)
    gemm_hmma<false, false, true><<<dim3(H / 128, V / 128), 256, SMEM_DYN_H>>>(
        p2_table, p2_Wemb, b_emb, nullptr, p2_emb, H);
    // 2. gi_table[V,3H] (fp32 out)
    gemm_hmma<false, true, false><<<dim3(H3 / 128, V / 128), 256, SMEM_DYN_H>>>(
        p2_emb, p2_Wih, b_ih, p_gi, nullptr, H3);
    // 3. gh1 = state @ W_hh^T + b_hh (exact fp32 GEMV)
    gemv_rows<<<H3 / 8, 256>>>(state, W_hh, b_hh, p_gh1, H3);
    // 4. h1_table (fp32 + fp16)
    gru_h1_kernel<<<V, 256>>>(state);
    // 5. gh2_table[V,3H] (fp32 out)
    gemm_hmma<false, true, false><<<dim3(H3 / 128, V / 128), 256, SMEM_DYN_H>>>(
        p2_h1, p2_Whh, b_hh, p_gh2, nullptr, H3);
    // 6+7. merged step-2 (rel + attr)
    gru_step2_all<<<NREL + NATT, 256>>>(rel_tokens, attr_tokens);
    // 8. gh3[Nr,3H] (fp32 out)
    gemm_hmma<false, true, false><<<dim3(H3 / 128, NREL / 128), 256, SMEM_DYN_H>>>(
        p2_h2rel, p2_Whh, b_hh, p_gh3, nullptr, H3);
    // 9. rel step 3 -> clause fp16 rows [0, 4096)
    gru_step3_kernel<<<NREL, 256>>>(rel_tokens);
    // 10. x1 = relu(clause @ W1^T + b1) (fp16 out)
    gemm_hmma<true, false, true><<<dim3(H / 128, NCL / 128), 256, SMEM_DYN_H>>>(
        p2_clause, p2_W1, b1, nullptr, p2_x1, H);
    // 11. x2 = relu(x1 @ W2^T + b2) (fp32 out)
    gemm_hmma<true, true, false><<<dim3(H / 128, NCL / 128), 256, SMEM_DYN_H>>>(
        p2_x1, p2_W2, b2, p_x2, nullptr, H);
    // 12. logits
    logits_kernel<<<NCL / 8, 256>>>(p_x2, W3, b3);
    // 13. softmax + smoothing
    softmax_kernel<<<1, 1024>>>(eps, out);
}

// round 7
// speedup vs baseline: 5.9602x; 1.0907x over previous
#include <cuda_runtime.h>
#include <cuda_fp16.h>
#include <math.h>
#include <stdint.h>

#define H    1024
#define H3   3072
#define NREL 4096
#define NATT 4096
#define NCL  8192
#define V    256

// ===================== scratch (device globals; no allocations) =====================
__device__ __align__(256) __half g2_table[V * H];
__device__ __align__(256) __half g2_Wemb[H * H];
__device__ __align__(256) __half g2_Wih[H3 * H];
__device__ __align__(256) __half g2_Whh[H3 * H];
__device__ __align__(256) __half g2_W1[H * H];
__device__ __align__(256) __half g2_W2[H * H];
__device__ __align__(256) __half g2_emb[V * H];
__device__ __align__(256) __half g2_h1[V * H];
__device__ __align__(256) __half g2_h2rel[NREL * H];
__device__ __align__(256) __half g2_clause[NCL * H];
__device__ __align__(256) __half g2_x1[NCL * H];
__device__ float g_gi[V * H3];
__device__ float g_gh1[H3];
__device__ float g_h1[V * H];
__device__ float g_gh2[V * H3];
__device__ float g_h2rel[NREL * H];
__device__ float g_gh3[NREL * H3];
__device__ float g_x2[NCL * H];
__device__ float g_logits[NCL];

// ===================== PTX helpers (valid at compute_103, no 'a' features) ============
__device__ __forceinline__ uint32_t smem_u32(const void* p) {
    uint32_t a;
    asm("{ .reg .u64 t; cvta.to.shared.u64 t, %1; cvt.u32.u64 %0, t; }" : "=r"(a) : "l"(p));
    return a;
}
__device__ __forceinline__ void cp16(uint32_t dst, const void* src) {
    asm volatile("cp.async.cg.shared.global [%0], [%1], 16;" :: "r"(dst), "l"(src));
}
__device__ __forceinline__ void cp_commit() {
    asm volatile("cp.async.commit_group;" ::: "memory");
}
template <int N>
__device__ __forceinline__ void cp_wait() {
    asm volatile("cp.async.wait_group %0;" :: "n"(N) : "memory");
}
__device__ __forceinline__ void ldm_x4(uint32_t& r0, uint32_t& r1, uint32_t& r2, uint32_t& r3,
                                       uint32_t addr) {
    asm volatile("ldmatrix.sync.aligned.m8n8.x4.shared.b16 {%0,%1,%2,%3}, [%4];"
                 : "=r"(r0), "=r"(r1), "=r"(r2), "=r"(r3) : "r"(addr));
}
__device__ __forceinline__ void mma16816(float* c, uint32_t a0, uint32_t a1, uint32_t a2,
                                         uint32_t a3, uint32_t b0, uint32_t b1) {
    asm volatile(
        "mma.sync.aligned.m16n8k16.row.col.f32.f16.f16.f32 "
        "{%0,%1,%2,%3}, {%4,%5,%6,%7}, {%8,%9}, {%0,%1,%2,%3};"
        : "+f"(c[0]), "+f"(c[1]), "+f"(c[2]), "+f"(c[3])
        : "r"(a0), "r"(a1), "r"(a2), "r"(a3), "r"(b0), "r"(b1));
}

#define APITCH   80                     // bytes per 32-elem fp16 row (64B data + 16B pad)
#define NIT      32                     // 32 chunks of K=32

// ===================== 128x128 fp16 HMMA GEMM (big-M GEMMs) ====================
#define ATILE_B  (128 * APITCH)         // 10240
#define STAGE_B  (2 * ATILE_B)          // 20480 (A then B)
#define SMEM_DYN_H (4 * STAGE_B)        // 81920

__device__ __forceinline__ void cp_stage(const __half* __restrict__ A,
                                         const __half* __restrict__ B,
                                         int bm, int bn, uint32_t sbase, int tid,
                                         int it)
{
    const int kk = it * 32;
#pragma unroll
    for (int h = 0; h < 2; h++) {
        int c = tid + h * 256;
        int row = c >> 2, kc = c & 3;
        cp16(sbase + row * APITCH + kc * 16,
             A + (size_t)(bm + row) * H + kk + kc * 8);
    }
#pragma unroll
    for (int h = 0; h < 2; h++) {
        int c = tid + h * 256;
        int row = c >> 2, kc = c & 3;
        cp16(sbase + ATILE_B + row * APITCH + kc * 16,
             B + (size_t)(bn + row) * H + kk + kc * 8);
    }
}

template <bool RELU, bool OUTF, bool OUTS>
__global__ void __launch_bounds__(256, 2)
gemm_hmma(const __half* __restrict__ A, const __half* __restrict__ B,
          const float* __restrict__ bias, float* __restrict__ Cf,
          __half* __restrict__ Cs, int N)
{
    extern __shared__ char sm[];
    const uint32_t sbase = smem_u32(sm);
    const int tid = threadIdx.x, lane = tid & 31, w = tid >> 5;
    const int bm = blockIdx.y * 128, bn = blockIdx.x * 128;
    const int wm = w & 3, wn = w >> 2;

#pragma unroll
    for (int s = 0; s < 3; s++) {
        cp_stage(A, B, bm, bn, sbase + s * STAGE_B, tid, s);
        cp_commit();
    }

    float acc[2][8][4];
#pragma unroll
    for (int mb = 0; mb < 2; mb++)
#pragma unroll
        for (int nb = 0; nb < 8; nb++)
#pragma unroll
            for (int q = 0; q < 4; q++) acc[mb][nb][q] = 0.f;

    const int quad = lane >> 3, li = lane & 7;
    const uint32_t aAddr = sbase +
        (uint32_t)((wm * 32 + (quad & 1) * 8 + li) * APITCH + (quad >> 1) * 16);
    const uint32_t bAddr = sbase + ATILE_B +
        (uint32_t)((wn * 64 + (quad >> 1) * 8 + li) * APITCH + (quad & 1) * 16);

    for (int i = 0; i < NIT; i++) {
        cp_wait<2>();
        __syncthreads();
        if (i + 3 < NIT)
            cp_stage(A, B, bm, bn, sbase + ((i + 3) & 3) * STAGE_B, tid, i + 3);
        cp_commit();

        const uint32_t sa = aAddr + (i & 3) * STAGE_B;
        const uint32_t sb = bAddr + (i & 3) * STAGE_B;
#pragma unroll
        for (int kh = 0; kh < 2; kh++) {
            uint32_t a[2][4];
            ldm_x4(a[0][0], a[0][1], a[0][2], a[0][3], sa + kh * 32);
            ldm_x4(a[1][0], a[1][1], a[1][2], a[1][3], sa + kh * 32 + 16 * APITCH);
            uint32_t b[8][2];
#pragma unroll
            for (int n2 = 0; n2 < 4; n2++)
                ldm_x4(b[2 * n2][0], b[2 * n2][1], b[2 * n2 + 1][0], b[2 * n2 + 1][1],
                       sb + kh * 32 + n2 * 16 * APITCH);
#pragma unroll
            for (int mb = 0; mb < 2; mb++)
#pragma unroll
                for (int nb = 0; nb < 8; nb++)
                    mma16816(acc[mb][nb], a[mb][0], a[mb][1], a[mb][2], a[mb][3],
                             b[nb][0], b[nb][1]);
        }
    }

    const int g = lane >> 2, t = lane & 3;
#pragma unroll
    for (int mb = 0; mb < 2; mb++) {
        const int r0 = bm + wm * 32 + mb * 16 + g;
#pragma unroll
        for (int nb = 0; nb < 8; nb++) {
            const int col = bn + wn * 64 + nb * 8 + t * 2;
            const float b0 = bias[col], b1 = bias[col + 1];
            float v00 = acc[mb][nb][0] + b0, v01 = acc[mb][nb][1] + b1;
            float v10 = acc[mb][nb][2] + b0, v11 = acc[mb][nb][3] + b1;
            if (RELU) {
                v00 = fmaxf(v00, 0.f); v01 = fmaxf(v01, 0.f);
                v10 = fmaxf(v10, 0.f); v11 = fmaxf(v11, 0.f);
            }
            if (OUTF) {
                *(float2*)(Cf + (size_t)r0 * N + col)       = make_float2(v00, v01);
                *(float2*)(Cf + (size_t)(r0 + 8) * N + col) = make_float2(v10, v11);
            }
            if (OUTS) {
                *(__half2*)(Cs + (size_t)r0 * N + col) =
                    __halves2half2(__float2half(v00), __float2half(v01));
                *(__half2*)(Cs + (size_t)(r0 + 8) * N + col) =
                    __halves2half2(__float2half(v10), __float2half(v11));
            }
        }
    }
}

// ===================== 64x64 fp16 HMMA GEMM (small-M GEMMs 1/2/5) ==============
// 8 warps, warp tile 32x16 (wm = w&1, wn = w>>1). Same 4-stage cp.async pipeline.
#define ATILE64_B (64 * APITCH)          // 5120
#define STAGE64_B (2 * ATILE64_B)        // 10240
#define SMEM_DYN64 (4 * STAGE64_B)       // 40960 (< 48KB, no opt-in needed)

__device__ __forceinline__ void cp_stage64(const __half* __restrict__ A,
                                           const __half* __restrict__ B,
                                           int bm, int bn, uint32_t sbase, int tid,
                                           int it)
{
    const int kk = it * 32;
    {
        int row = tid >> 2, kc = tid & 3;   // 256 threads -> 64 rows x 4 chunks
        cp16(sbase + row * APITCH + kc * 16,
             A + (size_t)(bm + row) * H + kk + kc * 8);
        cp16(sbase + ATILE64_B + row * APITCH + kc * 16,
             B + (size_t)(bn + row) * H + kk + kc * 8);
    }
}

template <bool OUTF, bool OUTS>
__global__ void __launch_bounds__(256, 2)
gemm_hmma64(const __half* __restrict__ A, const __half* __restrict__ B,
            const float* __restrict__ bias, float* __restrict__ Cf,
            __half* __restrict__ Cs, int N)
{
    extern __shared__ char sm[];
    const uint32_t sbase = smem_u32(sm);
    const int tid = threadIdx.x, lane = tid & 31, w = tid >> 5;
    const int bm = blockIdx.y * 64, bn = blockIdx.x * 64;
    const int wm = w & 1, wn = w >> 1;      // warp tile: rows [wm*32,+32), cols [wn*16,+16)

#pragma unroll
    for (int s = 0; s < 3; s++) {
        cp_stage64(A, B, bm, bn, sbase + s * STAGE64_B, tid, s);
        cp_commit();
    }

    float acc[2][2][4];
#pragma unroll
    for (int mb = 0; mb < 2; mb++)
#pragma unroll
        for (int nb = 0; nb < 2; nb++)
#pragma unroll
            for (int q = 0; q < 4; q++) acc[mb][nb][q] = 0.f;

    const int quad = lane >> 3, li = lane & 7;
    const uint32_t aAddr = sbase +
        (uint32_t)((wm * 32 + (quad & 1) * 8 + li) * APITCH + (quad >> 1) * 16);
    const uint32_t bAddr = sbase + ATILE64_B +
        (uint32_t)((wn * 16 + (quad >> 1) * 8 + li) * APITCH + (quad & 1) * 16);

    for (int i = 0; i < NIT; i++) {
        cp_wait<2>();
        __syncthreads();
        if (i + 3 < NIT)
            cp_stage64(A, B, bm, bn, sbase + ((i + 3) & 3) * STAGE64_B, tid, i + 3);
        cp_commit();

        const uint32_t sa = aAddr + (i & 3) * STAGE64_B;
        const uint32_t sb = bAddr + (i & 3) * STAGE64_B;
#pragma unroll
        for (int kh = 0; kh < 2; kh++) {
            uint32_t a[2][4];
            ldm_x4(a[0][0], a[0][1], a[0][2], a[0][3], sa + kh * 32);
            ldm_x4(a[1][0], a[1][1], a[1][2], a[1][3], sa + kh * 32 + 16 * APITCH);
            uint32_t b[2][2];
            ldm_x4(b[0][0], b[0][1], b[1][0], b[1][1], sb + kh * 32);
#pragma unroll
            for (int mb = 0; mb < 2; mb++)
#pragma unroll
                for (int nb = 0; nb < 2; nb++)
                    mma16816(acc[mb][nb], a[mb][0], a[mb][1], a[mb][2], a[mb][3],
                             b[nb][0], b[nb][1]);
        }
    }

    const int g = lane >> 2, t = lane & 3;
#pragma unroll
    for (int mb = 0; mb < 2; mb++) {
        const int r0 = bm + wm * 32 + mb * 16 + g;
#pragma unroll
        for (int nb = 0; nb < 2; nb++) {
            const int col = bn + wn * 16 + nb * 8 + t * 2;
            const float b0 = bias[col], b1 = bias[col + 1];
            float v00 = acc[mb][nb][0] + b0, v01 = acc[mb][nb][1] + b1;
            float v10 = acc[mb][nb][2] + b0, v11 = acc[mb][nb][3] + b1;
            if (OUTF) {
                *(float2*)(Cf + (size_t)r0 * N + col)       = make_float2(v00, v01);
                *(float2*)(Cf + (size_t)(r0 + 8) * N + col) = make_float2(v10, v11);
            }
            if (OUTS) {
                *(__half2*)(Cs + (size_t)r0 * N + col) =
                    __halves2half2(__float2half(v00), __float2half(v01));
                *(__half2*)(Cs + (size_t)(r0 + 8) * N + col) =
                    __halves2half2(__float2half(v10), __float2half(v11));
            }
        }
    }
}

// ===================== fused fp32 -> fp16 convert for ALL 6 operands =====================
#define CVT_ROWS (256 + 1024 + 3072 + 3072 + 1024 + 1024)   // 9472
__global__ void __launch_bounds__(256)
cvt_all(const float* __restrict__ s0, const float* __restrict__ s1,
        const float* __restrict__ s2, const float* __restrict__ s3,
        const float* __restrict__ s4, const float* __restrict__ s5,
        __half* __restrict__ d0, __half* __restrict__ d1,
        __half* __restrict__ d2, __half* __restrict__ d3,
        __half* __restrict__ d4, __half* __restrict__ d5)
{
    int row = blockIdx.x;
    const float* src; __half* dst; int r = row;
    if      (r < 256)        { src = s0; dst = d0; }
    else if ((r -= 256)  < 1024) { src = s1; dst = d1; }
    else if ((r -= 1024) < 3072) { src = s2; dst = d2; }
    else if ((r -= 3072) < 3072) { src = s3; dst = d3; }
    else if ((r -= 3072) < 1024) { src = s4; dst = d4; }
    else     { r -= 1024;      src = s5; dst = d5; }

    int c4 = threadIdx.x * 4;
    float4 x = *(const float4*)(src + (size_t)r * H + c4);
    __half* o = dst + (size_t)r * H + c4;
    *(__half2*)(o)     = __halves2half2(__float2half(x.x), __float2half(x.y));
    *(__half2*)(o + 2) = __halves2half2(__float2half(x.z), __float2half(x.w));
}

// ===================== GEMV (gh1 / logits) =====================
__global__ void gemv_rows(const float* __restrict__ x, const float* __restrict__ W,
                          const float* __restrict__ b, float* __restrict__ out, int Nout)
{
    int n = blockIdx.x * 8 + (threadIdx.x >> 5);
    if (n >= Nout) return;
    int lane = threadIdx.x & 31;
    const float* w = W + (size_t)n * H;
    float s = 0.f;
#pragma unroll
    for (int k = lane * 4; k < H; k += 128) {
        float4 wv = *(const float4*)(w + k);
        float4 xv = *(const float4*)(x + k);
        s = fmaf(wv.x, xv.x, s); s = fmaf(wv.y, xv.y, s);
        s = fmaf(wv.z, xv.z, s); s = fmaf(wv.w, xv.w, s);
    }
#pragma unroll
    for (int o = 16; o; o >>= 1) s += __shfl_xor_sync(0xffffffffu, s, o);
    if (lane == 0) out[n] = s + b[n];
}

__global__ void logits_kernel(const float* __restrict__ X, const float* __restrict__ w3,
                              const float* __restrict__ b3)
{
    int n = blockIdx.x * 8 + (threadIdx.x >> 5);
    int lane = threadIdx.x & 31;
    const float* x = X + (size_t)n * H;
    float s = 0.f;
#pragma unroll
    for (int k = lane * 4; k < H; k += 128) {
        float4 xv = *(const float4*)(x + k);
        float4 wv = *(const float4*)(w3 + k);
        s = fmaf(wv.x, xv.x, s); s = fmaf(wv.y, xv.y, s);
        s = fmaf(wv.z, xv.z, s); s = fmaf(wv.w, xv.w, s);
    }
#pragma unroll
    for (int o = 16; o; o >>= 1) s += __shfl_xor_sync(0xffffffffu, s, o);
    if (lane == 0) g_logits[n] = s + b3[0];
}

// ===================== GRU combine (+ fused fp16 output) =====================
__device__ __forceinline__ float gru1(float ir, float iz, float inn,
                                      float hr, float hz, float hn, float h)
{
    float r = 1.f / (1.f + __expf(-(ir + hr)));
    float z = 1.f / (1.f + __expf(-(iz + hz)));
    float n = tanhf(fmaf(r, hn, inn));
    return fmaf(z, h - n, n);
}
__device__ __forceinline__ float4 gru4(const float* __restrict__ gi,
                                       const float* __restrict__ gh,
                                       const float* __restrict__ h, int j)
{
    float4 ir  = *(const float4*)(gi + j);
    float4 iz  = *(const float4*)(gi + H + j);
    float4 inn = *(const float4*)(gi + 2 * H + j);
    float4 hr  = *(const float4*)(gh + j);
    float4 hz  = *(const float4*)(gh + H + j);
    float4 hn  = *(const float4*)(gh + 2 * H + j);
    float4 hv  = *(const float4*)(h + j);
    float4 o;
    o.x = gru1(ir.x, iz.x, inn.x, hr.x, hz.x, hn.x, hv.x);
    o.y = gru1(ir.y, iz.y, inn.y, hr.y, hz.y, hn.y, hv.y);
    o.z = gru1(ir.z, iz.z, inn.z, hr.z, hz.z, hn.z, hv.z);
    o.w = gru1(ir.w, iz.w, inn.w, hr.w, hz.w, hn.w, hv.w);
    return o;
}
__device__ __forceinline__ void cvt_store(__half* o, float4 v)
{
    *(__half2*)(o)     = __halves2half2(__float2half(v.x), __float2half(v.y));
    *(__half2*)(o + 2) = __halves2half2(__float2half(v.z), __float2half(v.w));
}

__global__ void gru_h1_kernel(const float* __restrict__ state)
{
    int v = blockIdx.x;
    int j = threadIdx.x * 4;
    float4 o = gru4(g_gi + (size_t)v * H3, g_gh1, state, j);
    *(float4*)(g_h1 + (size_t)v * H + j) = o;
    cvt_store(g2_h1 + (size_t)v * H + j, o);
}

// merged rel+attr step 2
__global__ void gru_step2_all(const int* __restrict__ rel_tokens,
                              const int* __restrict__ attr_tokens)
{
    int blk = blockIdx.x;
    int j = threadIdx.x * 4;
    if (blk < NREL) {
        int t0 = rel_tokens[blk * 3 + 0];
        int t1 = rel_tokens[blk * 3 + 1];
        float4 o = gru4(g_gi + (size_t)t1 * H3, g_gh2 + (size_t)t0 * H3,
                        g_h1 + (size_t)t0 * H, j);
        *(float4*)(g_h2rel + (size_t)blk * H + j) = o;
        cvt_store(g2_h2rel + (size_t)blk * H + j, o);
    } else {
        int n = blk - NREL;
        int t0 = attr_tokens[n * 2 + 0];
        int t1 = attr_tokens[n * 2 + 1];
        float4 o = gru4(g_gi + (size_t)t1 * H3, g_gh2 + (size_t)t0 * H3,
                        g_h1 + (size_t)t0 * H, j);
        cvt_store(g2_clause + (size_t)(NREL + n) * H + j, o);
    }
}

__global__ void gru_step3_kernel(const int* __restrict__ rel_tokens)
{
    int n  = blockIdx.x;
    int t2 = rel_tokens[n * 3 + 2];
    int j  = threadIdx.x * 4;
    float4 o = gru4(g_gi + (size_t)t2 * H3, g_gh3 + (size_t)n * H3, g_h2rel + (size_t)n * H, j);
    cvt_store(g2_clause + (size_t)n * H + j, o);
}

// ===================== softmax + eps smoothing =====================
__global__ void softmax_kernel(const float* __restrict__ eps, float* __restrict__ out)
{
    const int N = NCL;
    __shared__ float shm[32], shs[32];
    int tid = threadIdx.x;

    float m = -1e30f;
    for (int i = tid; i < N; i += 1024) m = fmaxf(m, g_logits[i]);
#pragma unroll
    for (int o = 16; o; o >>= 1) m = fmaxf(m, __shfl_xor_sync(0xffffffffu, m, o));
    if ((tid & 31) == 0) shm[tid >> 5] = m;
    __syncthreads();
    if (tid < 32) {
        float v = shm[tid];
#pragma unroll
        for (int o = 16; o; o >>= 1) v = fmaxf(v, __shfl_xor_sync(0xffffffffu, v, o));
        shm[tid] = v;
    }
    __syncthreads();
    float M = shm[0];

    float s = 0.f;
    for (int i = tid; i < N; i += 1024) s += __expf(g_logits[i] - M);
#pragma unroll
    for (int o = 16; o; o >>= 1) s += __shfl_xor_sync(0xffffffffu, s, o);
    if ((tid & 31) == 0) shs[tid >> 5] = s;
    __syncthreads();
    if (tid < 32) {
        float v = shs[tid];
#pragma unroll
        for (int o = 16; o; o >>= 1) v += __shfl_xor_sync(0xffffffffu, v, o);
        shs[tid] = v;
    }
    __syncthreads();
    float S = shs[0];
    float e = eps[0];
    float inv = (1.f - e) / S;
    float add = e / (float)N;
    for (int i = tid; i < N; i += 1024)
        out[i] = __expf(g_logits[i] - M) * inv + add;
}

// ===================== launch =====================
extern "C" void kernel_launch(void* const* d_in, const int* in_sizes, int n_in,
                              void* d_out, int out_size)
{
    const float* state       = (const float*)d_in[0];
    const int*   rel_tokens  = (const int*)d_in[1];
    const int*   attr_tokens = (const int*)d_in[2];
    const float* table       = (const float*)d_in[3];
    const float* W_emb       = (const float*)d_in[4];
    const float* b_emb       = (const float*)d_in[5];
    const float* W_ih        = (const float*)d_in[6];
    const float* W_hh        = (const float*)d_in[7];
    const float* b_ih        = (const float*)d_in[8];
    const float* b_hh        = (const float*)d_in[9];
    const float* W1          = (const float*)d_in[10];
    const float* b1          = (const float*)d_in[11];
    const float* W2          = (const float*)d_in[12];
    const float* b2          = (const float*)d_in[13];
    const float* W3          = (const float*)d_in[14];
    const float* b3          = (const float*)d_in[15];
    const float* eps         = (const float*)d_in[16];
    float* out = (float*)d_out;

    __half *p2_table, *p2_Wemb, *p2_Wih, *p2_Whh, *p2_W1, *p2_W2;
    __half *p2_emb, *p2_h1, *p2_h2rel, *p2_clause, *p2_x1;
    float *p_gi, *p_gh1, *p_gh2, *p_h2rel, *p_gh3, *p_x2;
    cudaGetSymbolAddress((void**)&p2_table,  g2_table);
    cudaGetSymbolAddress((void**)&p2_Wemb,   g2_Wemb);
    cudaGetSymbolAddress((void**)&p2_Wih,    g2_Wih);
    cudaGetSymbolAddress((void**)&p2_Whh,    g2_Whh);
    cudaGetSymbolAddress((void**)&p2_W1,     g2_W1);
    cudaGetSymbolAddress((void**)&p2_W2,     g2_W2);
    cudaGetSymbolAddress((void**)&p2_emb,    g2_emb);
    cudaGetSymbolAddress((void**)&p2_h1,     g2_h1);
    cudaGetSymbolAddress((void**)&p2_h2rel,  g2_h2rel);
    cudaGetSymbolAddress((void**)&p2_clause, g2_clause);
    cudaGetSymbolAddress((void**)&p2_x1,     g2_x1);
    cudaGetSymbolAddress((void**)&p_gi,      g_gi);
    cudaGetSymbolAddress((void**)&p_gh1,     g_gh1);
    cudaGetSymbolAddress((void**)&p_gh2,     g_gh2);
    cudaGetSymbolAddress((void**)&p_h2rel,   g_h2rel);
    cudaGetSymbolAddress((void**)&p_gh3,     g_gh3);
    cudaGetSymbolAddress((void**)&p_x2,      g_x2);

    cudaFuncSetAttribute(gemm_hmma<false, true, false>,
                         cudaFuncAttributeMaxDynamicSharedMemorySize, SMEM_DYN_H);
    cudaFuncSetAttribute(gemm_hmma<true, false, true>,
                         cudaFuncAttributeMaxDynamicSharedMemorySize, SMEM_DYN_H);
    cudaFuncSetAttribute(gemm_hmma<true, true, false>,
                         cudaFuncAttributeMaxDynamicSharedMemorySize, SMEM_DYN_H);

    // 0. convert all fp32 operands to fp16 in one launch
    cvt_all<<<CVT_ROWS, 256>>>(table, W_emb, W_ih, W_hh, W1, W2,
                               p2_table, p2_Wemb, p2_Wih, p2_Whh, p2_W1, p2_W2);

    // 1. emb_proj[V,H] (fp16 out) — small-M, 64x64 tiles: grid 16x4 = 64 CTAs
    gemm_hmma64<false, true><<<dim3(H / 64, V / 64), 256, SMEM_DYN64>>>(
        p2_table, p2_Wemb, b_emb, nullptr, p2_emb, H);
    // 2. gi_table[V,3H] (fp32 out) — 48x4 = 192 CTAs
    gemm_hmma64<true, false><<<dim3(H3 / 64, V / 64), 256, SMEM_DYN64>>>(
        p2_emb, p2_Wih, b_ih, p_gi, nullptr, H3);
    // 3. gh1 = state @ W_hh^T + b_hh (exact fp32 GEMV)
    gemv_rows<<<H3 / 8, 256>>>(state, W_hh, b_hh, p_gh1, H3);
    // 4. h1_table (fp32 + fp16)
    gru_h1_kernel<<<V, 256>>>(state);
    // 5. gh2_table[V,3H] (fp32 out) — 48x4 = 192 CTAs
    gemm_hmma64<true, false><<<dim3(H3 / 64, V / 64), 256, SMEM_DYN64>>>(
        p2_h1, p2_Whh, b_hh, p_gh2, nullptr, H3);
    // 6+7. merged step-2 (rel + attr)
    gru_step2_all<<<NREL + NATT, 256>>>(rel_tokens, attr_tokens);
    // 8. gh3[Nr,3H] (fp32 out) — big: 128x128 tiles
    gemm_hmma<false, true, false><<<dim3(H3 / 128, NREL / 128), 256, SMEM_DYN_H>>>(
        p2_h2rel, p2_Whh, b_hh, p_gh3, nullptr, H3);
    // 9. rel step 3 -> clause fp16 rows [0, 4096)
    gru_step3_kernel<<<NREL, 256>>>(rel_tokens);
    // 10. x1 = relu(clause @ W1^T + b1) (fp16 out)
    gemm_hmma<true, false, true><<<dim3(H / 128, NCL / 128), 256, SMEM_DYN_H>>>(
        p2_clause, p2_W1, b1, nullptr, p2_x1, H);
    // 11. x2 = relu(x1 @ W2^T + b2) (fp32 out)
    gemm_hmma<true, true, false><<<dim3(H / 128, NCL / 128), 256, SMEM_DYN_H>>>(
        p2_x1, p2_W2, b2, p_x2, nullptr, H);
    // 12. logits
    logits_kernel<<<NCL / 8, 256>>>(p_x2, W3, b3);
    // 13. softmax + smoothing
    softmax_kernel<<<1, 1024>>>(eps, out);
}

// round 8
// speedup vs baseline: 6.0254x; 1.0109x over previous
#include <cuda_runtime.h>
#include <cuda_fp16.h>
#include <math.h>
#include <stdint.h>

#define H    1024
#define H3   3072
#define NREL 4096
#define NATT 4096
#define NCL  8192
#define V    256

// ===================== scratch (device globals; no allocations) =====================
__device__ __align__(256) __half g2_table[V * H];
__device__ __align__(256) __half g2_Wemb[H * H];
__device__ __align__(256) __half g2_Wih[H3 * H];
__device__ __align__(256) __half g2_Whh[H3 * H];
__device__ __align__(256) __half g2_W1[H * H];
__device__ __align__(256) __half g2_W2[H * H];
__device__ __align__(256) __half g2_emb[V * H];
__device__ __align__(256) __half g2_h1[V * H];
__device__ __align__(256) __half g2_h2rel[NREL * H];
__device__ __align__(256) __half g2_clause[NCL * H];
__device__ __align__(256) __half g2_x1[NCL * H];
__device__ __align__(256) __half g2_gi[V * H3];      // fp16 gi table
__device__ __align__(256) __half g2_gh2[V * H3];     // fp16 gh2 table
__device__ __align__(256) __half g2_gh3[NREL * H3];  // fp16 gh3
__device__ float g_gh1[H3];
__device__ float g_h1[V * H];
__device__ float g_h2rel[NREL * H];
__device__ float g_lpart[NCL * 16];                  // logits partials (deterministic)

// ===================== PTX helpers (valid at compute_103, no 'a' features) ============
__device__ __forceinline__ uint32_t smem_u32(const void* p) {
    uint32_t a;
    asm("{ .reg .u64 t; cvta.to.shared.u64 t, %1; cvt.u32.u64 %0, t; }" : "=r"(a) : "l"(p));
    return a;
}
__device__ __forceinline__ void cp16(uint32_t dst, const void* src) {
    asm volatile("cp.async.cg.shared.global [%0], [%1], 16;" :: "r"(dst), "l"(src));
}
__device__ __forceinline__ void cp_commit() {
    asm volatile("cp.async.commit_group;" ::: "memory");
}
template <int N>
__device__ __forceinline__ void cp_wait() {
    asm volatile("cp.async.wait_group %0;" :: "n"(N) : "memory");
}
__device__ __forceinline__ void ldm_x4(uint32_t& r0, uint32_t& r1, uint32_t& r2, uint32_t& r3,
                                       uint32_t addr) {
    asm volatile("ldmatrix.sync.aligned.m8n8.x4.shared.b16 {%0,%1,%2,%3}, [%4];"
                 : "=r"(r0), "=r"(r1), "=r"(r2), "=r"(r3) : "r"(addr));
}
__device__ __forceinline__ void mma16816(float* c, uint32_t a0, uint32_t a1, uint32_t a2,
                                         uint32_t a3, uint32_t b0, uint32_t b1) {
    asm volatile(
        "mma.sync.aligned.m16n8k16.row.col.f32.f16.f16.f32 "
        "{%0,%1,%2,%3}, {%4,%5,%6,%7}, {%8,%9}, {%0,%1,%2,%3};"
        : "+f"(c[0]), "+f"(c[1]), "+f"(c[2]), "+f"(c[3])
        : "r"(a0), "r"(a1), "r"(a2), "r"(a3), "r"(b0), "r"(b1));
}

#define APITCH   80
#define NIT      32

// ===================== 128x128 fp16 HMMA GEMM ====================
#define ATILE_B  (128 * APITCH)
#define STAGE_B  (2 * ATILE_B)
#define SMEM_DYN_H (4 * STAGE_B)        // 81920

__device__ __forceinline__ void cp_stage(const __half* __restrict__ A,
                                         const __half* __restrict__ B,
                                         int bm, int bn, uint32_t sbase, int tid,
                                         int it)
{
    const int kk = it * 32;
#pragma unroll
    for (int h = 0; h < 2; h++) {
        int c = tid + h * 256;
        int row = c >> 2, kc = c & 3;
        cp16(sbase + row * APITCH + kc * 16,
             A + (size_t)(bm + row) * H + kk + kc * 8);
    }
#pragma unroll
    for (int h = 0; h < 2; h++) {
        int c = tid + h * 256;
        int row = c >> 2, kc = c & 3;
        cp16(sbase + ATILE_B + row * APITCH + kc * 16,
             B + (size_t)(bn + row) * H + kk + kc * 8);
    }
}

template <bool RELU, bool OUTF, bool OUTS, bool LOGITS>
__global__ void __launch_bounds__(256, 2)
gemm_hmma(const __half* __restrict__ A, const __half* __restrict__ B,
          const float* __restrict__ bias, float* __restrict__ Cf,
          __half* __restrict__ Cs, int N,
          const float* __restrict__ w3, float* __restrict__ lpart)
{
    extern __shared__ char sm[];
    const uint32_t sbase = smem_u32(sm);
    const int tid = threadIdx.x, lane = tid & 31, w = tid >> 5;
    const int bm = blockIdx.y * 128, bn = blockIdx.x * 128;
    const int wm = w & 3, wn = w >> 2;

#pragma unroll
    for (int s = 0; s < 3; s++) {
        cp_stage(A, B, bm, bn, sbase + s * STAGE_B, tid, s);
        cp_commit();
    }

    float acc[2][8][4];
#pragma unroll
    for (int mb = 0; mb < 2; mb++)
#pragma unroll
        for (int nb = 0; nb < 8; nb++)
#pragma unroll
            for (int q = 0; q < 4; q++) acc[mb][nb][q] = 0.f;

    const int quad = lane >> 3, li = lane & 7;
    const uint32_t aAddr = sbase +
        (uint32_t)((wm * 32 + (quad & 1) * 8 + li) * APITCH + (quad >> 1) * 16);
    const uint32_t bAddr = sbase + ATILE_B +
        (uint32_t)((wn * 64 + (quad >> 1) * 8 + li) * APITCH + (quad & 1) * 16);

    for (int i = 0; i < NIT; i++) {
        cp_wait<2>();
        __syncthreads();
        if (i + 3 < NIT)
            cp_stage(A, B, bm, bn, sbase + ((i + 3) & 3) * STAGE_B, tid, i + 3);
        cp_commit();

        const uint32_t sa = aAddr + (i & 3) * STAGE_B;
        const uint32_t sb = bAddr + (i & 3) * STAGE_B;
#pragma unroll
        for (int kh = 0; kh < 2; kh++) {
            uint32_t a[2][4];
            ldm_x4(a[0][0], a[0][1], a[0][2], a[0][3], sa + kh * 32);
            ldm_x4(a[1][0], a[1][1], a[1][2], a[1][3], sa + kh * 32 + 16 * APITCH);
            uint32_t b[8][2];
#pragma unroll
            for (int n2 = 0; n2 < 4; n2++)
                ldm_x4(b[2 * n2][0], b[2 * n2][1], b[2 * n2 + 1][0], b[2 * n2 + 1][1],
                       sb + kh * 32 + n2 * 16 * APITCH);
#pragma unroll
            for (int mb = 0; mb < 2; mb++)
#pragma unroll
                for (int nb = 0; nb < 8; nb++)
                    mma16816(acc[mb][nb], a[mb][0], a[mb][1], a[mb][2], a[mb][3],
                             b[nb][0], b[nb][1]);
        }
    }

    const int g = lane >> 2, t = lane & 3;
    float lsum[2][2] = {{0.f, 0.f}, {0.f, 0.f}};
#pragma unroll
    for (int mb = 0; mb < 2; mb++) {
        const int r0 = bm + wm * 32 + mb * 16 + g;
#pragma unroll
        for (int nb = 0; nb < 8; nb++) {
            const int col = bn + wn * 64 + nb * 8 + t * 2;
            const float b0 = bias[col], b1 = bias[col + 1];
            float v00 = acc[mb][nb][0] + b0, v01 = acc[mb][nb][1] + b1;
            float v10 = acc[mb][nb][2] + b0, v11 = acc[mb][nb][3] + b1;
            if (RELU) {
                v00 = fmaxf(v00, 0.f); v01 = fmaxf(v01, 0.f);
                v10 = fmaxf(v10, 0.f); v11 = fmaxf(v11, 0.f);
            }
            if (OUTF) {
                *(float2*)(Cf + (size_t)r0 * N + col)       = make_float2(v00, v01);
                *(float2*)(Cf + (size_t)(r0 + 8) * N + col) = make_float2(v10, v11);
            }
            if (OUTS) {
                *(__half2*)(Cs + (size_t)r0 * N + col) =
                    __halves2half2(__float2half(v00), __float2half(v01));
                *(__half2*)(Cs + (size_t)(r0 + 8) * N + col) =
                    __halves2half2(__float2half(v10), __float2half(v11));
            }
            if (LOGITS) {
                const float w0 = w3[col], w1 = w3[col + 1];
                lsum[mb][0] = fmaf(v00, w0, fmaf(v01, w1, lsum[mb][0]));
                lsum[mb][1] = fmaf(v10, w0, fmaf(v11, w1, lsum[mb][1]));
            }
        }
    }
    if (LOGITS) {
#pragma unroll
        for (int mb = 0; mb < 2; mb++)
#pragma unroll
            for (int rr = 0; rr < 2; rr++) {
                float s = lsum[mb][rr];
                s += __shfl_xor_sync(0xffffffffu, s, 1);
                s += __shfl_xor_sync(0xffffffffu, s, 2);
                if (t == 0) {
                    int row = bm + wm * 32 + mb * 16 + g + rr * 8;
                    lpart[(size_t)row * 16 + blockIdx.x * 2 + wn] = s;
                }
            }
    }
}

// ===================== 64x64 fp16 HMMA GEMM (small-M GEMMs 1/2/5) ==============
#define ATILE64_B (64 * APITCH)
#define STAGE64_B (2 * ATILE64_B)
#define SMEM_DYN64 (4 * STAGE64_B)       // 40960

__device__ __forceinline__ void cp_stage64(const __half* __restrict__ A,
                                           const __half* __restrict__ B,
                                           int bm, int bn, uint32_t sbase, int tid,
                                           int it)
{
    const int kk = it * 32;
    int row = tid >> 2, kc = tid & 3;
    cp16(sbase + row * APITCH + kc * 16,
         A + (size_t)(bm + row) * H + kk + kc * 8);
    cp16(sbase + ATILE64_B + row * APITCH + kc * 16,
         B + (size_t)(bn + row) * H + kk + kc * 8);
}

__global__ void __launch_bounds__(256, 2)
gemm_hmma64(const __half* __restrict__ A, const __half* __restrict__ B,
            const float* __restrict__ bias, __half* __restrict__ Cs, int N)
{
    extern __shared__ char sm[];
    const uint32_t sbase = smem_u32(sm);
    const int tid = threadIdx.x, lane = tid & 31, w = tid >> 5;
    const int bm = blockIdx.y * 64, bn = blockIdx.x * 64;
    const int wm = w & 1, wn = w >> 1;

#pragma unroll
    for (int s = 0; s < 3; s++) {
        cp_stage64(A, B, bm, bn, sbase + s * STAGE64_B, tid, s);
        cp_commit();
    }

    float acc[2][2][4];
#pragma unroll
    for (int mb = 0; mb < 2; mb++)
#pragma unroll
        for (int nb = 0; nb < 2; nb++)
#pragma unroll
            for (int q = 0; q < 4; q++) acc[mb][nb][q] = 0.f;

    const int quad = lane >> 3, li = lane & 7;
    const uint32_t aAddr = sbase +
        (uint32_t)((wm * 32 + (quad & 1) * 8 + li) * APITCH + (quad >> 1) * 16);
    const uint32_t bAddr = sbase + ATILE64_B +
        (uint32_t)((wn * 16 + (quad >> 1) * 8 + li) * APITCH + (quad & 1) * 16);

    for (int i = 0; i < NIT; i++) {
        cp_wait<2>();
        __syncthreads();
        if (i + 3 < NIT)
            cp_stage64(A, B, bm, bn, sbase + ((i + 3) & 3) * STAGE64_B, tid, i + 3);
        cp_commit();

        const uint32_t sa = aAddr + (i & 3) * STAGE64_B;
        const uint32_t sb = bAddr + (i & 3) * STAGE64_B;
#pragma unroll
        for (int kh = 0; kh < 2; kh++) {
            uint32_t a[2][4];
            ldm_x4(a[0][0], a[0][1], a[0][2], a[0][3], sa + kh * 32);
            ldm_x4(a[1][0], a[1][1], a[1][2], a[1][3], sa + kh * 32 + 16 * APITCH);
            uint32_t b[2][2];
            ldm_x4(b[0][0], b[0][1], b[1][0], b[1][1], sb + kh * 32);
#pragma unroll
            for (int mb = 0; mb < 2; mb++)
#pragma unroll
                for (int nb = 0; nb < 2; nb++)
                    mma16816(acc[mb][nb], a[mb][0], a[mb][1], a[mb][2], a[mb][3],
                             b[nb][0], b[nb][1]);
        }
    }

    const int g = lane >> 2, t = lane & 3;
#pragma unroll
    for (int mb = 0; mb < 2; mb++) {
        const int r0 = bm + wm * 32 + mb * 16 + g;
#pragma unroll
        for (int nb = 0; nb < 2; nb++) {
            const int col = bn + wn * 16 + nb * 8 + t * 2;
            const float b0 = bias[col], b1 = bias[col + 1];
            *(__half2*)(Cs + (size_t)r0 * N + col) = __halves2half2(
                __float2half(acc[mb][nb][0] + b0), __float2half(acc[mb][nb][1] + b1));
            *(__half2*)(Cs + (size_t)(r0 + 8) * N + col) = __halves2half2(
                __float2half(acc[mb][nb][2] + b0), __float2half(acc[mb][nb][3] + b1));
        }
    }
}

// ===================== fused fp32 -> fp16 convert for ALL 6 operands =====================
#define CVT_ROWS (256 + 1024 + 3072 + 3072 + 1024 + 1024)
__global__ void __launch_bounds__(256)
cvt_all(const float* __restrict__ s0, const float* __restrict__ s1,
        const float* __restrict__ s2, const float* __restrict__ s3,
        const float* __restrict__ s4, const float* __restrict__ s5,
        __half* __restrict__ d0, __half* __restrict__ d1,
        __half* __restrict__ d2, __half* __restrict__ d3,
        __half* __restrict__ d4, __half* __restrict__ d5)
{
    int row = blockIdx.x;
    const float* src; __half* dst; int r = row;
    if      (r < 256)        { src = s0; dst = d0; }
    else if ((r -= 256)  < 1024) { src = s1; dst = d1; }
    else if ((r -= 1024) < 3072) { src = s2; dst = d2; }
    else if ((r -= 3072) < 3072) { src = s3; dst = d3; }
    else if ((r -= 3072) < 1024) { src = s4; dst = d4; }
    else     { r -= 1024;      src = s5; dst = d5; }

    int c4 = threadIdx.x * 4;
    float4 x = *(const float4*)(src + (size_t)r * H + c4);
    __half* o = dst + (size_t)r * H + c4;
    *(__half2*)(o)     = __halves2half2(__float2half(x.x), __float2half(x.y));
    *(__half2*)(o + 2) = __halves2half2(__float2half(x.z), __float2half(x.w));
}

// ===================== GEMV (gh1) =====================
__global__ void gemv_rows(const float* __restrict__ x, const float* __restrict__ W,
                          const float* __restrict__ b, float* __restrict__ out, int Nout)
{
    int n = blockIdx.x * 8 + (threadIdx.x >> 5);
    if (n >= Nout) return;
    int lane = threadIdx.x & 31;
    const float* w = W + (size_t)n * H;
    float s = 0.f;
#pragma unroll
    for (int k = lane * 4; k < H; k += 128) {
        float4 wv = *(const float4*)(w + k);
        float4 xv = *(const float4*)(x + k);
        s = fmaf(wv.x, xv.x, s); s = fmaf(wv.y, xv.y, s);
        s = fmaf(wv.z, xv.z, s); s = fmaf(wv.w, xv.w, s);
    }
#pragma unroll
    for (int o = 16; o; o >>= 1) s += __shfl_xor_sync(0xffffffffu, s, o);
    if (lane == 0) out[n] = s + b[n];
}

// ===================== GRU combine =====================
__device__ __forceinline__ float4 ld4h(const __half* p) {
    float2 f0 = __half22float2(*(const __half2*)p);
    float2 f1 = __half22float2(*(const __half2*)(p + 2));
    return make_float4(f0.x, f0.y, f1.x, f1.y);
}
__device__ __forceinline__ float gru1(float ir, float iz, float inn,
                                      float hr, float hz, float hn, float h)
{
    float r = 1.f / (1.f + __expf(-(ir + hr)));
    float z = 1.f / (1.f + __expf(-(iz + hz)));
    float n = tanhf(fmaf(r, hn, inn));
    return fmaf(z, h - n, n);
}
__device__ __forceinline__ float4 gru4_comb(float4 ir, float4 iz, float4 inn,
                                            float4 hr, float4 hz, float4 hn, float4 hv)
{
    float4 o;
    o.x = gru1(ir.x, iz.x, inn.x, hr.x, hz.x, hn.x, hv.x);
    o.y = gru1(ir.y, iz.y, inn.y, hr.y, hz.y, hn.y, hv.y);
    o.z = gru1(ir.z, iz.z, inn.z, hr.z, hz.z, hn.z, hv.z);
    o.w = gru1(ir.w, iz.w, inn.w, hr.w, hz.w, hn.w, hv.w);
    return o;
}
// gi fp16, gh fp32
__device__ __forceinline__ float4 gru4_hf(const __half* gi, const float* gh,
                                          const float* h, int j)
{
    return gru4_comb(ld4h(gi + j), ld4h(gi + H + j), ld4h(gi + 2 * H + j),
                     *(const float4*)(gh + j), *(const float4*)(gh + H + j),
                     *(const float4*)(gh + 2 * H + j), *(const float4*)(h + j));
}
// gi fp16, gh fp16
__device__ __forceinline__ float4 gru4_hh(const __half* gi, const __half* gh,
                                          const float* h, int j)
{
    return gru4_comb(ld4h(gi + j), ld4h(gi + H + j), ld4h(gi + 2 * H + j),
                     ld4h(gh + j), ld4h(gh + H + j), ld4h(gh + 2 * H + j),
                     *(const float4*)(h + j));
}
__device__ __forceinline__ void cvt_store(__half* o, float4 v)
{
    *(__half2*)(o)     = __halves2half2(__float2half(v.x), __float2half(v.y));
    *(__half2*)(o + 2) = __halves2half2(__float2half(v.z), __float2half(v.w));
}

__global__ void gru_h1_kernel(const float* __restrict__ state)
{
    int v = blockIdx.x;
    int j = threadIdx.x * 4;
    float4 o = gru4_hf(g2_gi + (size_t)v * H3, g_gh1, state, j);
    *(float4*)(g_h1 + (size_t)v * H + j) = o;
    cvt_store(g2_h1 + (size_t)v * H + j, o);
}

__global__ void gru_step2_all(const int* __restrict__ rel_tokens,
                              const int* __restrict__ attr_tokens)
{
    int blk = blockIdx.x;
    int j = threadIdx.x * 4;
    if (blk < NREL) {
        int t0 = rel_tokens[blk * 3 + 0];
        int t1 = rel_tokens[blk * 3 + 1];
        float4 o = gru4_hh(g2_gi + (size_t)t1 * H3, g2_gh2 + (size_t)t0 * H3,
                           g_h1 + (size_t)t0 * H, j);
        *(float4*)(g_h2rel + (size_t)blk * H + j) = o;
        cvt_store(g2_h2rel + (size_t)blk * H + j, o);
    } else {
        int n = blk - NREL;
        int t0 = attr_tokens[n * 2 + 0];
        int t1 = attr_tokens[n * 2 + 1];
        float4 o = gru4_hh(g2_gi + (size_t)t1 * H3, g2_gh2 + (size_t)t0 * H3,
                           g_h1 + (size_t)t0 * H, j);
        cvt_store(g2_clause + (size_t)(NREL + n) * H + j, o);
    }
}

__global__ void gru_step3_kernel(const int* __restrict__ rel_tokens)
{
    int n  = blockIdx.x;
    int t2 = rel_tokens[n * 3 + 2];
    int j  = threadIdx.x * 4;
    float4 o = gru4_hh(g2_gi + (size_t)t2 * H3, g2_gh3 + (size_t)n * H3,
                       g_h2rel + (size_t)n * H, j);
    cvt_store(g2_clause + (size_t)n * H + j, o);
}

// ===================== logits reduce + softmax + eps smoothing =====================
__global__ void softmax_kernel(const float* __restrict__ eps, float* __restrict__ out)
{
    const int N = NCL;
    __shared__ float sl[NCL];        // 32 KB
    __shared__ float shm[32], shs[32];
    int tid = threadIdx.x;

    // build logits from 16 deterministic partials per row
    for (int i = tid; i < N; i += 1024) {
        const float4* p = (const float4*)(g_lpart + (size_t)i * 16);
        float4 a = p[0], b = p[1], c = p[2], d = p[3];
        sl[i] = ((a.x + a.y) + (a.z + a.w)) + ((b.x + b.y) + (b.z + b.w))
              + ((c.x + c.y) + (c.z + c.w)) + ((d.x + d.y) + (d.z + d.w));
    }
    __syncthreads();

    float m = -1e30f;
    for (int i = tid; i < N; i += 1024) m = fmaxf(m, sl[i]);
#pragma unroll
    for (int o = 16; o; o >>= 1) m = fmaxf(m, __shfl_xor_sync(0xffffffffu, m, o));
    if ((tid & 31) == 0) shm[tid >> 5] = m;
    __syncthreads();
    if (tid < 32) {
        float v = shm[tid];
#pragma unroll
        for (int o = 16; o; o >>= 1) v = fmaxf(v, __shfl_xor_sync(0xffffffffu, v, o));
        shm[tid] = v;
    }
    __syncthreads();
    float M = shm[0];

    float s = 0.f;
    for (int i = tid; i < N; i += 1024) s += __expf(sl[i] - M);
#pragma unroll
    for (int o = 16; o; o >>= 1) s += __shfl_xor_sync(0xffffffffu, s, o);
    if ((tid & 31) == 0) shs[tid >> 5] = s;
    __syncthreads();
    if (tid < 32) {
        float v = shs[tid];
#pragma unroll
        for (int o = 16; o; o >>= 1) v += __shfl_xor_sync(0xffffffffu, v, o);
        shs[tid] = v;
    }
    __syncthreads();
    float S = shs[0];
    float e = eps[0];
    float inv = (1.f - e) / S;
    float add = e / (float)N;
    for (int i = tid; i < N; i += 1024)
        out[i] = __expf(sl[i] - M) * inv + add;
}

// ===================== launch =====================
extern "C" void kernel_launch(void* const* d_in, const int* in_sizes, int n_in,
                              void* d_out, int out_size)
{
    const float* state       = (const float*)d_in[0];
    const int*   rel_tokens  = (const int*)d_in[1];
    const int*   attr_tokens = (const int*)d_in[2];
    const float* table       = (const float*)d_in[3];
    const float* W_emb       = (const float*)d_in[4];
    const float* b_emb       = (const float*)d_in[5];
    const float* W_ih        = (const float*)d_in[6];
    const float* W_hh        = (const float*)d_in[7];
    const float* b_ih        = (const float*)d_in[8];
    const float* b_hh        = (const float*)d_in[9];
    const float* W1          = (const float*)d_in[10];
    const float* b1          = (const float*)d_in[11];
    const float* W2          = (const float*)d_in[12];
    const float* b2          = (const float*)d_in[13];
    const float* W3          = (const float*)d_in[14];
    const float* eps         = (const float*)d_in[16];
    float* out = (float*)d_out;

    __half *p2_table, *p2_Wemb, *p2_Wih, *p2_Whh, *p2_W1, *p2_W2;
    __half *p2_emb, *p2_h1, *p2_h2rel, *p2_clause, *p2_x1, *p2_gi, *p2_gh2, *p2_gh3;
    float *p_gh1, *p_lpart;
    cudaGetSymbolAddress((void**)&p2_table,  g2_table);
    cudaGetSymbolAddress((void**)&p2_Wemb,   g2_Wemb);
    cudaGetSymbolAddress((void**)&p2_Wih,    g2_Wih);
    cudaGetSymbolAddress((void**)&p2_Whh,    g2_Whh);
    cudaGetSymbolAddress((void**)&p2_W1,     g2_W1);
    cudaGetSymbolAddress((void**)&p2_W2,     g2_W2);
    cudaGetSymbolAddress((void**)&p2_emb,    g2_emb);
    cudaGetSymbolAddress((void**)&p2_h1,     g2_h1);
    cudaGetSymbolAddress((void**)&p2_h2rel,  g2_h2rel);
    cudaGetSymbolAddress((void**)&p2_clause, g2_clause);
    cudaGetSymbolAddress((void**)&p2_x1,     g2_x1);
    cudaGetSymbolAddress((void**)&p2_gi,     g2_gi);
    cudaGetSymbolAddress((void**)&p2_gh2,    g2_gh2);
    cudaGetSymbolAddress((void**)&p2_gh3,    g2_gh3);
    cudaGetSymbolAddress((void**)&p_gh1,     g_gh1);
    cudaGetSymbolAddress((void**)&p_lpart,   g_lpart);

    cudaFuncSetAttribute(gemm_hmma<false, false, true, false>,
                         cudaFuncAttributeMaxDynamicSharedMemorySize, SMEM_DYN_H);
    cudaFuncSetAttribute(gemm_hmma<true, false, true, false>,
                         cudaFuncAttributeMaxDynamicSharedMemorySize, SMEM_DYN_H);
    cudaFuncSetAttribute(gemm_hmma<true, false, false, true>,
                         cudaFuncAttributeMaxDynamicSharedMemorySize, SMEM_DYN_H);

    // 0. convert all fp32 operands to fp16 in one launch
    cvt_all<<<CVT_ROWS, 256>>>(table, W_emb, W_ih, W_hh, W1, W2,
                               p2_table, p2_Wemb, p2_Wih, p2_Whh, p2_W1, p2_W2);

    // 1. emb_proj[V,H] (fp16 out)
    gemm_hmma64<<<dim3(H / 64, V / 64), 256, SMEM_DYN64>>>(
        p2_table, p2_Wemb, b_emb, p2_emb, H);
    // 2. gi_table[V,3H] (fp16 out)
    gemm_hmma64<<<dim3(H3 / 64, V / 64), 256, SMEM_DYN64>>>(
        p2_emb, p2_Wih, b_ih, p2_gi, H3);
    // 3. gh1 = state @ W_hh^T + b_hh (exact fp32 GEMV)
    gemv_rows<<<H3 / 8, 256>>>(state, W_hh, b_hh, p_gh1, H3);
    // 4. h1_table (fp32 + fp16)
    gru_h1_kernel<<<V, 256>>>(state);
    // 5. gh2_table[V,3H] (fp16 out)
    gemm_hmma64<<<dim3(H3 / 64, V / 64), 256, SMEM_DYN64>>>(
        p2_h1, p2_Whh, b_hh, p2_gh2, H3);
    // 6+7. merged step-2 (rel + attr)
    gru_step2_all<<<NREL + NATT, 256>>>(rel_tokens, attr_tokens);
    // 8. gh3[Nr,3H] (fp16 out)
    gemm_hmma<false, false, true, false><<<dim3(H3 / 128, NREL / 128), 256, SMEM_DYN_H>>>(
        p2_h2rel, p2_Whh, b_hh, nullptr, p2_gh3, H3, nullptr, nullptr);
    // 9. rel step 3 -> clause fp16 rows [0, 4096)
    gru_step3_kernel<<<NREL, 256>>>(rel_tokens);
    // 10. x1 = relu(clause @ W1^T + b1) (fp16 out)
    gemm_hmma<true, false, true, false><<<dim3(H / 128, NCL / 128), 256, SMEM_DYN_H>>>(
        p2_clause, p2_W1, b1, nullptr, p2_x1, H, nullptr, nullptr);
    // 11. x2 GEMM with fused logits partials (x2 never materialized; b3 is a
    //     uniform shift, invariant under softmax, so it is dropped)
    gemm_hmma<true, false, false, true><<<dim3(H / 128, NCL / 128), 256, SMEM_DYN_H>>>(
        p2_x1, p2_W2, b2, nullptr, nullptr, H, W3, p_lpart);
    // 12. logits reduce + softmax + smoothing
    softmax_kernel<<<1, 1024>>>(eps, out);
}

// round 9
// speedup vs baseline: 6.3920x; 1.0608x over previous
#include <cuda_runtime.h>
#include <cuda_fp16.h>
#include <math.h>
#include <stdint.h>

#define H    1024
#define H3   3072
#define NREL 4096
#define NATT 4096
#define NCL  8192
#define V    256

// ===================== scratch (device globals; no allocations) =====================
__device__ __align__(256) __half g2_table[V * H];
__device__ __align__(256) __half g2_Wemb[H * H];
__device__ __align__(256) __half g2_Wih[H3 * H];
__device__ __align__(256) __half g2_Whh[H3 * H];
__device__ __align__(256) __half g2_W1[H * H];
__device__ __align__(256) __half g2_W2[H * H];
__device__ __align__(256) __half g2_emb[V * H];
__device__ __align__(256) __half g2_h1[V * H];
__device__ __align__(256) __half g2_h2rel[NREL * H];
__device__ __align__(256) __half g2_clause[NCL * H];
__device__ __align__(256) __half g2_x1[NCL * H];
__device__ __align__(256) __half g2_gi[V * H3];
__device__ __align__(256) __half g2_gh2[V * H3];
__device__ __align__(256) __half g2_gh3[NREL * H3];
__device__ float g_gh1[H3];
__device__ float g_h1[V * H];
__device__ float g_h2rel[NREL * H];
__device__ float g_lpart[NCL * 16];

// ===================== PTX helpers =====================
__device__ __forceinline__ uint32_t smem_u32(const void* p) {
    uint32_t a;
    asm("{ .reg .u64 t; cvta.to.shared.u64 t, %1; cvt.u32.u64 %0, t; }" : "=r"(a) : "l"(p));
    return a;
}
__device__ __forceinline__ void cp16(uint32_t dst, const void* src) {
    asm volatile("cp.async.cg.shared.global [%0], [%1], 16;" :: "r"(dst), "l"(src));
}
__device__ __forceinline__ void cp_commit() {
    asm volatile("cp.async.commit_group;" ::: "memory");
}
template <int N>
__device__ __forceinline__ void cp_wait() {
    asm volatile("cp.async.wait_group %0;" :: "n"(N) : "memory");
}
__device__ __forceinline__ void ldm_x4(uint32_t& r0, uint32_t& r1, uint32_t& r2, uint32_t& r3,
                                       uint32_t addr) {
    asm volatile("ldmatrix.sync.aligned.m8n8.x4.shared.b16 {%0,%1,%2,%3}, [%4];"
                 : "=r"(r0), "=r"(r1), "=r"(r2), "=r"(r3) : "r"(addr));
}
__device__ __forceinline__ void mma16816(float* c, uint32_t a0, uint32_t a1, uint32_t a2,
                                         uint32_t a3, uint32_t b0, uint32_t b1) {
    asm volatile(
        "mma.sync.aligned.m16n8k16.row.col.f32.f16.f16.f32 "
        "{%0,%1,%2,%3}, {%4,%5,%6,%7}, {%8,%9}, {%0,%1,%2,%3};"
        : "+f"(c[0]), "+f"(c[1]), "+f"(c[2]), "+f"(c[3])
        : "r"(a0), "r"(a1), "r"(a2), "r"(a3), "r"(b0), "r"(b1));
}

#define APITCH   80
#define NIT      32

// ===================== 128x128 fp16 HMMA GEMM ====================
#define ATILE_B  (128 * APITCH)
#define STAGE_B  (2 * ATILE_B)
#define SMEM_DYN_H (4 * STAGE_B)        // 81920

__device__ __forceinline__ void cp_stage(const __half* __restrict__ A,
                                         const __half* __restrict__ B,
                                         int bm, int bn, uint32_t sbase, int tid,
                                         int it)
{
    const int kk = it * 32;
#pragma unroll
    for (int h = 0; h < 2; h++) {
        int c = tid + h * 256;
        int row = c >> 2, kc = c & 3;
        cp16(sbase + row * APITCH + kc * 16,
             A + (size_t)(bm + row) * H + kk + kc * 8);
    }
#pragma unroll
    for (int h = 0; h < 2; h++) {
        int c = tid + h * 256;
        int row = c >> 2, kc = c & 3;
        cp16(sbase + ATILE_B + row * APITCH + kc * 16,
             B + (size_t)(bn + row) * H + kk + kc * 8);
    }
}

// core 128x128 mainloop + epilogue, shared by all 128-tile kernels
template <bool OUTS, bool LOGITS>
__device__ __forceinline__ void gemm128_body(
    const __half* __restrict__ A, const __half* __restrict__ B,
    const float* __restrict__ bias, __half* __restrict__ Cs, int N,
    int bm, int bn, float relu_floor,
    const float* __restrict__ w3, float* __restrict__ lpart, int bxLog,
    uint32_t sbase, int tid)
{
    const int lane = tid & 31, w = tid >> 5;
    const int wm = w & 3, wn = w >> 2;

#pragma unroll
    for (int s = 0; s < 3; s++) {
        cp_stage(A, B, bm, bn, sbase + s * STAGE_B, tid, s);
        cp_commit();
    }

    float acc[2][8][4];
#pragma unroll
    for (int mb = 0; mb < 2; mb++)
#pragma unroll
        for (int nb = 0; nb < 8; nb++)
#pragma unroll
            for (int q = 0; q < 4; q++) acc[mb][nb][q] = 0.f;

    const int quad = lane >> 3, li = lane & 7;
    const uint32_t aAddr = sbase +
        (uint32_t)((wm * 32 + (quad & 1) * 8 + li) * APITCH + (quad >> 1) * 16);
    const uint32_t bAddr = sbase + ATILE_B +
        (uint32_t)((wn * 64 + (quad >> 1) * 8 + li) * APITCH + (quad & 1) * 16);

    for (int i = 0; i < NIT; i++) {
        cp_wait<2>();
        __syncthreads();
        if (i + 3 < NIT)
            cp_stage(A, B, bm, bn, sbase + ((i + 3) & 3) * STAGE_B, tid, i + 3);
        cp_commit();

        const uint32_t sa = aAddr + (i & 3) * STAGE_B;
        const uint32_t sb = bAddr + (i & 3) * STAGE_B;
#pragma unroll
        for (int kh = 0; kh < 2; kh++) {
            uint32_t a[2][4];
            ldm_x4(a[0][0], a[0][1], a[0][2], a[0][3], sa + kh * 32);
            ldm_x4(a[1][0], a[1][1], a[1][2], a[1][3], sa + kh * 32 + 16 * APITCH);
            uint32_t b[8][2];
#pragma unroll
            for (int n2 = 0; n2 < 4; n2++)
                ldm_x4(b[2 * n2][0], b[2 * n2][1], b[2 * n2 + 1][0], b[2 * n2 + 1][1],
                       sb + kh * 32 + n2 * 16 * APITCH);
#pragma unroll
            for (int mb = 0; mb < 2; mb++)
#pragma unroll
                for (int nb = 0; nb < 8; nb++)
                    mma16816(acc[mb][nb], a[mb][0], a[mb][1], a[mb][2], a[mb][3],
                             b[nb][0], b[nb][1]);
        }
    }

    const int g = lane >> 2, t = lane & 3;
    float lsum[2][2] = {{0.f, 0.f}, {0.f, 0.f}};
#pragma unroll
    for (int mb = 0; mb < 2; mb++) {
        const int r0 = bm + wm * 32 + mb * 16 + g;
#pragma unroll
        for (int nb = 0; nb < 8; nb++) {
            const int col = bn + wn * 64 + nb * 8 + t * 2;
            const float b0 = bias[col], b1 = bias[col + 1];
            float v00 = fmaxf(acc[mb][nb][0] + b0, relu_floor);
            float v01 = fmaxf(acc[mb][nb][1] + b1, relu_floor);
            float v10 = fmaxf(acc[mb][nb][2] + b0, relu_floor);
            float v11 = fmaxf(acc[mb][nb][3] + b1, relu_floor);
            if (OUTS) {
                *(__half2*)(Cs + (size_t)r0 * N + col) =
                    __halves2half2(__float2half(v00), __float2half(v01));
                *(__half2*)(Cs + (size_t)(r0 + 8) * N + col) =
                    __halves2half2(__float2half(v10), __float2half(v11));
            }
            if (LOGITS) {
                const float w0 = w3[col], w1 = w3[col + 1];
                lsum[0][0] = fmaf(v00, w0, fmaf(v01, w1, lsum[0][0]));  // dummy to keep shape
                // (real accumulation below uses per-mb arrays)
            }
            if (LOGITS) {
                // overwrite dummy: accumulate properly
            }
            if (LOGITS) {
                const float w0 = w3[col], w1 = w3[col + 1];
                // correct accumulation (lsum[0][0] double-counted above; fix by
                // structuring: we instead recompute cleanly)
                (void)w0; (void)w1;
            }
        }
    }
    // NOTE: LOGITS epilogue handled by specialized path below (see gemm_logits).
    (void)lsum; (void)lpart; (void)bxLog; (void)w3;
}

// plain 128x128 GEMM with runtime operand set (for the dual launch)
__global__ void __launch_bounds__(256, 2)
gemm_dual(const float* __restrict__ b_hh, const float* __restrict__ b1)
{
    extern __shared__ char sm[];
    const uint32_t sbase = smem_u32(sm);
    const int tid = threadIdx.x;
    const int blk = blockIdx.x;

    const __half* A; const __half* B; const float* bias; __half* Cs;
    int N, bm, bn; float relu_floor;
    if (blk < 768) {        // GEMM8: gh3 = h2rel @ Whh^T + b_hh (no relu)
        int bx = blk % 24, by = blk / 24;
        A = g2_h2rel; B = g2_Whh; bias = b_hh; Cs = g2_gh3;
        N = H3; bm = by * 128; bn = bx * 128;
        relu_floor = __int_as_float(0xff800000);   // -inf
    } else {                // GEMM10-attr: x1[4096:] = relu(clause[4096:] @ W1^T + b1)
        int t = blk - 768;
        int bx = t % 8, by = t / 8;
        A = g2_clause + (size_t)NREL * H; B = g2_W1; bias = b1;
        Cs = g2_x1 + (size_t)NREL * H;
        N = H; bm = by * 128; bn = bx * 128;
        relu_floor = 0.f;
    }

    const int lane = tid & 31, w = tid >> 5;
    const int wm = w & 3, wn = w >> 2;

#pragma unroll
    for (int s = 0; s < 3; s++) {
        cp_stage(A, B, bm, bn, sbase + s * STAGE_B, tid, s);
        cp_commit();
    }

    float acc[2][8][4];
#pragma unroll
    for (int mb = 0; mb < 2; mb++)
#pragma unroll
        for (int nb = 0; nb < 8; nb++)
#pragma unroll
            for (int q = 0; q < 4; q++) acc[mb][nb][q] = 0.f;

    const int quad = lane >> 3, li = lane & 7;
    const uint32_t aAddr = sbase +
        (uint32_t)((wm * 32 + (quad & 1) * 8 + li) * APITCH + (quad >> 1) * 16);
    const uint32_t bAddr = sbase + ATILE_B +
        (uint32_t)((wn * 64 + (quad >> 1) * 8 + li) * APITCH + (quad & 1) * 16);

    for (int i = 0; i < NIT; i++) {
        cp_wait<2>();
        __syncthreads();
        if (i + 3 < NIT)
            cp_stage(A, B, bm, bn, sbase + ((i + 3) & 3) * STAGE_B, tid, i + 3);
        cp_commit();

        const uint32_t sa = aAddr + (i & 3) * STAGE_B;
        const uint32_t sb = bAddr + (i & 3) * STAGE_B;
#pragma unroll
        for (int kh = 0; kh < 2; kh++) {
            uint32_t a[2][4];
            ldm_x4(a[0][0], a[0][1], a[0][2], a[0][3], sa + kh * 32);
            ldm_x4(a[1][0], a[1][1], a[1][2], a[1][3], sa + kh * 32 + 16 * APITCH);
            uint32_t b[8][2];
#pragma unroll
            for (int n2 = 0; n2 < 4; n2++)
                ldm_x4(b[2 * n2][0], b[2 * n2][1], b[2 * n2 + 1][0], b[2 * n2 + 1][1],
                       sb + kh * 32 + n2 * 16 * APITCH);
#pragma unroll
            for (int mb = 0; mb < 2; mb++)
#pragma unroll
                for (int nb = 0; nb < 8; nb++)
                    mma16816(acc[mb][nb], a[mb][0], a[mb][1], a[mb][2], a[mb][3],
                             b[nb][0], b[nb][1]);
        }
    }

    const int g = lane >> 2, t = lane & 3;
#pragma unroll
    for (int mb = 0; mb < 2; mb++) {
        const int r0 = bm + wm * 32 + mb * 16 + g;
#pragma unroll
        for (int nb = 0; nb < 8; nb++) {
            const int col = bn + wn * 64 + nb * 8 + t * 2;
            const float b0 = bias[col], b1v = bias[col + 1];
            float v00 = fmaxf(acc[mb][nb][0] + b0,  relu_floor);
            float v01 = fmaxf(acc[mb][nb][1] + b1v, relu_floor);
            float v10 = fmaxf(acc[mb][nb][2] + b0,  relu_floor);
            float v11 = fmaxf(acc[mb][nb][3] + b1v, relu_floor);
            *(__half2*)(Cs + (size_t)r0 * N + col) =
                __halves2half2(__float2half(v00), __float2half(v01));
            *(__half2*)(Cs + (size_t)(r0 + 8) * N + col) =
                __halves2half2(__float2half(v10), __float2half(v11));
        }
    }
}

// templated 128x128 GEMM (GEMM10-rel and GEMM11-with-logits)
template <bool RELU, bool OUTS, bool LOGITS>
__global__ void __launch_bounds__(256, 2)
gemm_hmma(const __half* __restrict__ A, const __half* __restrict__ B,
          const float* __restrict__ bias, __half* __restrict__ Cs, int N,
          const float* __restrict__ w3, float* __restrict__ lpart)
{
    extern __shared__ char sm[];
    const uint32_t sbase = smem_u32(sm);
    const int tid = threadIdx.x, lane = tid & 31, w = tid >> 5;
    const int bm = blockIdx.y * 128, bn = blockIdx.x * 128;
    const int wm = w & 3, wn = w >> 2;

#pragma unroll
    for (int s = 0; s < 3; s++) {
        cp_stage(A, B, bm, bn, sbase + s * STAGE_B, tid, s);
        cp_commit();
    }

    float acc[2][8][4];
#pragma unroll
    for (int mb = 0; mb < 2; mb++)
#pragma unroll
        for (int nb = 0; nb < 8; nb++)
#pragma unroll
            for (int q = 0; q < 4; q++) acc[mb][nb][q] = 0.f;

    const int quad = lane >> 3, li = lane & 7;
    const uint32_t aAddr = sbase +
        (uint32_t)((wm * 32 + (quad & 1) * 8 + li) * APITCH + (quad >> 1) * 16);
    const uint32_t bAddr = sbase + ATILE_B +
        (uint32_t)((wn * 64 + (quad >> 1) * 8 + li) * APITCH + (quad & 1) * 16);

    for (int i = 0; i < NIT; i++) {
        cp_wait<2>();
        __syncthreads();
        if (i + 3 < NIT)
            cp_stage(A, B, bm, bn, sbase + ((i + 3) & 3) * STAGE_B, tid, i + 3);
        cp_commit();

        const uint32_t sa = aAddr + (i & 3) * STAGE_B;
        const uint32_t sb = bAddr + (i & 3) * STAGE_B;
#pragma unroll
        for (int kh = 0; kh < 2; kh++) {
            uint32_t a[2][4];
            ldm_x4(a[0][0], a[0][1], a[0][2], a[0][3], sa + kh * 32);
            ldm_x4(a[1][0], a[1][1], a[1][2], a[1][3], sa + kh * 32 + 16 * APITCH);
            uint32_t b[8][2];
#pragma unroll
            for (int n2 = 0; n2 < 4; n2++)
                ldm_x4(b[2 * n2][0], b[2 * n2][1], b[2 * n2 + 1][0], b[2 * n2 + 1][1],
                       sb + kh * 32 + n2 * 16 * APITCH);
#pragma unroll
            for (int mb = 0; mb < 2; mb++)
#pragma unroll
                for (int nb = 0; nb < 8; nb++)
                    mma16816(acc[mb][nb], a[mb][0], a[mb][1], a[mb][2], a[mb][3],
                             b[nb][0], b[nb][1]);
        }
    }

    const int g = lane >> 2, t = lane & 3;
    float lsum[2][2] = {{0.f, 0.f}, {0.f, 0.f}};
#pragma unroll
    for (int mb = 0; mb < 2; mb++) {
        const int r0 = bm + wm * 32 + mb * 16 + g;
#pragma unroll
        for (int nb = 0; nb < 8; nb++) {
            const int col = bn + wn * 64 + nb * 8 + t * 2;
            const float b0 = bias[col], b1 = bias[col + 1];
            float v00 = acc[mb][nb][0] + b0, v01 = acc[mb][nb][1] + b1;
            float v10 = acc[mb][nb][2] + b0, v11 = acc[mb][nb][3] + b1;
            if (RELU) {
                v00 = fmaxf(v00, 0.f); v01 = fmaxf(v01, 0.f);
                v10 = fmaxf(v10, 0.f); v11 = fmaxf(v11, 0.f);
            }
            if (OUTS) {
                *(__half2*)(Cs + (size_t)r0 * N + col) =
                    __halves2half2(__float2half(v00), __float2half(v01));
                *(__half2*)(Cs + (size_t)(r0 + 8) * N + col) =
                    __halves2half2(__float2half(v10), __float2half(v11));
            }
            if (LOGITS) {
                const float w0 = w3[col], w1 = w3[col + 1];
                lsum[mb][0] = fmaf(v00, w0, fmaf(v01, w1, lsum[mb][0]));
                lsum[mb][1] = fmaf(v10, w0, fmaf(v11, w1, lsum[mb][1]));
            }
        }
    }
    if (LOGITS) {
#pragma unroll
        for (int mb = 0; mb < 2; mb++)
#pragma unroll
            for (int rr = 0; rr < 2; rr++) {
                float s = lsum[mb][rr];
                s += __shfl_xor_sync(0xffffffffu, s, 1);
                s += __shfl_xor_sync(0xffffffffu, s, 2);
                if (t == 0) {
                    int row = bm + wm * 32 + mb * 16 + g + rr * 8;
                    lpart[(size_t)row * 16 + blockIdx.x * 2 + wn] = s;
                }
            }
    }
}

// ===================== 64x64 fp16 HMMA GEMM ==============
#define ATILE64_B (64 * APITCH)
#define STAGE64_B (2 * ATILE64_B)
#define SMEM_DYN64 (4 * STAGE64_B)       // 40960

__device__ __forceinline__ void cp_stage64(const __half* __restrict__ A,
                                           const __half* __restrict__ B,
                                           int bm, int bn, uint32_t sbase, int tid,
                                           int it)
{
    const int kk = it * 32;
    int row = tid >> 2, kc = tid & 3;
    cp16(sbase + row * APITCH + kc * 16,
         A + (size_t)(bm + row) * H + kk + kc * 8);
    cp16(sbase + ATILE64_B + row * APITCH + kc * 16,
         B + (size_t)(bn + row) * H + kk + kc * 8);
}

__device__ __forceinline__ void gemm64_body(
    const __half* __restrict__ A, const __half* __restrict__ B,
    const float* __restrict__ bias, __half* __restrict__ Cs, int N,
    int bm, int bn, uint32_t sbase, int tid)
{
    const int lane = tid & 31, w = tid >> 5;
    const int wm = w & 1, wn = w >> 1;

#pragma unroll
    for (int s = 0; s < 3; s++) {
        cp_stage64(A, B, bm, bn, sbase + s * STAGE64_B, tid, s);
        cp_commit();
    }

    float acc[2][2][4];
#pragma unroll
    for (int mb = 0; mb < 2; mb++)
#pragma unroll
        for (int nb = 0; nb < 2; nb++)
#pragma unroll
            for (int q = 0; q < 4; q++) acc[mb][nb][q] = 0.f;

    const int quad = lane >> 3, li = lane & 7;
    const uint32_t aAddr = sbase +
        (uint32_t)((wm * 32 + (quad & 1) * 8 + li) * APITCH + (quad >> 1) * 16);
    const uint32_t bAddr = sbase + ATILE64_B +
        (uint32_t)((wn * 16 + (quad >> 1) * 8 + li) * APITCH + (quad & 1) * 16);

    for (int i = 0; i < NIT; i++) {
        cp_wait<2>();
        __syncthreads();
        if (i + 3 < NIT)
            cp_stage64(A, B, bm, bn, sbase + ((i + 3) & 3) * STAGE64_B, tid, i + 3);
        cp_commit();

        const uint32_t sa = aAddr + (i & 3) * STAGE64_B;
        const uint32_t sb = bAddr + (i & 3) * STAGE64_B;
#pragma unroll
        for (int kh = 0; kh < 2; kh++) {
            uint32_t a[2][4];
            ldm_x4(a[0][0], a[0][1], a[0][2], a[0][3], sa + kh * 32);
            ldm_x4(a[1][0], a[1][1], a[1][2], a[1][3], sa + kh * 32 + 16 * APITCH);
            uint32_t b[2][2];
            ldm_x4(b[0][0], b[0][1], b[1][0], b[1][1], sb + kh * 32);
#pragma unroll
            for (int mb = 0; mb < 2; mb++)
#pragma unroll
                for (int nb = 0; nb < 2; nb++)
                    mma16816(acc[mb][nb], a[mb][0], a[mb][1], a[mb][2], a[mb][3],
                             b[nb][0], b[nb][1]);
        }
    }

    const int g = lane >> 2, t = lane & 3;
#pragma unroll
    for (int mb = 0; mb < 2; mb++) {
        const int r0 = bm + wm * 32 + mb * 16 + g;
#pragma unroll
        for (int nb = 0; nb < 2; nb++) {
            const int col = bn + wn * 16 + nb * 8 + t * 2;
            const float b0 = bias[col], b1 = bias[col + 1];
            *(__half2*)(Cs + (size_t)r0 * N + col) = __halves2half2(
                __float2half(acc[mb][nb][0] + b0), __float2half(acc[mb][nb][1] + b1));
            *(__half2*)(Cs + (size_t)(r0 + 8) * N + col) = __halves2half2(
                __float2half(acc[mb][nb][2] + b0), __float2half(acc[mb][nb][3] + b1));
        }
    }
}

__global__ void __launch_bounds__(256, 2)
gemm_hmma64(const __half* __restrict__ A, const __half* __restrict__ B,
            const float* __restrict__ bias, __half* __restrict__ Cs, int N)
{
    extern __shared__ char sm[];
    gemm64_body(A, B, bias, Cs, N,
                blockIdx.y * 64, blockIdx.x * 64, smem_u32(sm), threadIdx.x);
}

// GEMM1 (64 CTAs) + gh1 GEMV (384 blocks) fused into one 448-block launch
__global__ void __launch_bounds__(256, 2)
k_gemm1_gemv(const float* __restrict__ b_emb,
             const float* __restrict__ state, const float* __restrict__ W_hh,
             const float* __restrict__ b_hh)
{
    extern __shared__ char sm[];
    const int blk = blockIdx.x, tid = threadIdx.x;
    if (blk < 64) {         // GEMM1: emb = table @ Wemb^T + b_emb  (grid 16 x 4)
        gemm64_body(g2_table, g2_Wemb, b_emb, g2_emb, H,
                    (blk >> 4) * 64, (blk & 15) * 64, smem_u32(sm), tid);
    } else {                // GEMV: gh1 = state @ W_hh^T + b_hh
        int n = (blk - 64) * 8 + (tid >> 5);
        int lane = tid & 31;
        const float* w = W_hh + (size_t)n * H;
        float s = 0.f;
#pragma unroll
        for (int k = lane * 4; k < H; k += 128) {
            float4 wv = *(const float4*)(w + k);
            float4 xv = *(const float4*)(state + k);
            s = fmaf(wv.x, xv.x, s); s = fmaf(wv.y, xv.y, s);
            s = fmaf(wv.z, xv.z, s); s = fmaf(wv.w, xv.w, s);
        }
#pragma unroll
        for (int o = 16; o; o >>= 1) s += __shfl_xor_sync(0xffffffffu, s, o);
        if (lane == 0) g_gh1[n] = s + b_hh[n];
    }
}

// ===================== fused fp32 -> fp16 convert for ALL 6 operands =====================
#define CVT_ROWS (256 + 1024 + 3072 + 3072 + 1024 + 1024)
__global__ void __launch_bounds__(256)
cvt_all(const float* __restrict__ s0, const float* __restrict__ s1,
        const float* __restrict__ s2, const float* __restrict__ s3,
        const float* __restrict__ s4, const float* __restrict__ s5,
        __half* __restrict__ d0, __half* __restrict__ d1,
        __half* __restrict__ d2, __half* __restrict__ d3,
        __half* __restrict__ d4, __half* __restrict__ d5)
{
    int row = blockIdx.x;
    const float* src; __half* dst; int r = row;
    if      (r < 256)        { src = s0; dst = d0; }
    else if ((r -= 256)  < 1024) { src = s1; dst = d1; }
    else if ((r -= 1024) < 3072) { src = s2; dst = d2; }
    else if ((r -= 3072) < 3072) { src = s3; dst = d3; }
    else if ((r -= 3072) < 1024) { src = s4; dst = d4; }
    else     { r -= 1024;      src = s5; dst = d5; }

    int c4 = threadIdx.x * 4;
    float4 x = *(const float4*)(src + (size_t)r * H + c4);
    __half* o = dst + (size_t)r * H + c4;
    *(__half2*)(o)     = __halves2half2(__float2half(x.x), __float2half(x.y));
    *(__half2*)(o + 2) = __halves2half2(__float2half(x.z), __float2half(x.w));
}

// ===================== GRU combine =====================
__device__ __forceinline__ float4 ld4h(const __half* p) {
    float2 f0 = __half22float2(*(const __half2*)p);
    float2 f1 = __half22float2(*(const __half2*)(p + 2));
    return make_float4(f0.x, f0.y, f1.x, f1.y);
}
__device__ __forceinline__ float gru1(float ir, float iz, float inn,
                                      float hr, float hz, float hn, float h)
{
    float r = 1.f / (1.f + __expf(-(ir + hr)));
    float z = 1.f / (1.f + __expf(-(iz + hz)));
    float n = tanhf(fmaf(r, hn, inn));
    return fmaf(z, h - n, n);
}
__device__ __forceinline__ float4 gru4_comb(float4 ir, float4 iz, float4 inn,
                                            float4 hr, float4 hz, float4 hn, float4 hv)
{
    float4 o;
    o.x = gru1(ir.x, iz.x, inn.x, hr.x, hz.x, hn.x, hv.x);
    o.y = gru1(ir.y, iz.y, inn.y, hr.y, hz.y, hn.y, hv.y);
    o.z = gru1(ir.z, iz.z, inn.z, hr.z, hz.z, hn.z, hv.z);
    o.w = gru1(ir.w, iz.w, inn.w, hr.w, hz.w, hn.w, hv.w);
    return o;
}
__device__ __forceinline__ float4 gru4_hf(const __half* gi, const float* gh,
                                          const float* h, int j)
{
    return gru4_comb(ld4h(gi + j), ld4h(gi + H + j), ld4h(gi + 2 * H + j),
                     *(const float4*)(gh + j), *(const float4*)(gh + H + j),
                     *(const float4*)(gh + 2 * H + j), *(const float4*)(h + j));
}
__device__ __forceinline__ float4 gru4_hh(const __half* gi, const __half* gh,
                                          const float* h, int j)
{
    return gru4_comb(ld4h(gi + j), ld4h(gi + H + j), ld4h(gi + 2 * H + j),
                     ld4h(gh + j), ld4h(gh + H + j), ld4h(gh + 2 * H + j),
                     *(const float4*)(h + j));
}
__device__ __forceinline__ void cvt_store(__half* o, float4 v)
{
    *(__half2*)(o)     = __halves2half2(__float2half(v.x), __float2half(v.y));
    *(__half2*)(o + 2) = __halves2half2(__float2half(v.z), __float2half(v.w));
}

__global__ void gru_h1_kernel(const float* __restrict__ state)
{
    int v = blockIdx.x;
    int j = threadIdx.x * 4;
    float4 o = gru4_hf(g2_gi + (size_t)v * H3, g_gh1, state, j);
    *(float4*)(g_h1 + (size_t)v * H + j) = o;
    cvt_store(g2_h1 + (size_t)v * H + j, o);
}

__global__ void gru_step2_all(const int* __restrict__ rel_tokens,
                              const int* __restrict__ attr_tokens)
{
    int blk = blockIdx.x;
    int j = threadIdx.x * 4;
    if (blk < NREL) {
        int t0 = rel_tokens[blk * 3 + 0];
        int t1 = rel_tokens[blk * 3 + 1];
        float4 o = gru4_hh(g2_gi + (size_t)t1 * H3, g2_gh2 + (size_t)t0 * H3,
                           g_h1 + (size_t)t0 * H, j);
        *(float4*)(g_h2rel + (size_t)blk * H + j) = o;
        cvt_store(g2_h2rel + (size_t)blk * H + j, o);
    } else {
        int n = blk - NREL;
        int t0 = attr_tokens[n * 2 + 0];
        int t1 = attr_tokens[n * 2 + 1];
        float4 o = gru4_hh(g2_gi + (size_t)t1 * H3, g2_gh2 + (size_t)t0 * H3,
                           g_h1 + (size_t)t0 * H, j);
        cvt_store(g2_clause + (size_t)(NREL + n) * H + j, o);
    }
}

__global__ void gru_step3_kernel(const int* __restrict__ rel_tokens)
{
    int n  = blockIdx.x;
    int t2 = rel_tokens[n * 3 + 2];
    int j  = threadIdx.x * 4;
    float4 o = gru4_hh(g2_gi + (size_t)t2 * H3, g2_gh3 + (size_t)n * H3,
                       g_h2rel + (size_t)n * H, j);
    cvt_store(g2_clause + (size_t)n * H + j, o);
}

// ===================== logits reduce + softmax + eps smoothing =====================
__global__ void softmax_kernel(const float* __restrict__ eps, float* __restrict__ out)
{
    const int N = NCL;
    __shared__ float sl[NCL];
    __shared__ float shm[32], shs[32];
    int tid = threadIdx.x;

    for (int i = tid; i < N; i += 1024) {
        const float4* p = (const float4*)(g_lpart + (size_t)i * 16);
        float4 a = p[0], b = p[1], c = p[2], d = p[3];
        sl[i] = ((a.x + a.y) + (a.z + a.w)) + ((b.x + b.y) + (b.z + b.w))
              + ((c.x + c.y) + (c.z + c.w)) + ((d.x + d.y) + (d.z + d.w));
    }
    __syncthreads();

    float m = -1e30f;
    for (int i = tid; i < N; i += 1024) m = fmaxf(m, sl[i]);
#pragma unroll
    for (int o = 16; o; o >>= 1) m = fmaxf(m, __shfl_xor_sync(0xffffffffu, m, o));
    if ((tid & 31) == 0) shm[tid >> 5] = m;
    __syncthreads();
    if (tid < 32) {
        float v = shm[tid];
#pragma unroll
        for (int o = 16; o; o >>= 1) v = fmaxf(v, __shfl_xor_sync(0xffffffffu, v, o));
        shm[tid] = v;
    }
    __syncthreads();
    float M = shm[0];

    float s = 0.f;
    for (int i = tid; i < N; i += 1024) s += __expf(sl[i] - M);
#pragma unroll
    for (int o = 16; o; o >>= 1) s += __shfl_xor_sync(0xffffffffu, s, o);
    if ((tid & 31) == 0) shs[tid >> 5] = s;
    __syncthreads();
    if (tid < 32) {
        float v = shs[tid];
#pragma unroll
        for (int o = 16; o; o >>= 1) v += __shfl_xor_sync(0xffffffffu, v, o);
        shs[tid] = v;
    }
    __syncthreads();
    float S = shs[0];
    float e = eps[0];
    float inv = (1.f - e) / S;
    float add = e / (float)N;
    for (int i = tid; i < N; i += 1024)
        out[i] = __expf(sl[i] - M) * inv + add;
}

// ===================== launch =====================
extern "C" void kernel_launch(void* const* d_in, const int* in_sizes, int n_in,
                              void* d_out, int out_size)
{
    const float* state       = (const float*)d_in[0];
    const int*   rel_tokens  = (const int*)d_in[1];
    const int*   attr_tokens = (const int*)d_in[2];
    const float* table       = (const float*)d_in[3];
    const float* W_emb       = (const float*)d_in[4];
    const float* b_emb       = (const float*)d_in[5];
    const float* W_ih        = (const float*)d_in[6];
    const float* W_hh        = (const float*)d_in[7];
    const float* b_ih        = (const float*)d_in[8];
    const float* b_hh        = (const float*)d_in[9];
    const float* W1          = (const float*)d_in[10];
    const float* b1          = (const float*)d_in[11];
    const float* W2          = (const float*)d_in[12];
    const float* b2          = (const float*)d_in[13];
    const float* W3          = (const float*)d_in[14];
    const float* eps         = (const float*)d_in[16];
    float* out = (float*)d_out;

    __half *p2_table, *p2_Wemb, *p2_Wih, *p2_Whh, *p2_W1, *p2_W2;
    __half *p2_emb, *p2_h1, *p2_clause, *p2_x1, *p2_gi, *p2_gh2;
    float *p_lpart;
    cudaGetSymbolAddress((void**)&p2_table,  g2_table);
    cudaGetSymbolAddress((void**)&p2_Wemb,   g2_Wemb);
    cudaGetSymbolAddress((void**)&p2_Wih,    g2_Wih);
    cudaGetSymbolAddress((void**)&p2_Whh,    g2_Whh);
    cudaGetSymbolAddress((void**)&p2_W1,     g2_W1);
    cudaGetSymbolAddress((void**)&p2_W2,     g2_W2);
    cudaGetSymbolAddress((void**)&p2_emb,    g2_emb);
    cudaGetSymbolAddress((void**)&p2_h1,     g2_h1);
    cudaGetSymbolAddress((void**)&p2_clause, g2_clause);
    cudaGetSymbolAddress((void**)&p2_x1,     g2_x1);
    cudaGetSymbolAddress((void**)&p2_gi,     g2_gi);
    cudaGetSymbolAddress((void**)&p2_gh2,    g2_gh2);
    cudaGetSymbolAddress((void**)&p_lpart,   g_lpart);

    cudaFuncSetAttribute(gemm_dual,
                         cudaFuncAttributeMaxDynamicSharedMemorySize, SMEM_DYN_H);
    cudaFuncSetAttribute(gemm_hmma<true, true, false>,
                         cudaFuncAttributeMaxDynamicSharedMemorySize, SMEM_DYN_H);
    cudaFuncSetAttribute(gemm_hmma<true, false, true>,
                         cudaFuncAttributeMaxDynamicSharedMemorySize, SMEM_DYN_H);

    // 0. convert all fp32 operands to fp16
    cvt_all<<<CVT_ROWS, 256>>>(table, W_emb, W_ih, W_hh, W1, W2,
                               p2_table, p2_Wemb, p2_Wih, p2_Whh, p2_W1, p2_W2);
    // 1. GEMM1 (emb) + gh1 GEMV in one launch (GEMM1 alone is 64 CTAs — 78% idle)
    k_gemm1_gemv<<<448, 256, SMEM_DYN64>>>(b_emb, state, W_hh, b_hh);
    // 2. gi_table[V,3H] (fp16 out)
    gemm_hmma64<<<dim3(H3 / 64, V / 64), 256, SMEM_DYN64>>>(
        p2_emb, p2_Wih, b_ih, p2_gi, H3);
    // 3. h1_table (fp32 + fp16)
    gru_h1_kernel<<<V, 256>>>(state);
    // 4. gh2_table[V,3H] (fp16 out)
    gemm_hmma64<<<dim3(H3 / 64, V / 64), 256, SMEM_DYN64>>>(
        p2_h1, p2_Whh, b_hh, p2_gh2, H3);
    // 5. merged step-2 (rel + attr)
    gru_step2_all<<<NREL + NATT, 256>>>(rel_tokens, attr_tokens);
    // 6. DUAL: GEMM8 (gh3, 768 CTAs) + GEMM10-attr (256 CTAs) packed in one launch
    gemm_dual<<<1024, 256, SMEM_DYN_H>>>(b_hh, b1);
    // 7. rel step 3 -> clause fp16 rows [0, 4096)
    gru_step3_kernel<<<NREL, 256>>>(rel_tokens);
    // 8. GEMM10-rel: x1[0:4096) = relu(clause[0:4096) @ W1^T + b1)
    gemm_hmma<true, true, false><<<dim3(H / 128, NREL / 128), 256, SMEM_DYN_H>>>(
        p2_clause, p2_W1, b1, p2_x1, H, nullptr, nullptr);
    // 9. GEMM11 with fused logits partials (x2 never materialized; b3 shift dropped)
    gemm_hmma<true, false, true><<<dim3(H / 128, NCL / 128), 256, SMEM_DYN_H>>>(
        p2_x1, p2_W2, b2, nullptr, H, W3, p_lpart);
    // 10. logits reduce + softmax + smoothing
    softmax_kernel<<<1, 1024>>>(eps, out);
}

// round 10
// speedup vs baseline: 6.4363x; 1.0069x over previous
#include <cuda_runtime.h>
#include <cuda_fp16.h>
#include <math.h>
#include <stdint.h>

#define H    1024
#define H3   3072
#define NREL 4096
#define NATT 4096
#define NCL  8192
#define V    256

// ===================== scratch (device globals; no allocations) =====================
__device__ __align__(256) __half g2_table[V * H];
__device__ __align__(256) __half g2_Wemb[H * H];
__device__ __align__(256) __half g2_Wih[H3 * H];
__device__ __align__(256) __half g2_Whh[H3 * H];
__device__ __align__(256) __half g2_W1[H * H];
__device__ __align__(256) __half g2_W2[H * H];
__device__ __align__(256) __half g2_emb[V * H];
__device__ __align__(256) __half g2_h1[V * H];
__device__ __align__(256) __half g2_h2rel[NREL * H];
__device__ __align__(256) __half g2_clause[NCL * H];
__device__ __align__(256) __half g2_x1[NCL * H];
__device__ __align__(256) __half g2_gi[V * H3];
__device__ __align__(256) __half g2_gh2[V * H3];
__device__ __align__(256) __half g2_gh3[NREL * H3];
__device__ float g_gh1[H3];
__device__ float g_lpart[NCL * 16];

// ===================== PTX helpers =====================
__device__ __forceinline__ uint32_t smem_u32(const void* p) {
    uint32_t a;
    asm("{ .reg .u64 t; cvta.to.shared.u64 t, %1; cvt.u32.u64 %0, t; }" : "=r"(a) : "l"(p));
    return a;
}
__device__ __forceinline__ void cp16(uint32_t dst, const void* src) {
    asm volatile("cp.async.cg.shared.global [%0], [%1], 16;" :: "r"(dst), "l"(src));
}
__device__ __forceinline__ void cp_commit() {
    asm volatile("cp.async.commit_group;" ::: "memory");
}
template <int N>
__device__ __forceinline__ void cp_wait() {
    asm volatile("cp.async.wait_group %0;" :: "n"(N) : "memory");
}
__device__ __forceinline__ void ldm_x4(uint32_t& r0, uint32_t& r1, uint32_t& r2, uint32_t& r3,
                                       uint32_t addr) {
    asm volatile("ldmatrix.sync.aligned.m8n8.x4.shared.b16 {%0,%1,%2,%3}, [%4];"
                 : "=r"(r0), "=r"(r1), "=r"(r2), "=r"(r3) : "r"(addr));
}
__device__ __forceinline__ void mma16816(float* c, uint32_t a0, uint32_t a1, uint32_t a2,
                                         uint32_t a3, uint32_t b0, uint32_t b1) {
    asm volatile(
        "mma.sync.aligned.m16n8k16.row.col.f32.f16.f16.f32 "
        "{%0,%1,%2,%3}, {%4,%5,%6,%7}, {%8,%9}, {%0,%1,%2,%3};"
        : "+f"(c[0]), "+f"(c[1]), "+f"(c[2]), "+f"(c[3])
        : "r"(a0), "r"(a1), "r"(a2), "r"(a3), "r"(b0), "r"(b1));
}

#define APITCH   80
#define NIT      32

// ===================== shared 128x128 fp16 HMMA body ====================
#define ATILE_B  (128 * APITCH)
#define STAGE_B  (2 * ATILE_B)
#define SMEM_DYN_H (4 * STAGE_B)        // 81920

__device__ __forceinline__ void cp_stage(const __half* __restrict__ A,
                                         const __half* __restrict__ B,
                                         int bm, int bn, uint32_t sbase, int tid,
                                         int it)
{
    const int kk = it * 32;
#pragma unroll
    for (int h = 0; h < 2; h++) {
        int c = tid + h * 256;
        int row = c >> 2, kc = c & 3;
        cp16(sbase + row * APITCH + kc * 16,
             A + (size_t)(bm + row) * H + kk + kc * 8);
    }
#pragma unroll
    for (int h = 0; h < 2; h++) {
        int c = tid + h * 256;
        int row = c >> 2, kc = c & 3;
        cp16(sbase + ATILE_B + row * APITCH + kc * 16,
             B + (size_t)(bn + row) * H + kk + kc * 8);
    }
}

template <bool RELU, bool OUTS, bool LOGITS>
__device__ __forceinline__ void body128(
    const __half* __restrict__ A, const __half* __restrict__ B,
    const float* __restrict__ bias, __half* __restrict__ Cs, int N,
    int bm, int bn,
    const float* __restrict__ w3, float* __restrict__ lpart, int bxLog,
    uint32_t sbase, int tid)
{
    const int lane = tid & 31, w = tid >> 5;
    const int wm = w & 3, wn = w >> 2;

#pragma unroll
    for (int s = 0; s < 3; s++) {
        cp_stage(A, B, bm, bn, sbase + s * STAGE_B, tid, s);
        cp_commit();
    }

    float acc[2][8][4];
#pragma unroll
    for (int mb = 0; mb < 2; mb++)
#pragma unroll
        for (int nb = 0; nb < 8; nb++)
#pragma unroll
            for (int q = 0; q < 4; q++) acc[mb][nb][q] = 0.f;

    const int quad = lane >> 3, li = lane & 7;
    const uint32_t aAddr = sbase +
        (uint32_t)((wm * 32 + (quad & 1) * 8 + li) * APITCH + (quad >> 1) * 16);
    const uint32_t bAddr = sbase + ATILE_B +
        (uint32_t)((wn * 64 + (quad >> 1) * 8 + li) * APITCH + (quad & 1) * 16);

    for (int i = 0; i < NIT; i++) {
        cp_wait<2>();
        __syncthreads();
        if (i + 3 < NIT)
            cp_stage(A, B, bm, bn, sbase + ((i + 3) & 3) * STAGE_B, tid, i + 3);
        cp_commit();

        const uint32_t sa = aAddr + (i & 3) * STAGE_B;
        const uint32_t sb = bAddr + (i & 3) * STAGE_B;
#pragma unroll
        for (int kh = 0; kh < 2; kh++) {
            uint32_t a[2][4];
            ldm_x4(a[0][0], a[0][1], a[0][2], a[0][3], sa + kh * 32);
            ldm_x4(a[1][0], a[1][1], a[1][2], a[1][3], sa + kh * 32 + 16 * APITCH);
            uint32_t b[8][2];
#pragma unroll
            for (int n2 = 0; n2 < 4; n2++)
                ldm_x4(b[2 * n2][0], b[2 * n2][1], b[2 * n2 + 1][0], b[2 * n2 + 1][1],
                       sb + kh * 32 + n2 * 16 * APITCH);
#pragma unroll
            for (int mb = 0; mb < 2; mb++)
#pragma unroll
                for (int nb = 0; nb < 8; nb++)
                    mma16816(acc[mb][nb], a[mb][0], a[mb][1], a[mb][2], a[mb][3],
                             b[nb][0], b[nb][1]);
        }
    }

    const int g = lane >> 2, t = lane & 3;
    float lsum[2][2] = {{0.f, 0.f}, {0.f, 0.f}};
#pragma unroll
    for (int mb = 0; mb < 2; mb++) {
        const int r0 = bm + wm * 32 + mb * 16 + g;
#pragma unroll
        for (int nb = 0; nb < 8; nb++) {
            const int col = bn + wn * 64 + nb * 8 + t * 2;
            const float b0 = bias[col], b1 = bias[col + 1];
            float v00 = acc[mb][nb][0] + b0, v01 = acc[mb][nb][1] + b1;
            float v10 = acc[mb][nb][2] + b0, v11 = acc[mb][nb][3] + b1;
            if (RELU) {
                v00 = fmaxf(v00, 0.f); v01 = fmaxf(v01, 0.f);
                v10 = fmaxf(v10, 0.f); v11 = fmaxf(v11, 0.f);
            }
            if (OUTS) {
                *(__half2*)(Cs + (size_t)r0 * N + col) =
                    __halves2half2(__float2half(v00), __float2half(v01));
                *(__half2*)(Cs + (size_t)(r0 + 8) * N + col) =
                    __halves2half2(__float2half(v10), __float2half(v11));
            }
            if (LOGITS) {
                const float w0 = w3[col], w1 = w3[col + 1];
                lsum[mb][0] = fmaf(v00, w0, fmaf(v01, w1, lsum[mb][0]));
                lsum[mb][1] = fmaf(v10, w0, fmaf(v11, w1, lsum[mb][1]));
            }
        }
    }
    if (LOGITS) {
#pragma unroll
        for (int mb = 0; mb < 2; mb++)
#pragma unroll
            for (int rr = 0; rr < 2; rr++) {
                float s = lsum[mb][rr];
                s += __shfl_xor_sync(0xffffffffu, s, 1);
                s += __shfl_xor_sync(0xffffffffu, s, 2);
                if (t == 0) {
                    int row = bm + wm * 32 + mb * 16 + g + rr * 8;
                    lpart[(size_t)row * 16 + bxLog * 2 + wn] = s;
                }
            }
    }
}

// DUAL 1: GEMM8 (gh3, 768 CTAs) + GEMM10-attr (x1 attr half, 256 CTAs)
__global__ void __launch_bounds__(256, 2)
gemm_dual(const float* __restrict__ b_hh, const float* __restrict__ b1)
{
    extern __shared__ char sm[];
    const uint32_t sbase = smem_u32(sm);
    const int tid = threadIdx.x, blk = blockIdx.x;
    if (blk < 768) {        // gh3 = h2rel @ Whh^T + b_hh
        body128<false, true, false>(g2_h2rel, g2_Whh, b_hh, g2_gh3, H3,
                                    (blk / 24) * 128, (blk % 24) * 128,
                                    nullptr, nullptr, 0, sbase, tid);
    } else {                // x1[4096:] = relu(clause[4096:] @ W1^T + b1)
        int t = blk - 768;
        body128<true, true, false>(g2_clause, g2_W1, b1, g2_x1, H,
                                   NREL + (t >> 3) * 128, (t & 7) * 128,
                                   nullptr, nullptr, 0, sbase, tid);
    }
}

// DUAL 2: GEMM10-rel (x1 rel half, 256 CTAs, drains first) + GEMM11-attr (logits, 256)
__global__ void __launch_bounds__(256, 2)
gemm_dual2(const float* __restrict__ b1, const float* __restrict__ b2,
           const float* __restrict__ w3, float* __restrict__ lpart)
{
    extern __shared__ char sm[];
    const uint32_t sbase = smem_u32(sm);
    const int tid = threadIdx.x, blk = blockIdx.x;
    if (blk < 256) {        // x1[0:4096) = relu(clause[0:4096) @ W1^T + b1)
        body128<true, true, false>(g2_clause, g2_W1, b1, g2_x1, H,
                                   (blk >> 3) * 128, (blk & 7) * 128,
                                   nullptr, nullptr, 0, sbase, tid);
    } else {                // logits partials for attr rows: relu(x1@W2^T+b2) . w3
        int t = blk - 256;
        body128<true, false, true>(g2_x1, g2_W2, b2, nullptr, H,
                                   NREL + (t >> 3) * 128, (t & 7) * 128,
                                   w3, lpart, t & 7, sbase, tid);
    }
}

// GEMM11-rel (logits partials for rel rows, 256 CTAs)
__global__ void __launch_bounds__(256, 2)
gemm_logits_rel(const float* __restrict__ b2, const float* __restrict__ w3,
                float* __restrict__ lpart)
{
    extern __shared__ char sm[];
    body128<true, false, true>(g2_x1, g2_W2, b2, nullptr, H,
                               blockIdx.y * 128, blockIdx.x * 128,
                               w3, lpart, blockIdx.x, smem_u32(sm), threadIdx.x);
}

// ===================== 64x64 fp16 HMMA GEMM ==============
#define ATILE64_B (64 * APITCH)
#define STAGE64_B (2 * ATILE64_B)
#define SMEM_DYN64 (4 * STAGE64_B)       // 40960

__device__ __forceinline__ void cp_stage64(const __half* __restrict__ A,
                                           const __half* __restrict__ B,
                                           int bm, int bn, uint32_t sbase, int tid,
                                           int it)
{
    const int kk = it * 32;
    int row = tid >> 2, kc = tid & 3;
    cp16(sbase + row * APITCH + kc * 16,
         A + (size_t)(bm + row) * H + kk + kc * 8);
    cp16(sbase + ATILE64_B + row * APITCH + kc * 16,
         B + (size_t)(bn + row) * H + kk + kc * 8);
}

__device__ __forceinline__ void gemm64_body(
    const __half* __restrict__ A, const __half* __restrict__ B,
    const float* __restrict__ bias, __half* __restrict__ Cs, int N,
    int bm, int bn, uint32_t sbase, int tid)
{
    const int lane = tid & 31, w = tid >> 5;
    const int wm = w & 1, wn = w >> 1;

#pragma unroll
    for (int s = 0; s < 3; s++) {
        cp_stage64(A, B, bm, bn, sbase + s * STAGE64_B, tid, s);
        cp_commit();
    }

    float acc[2][2][4];
#pragma unroll
    for (int mb = 0; mb < 2; mb++)
#pragma unroll
        for (int nb = 0; nb < 2; nb++)
#pragma unroll
            for (int q = 0; q < 4; q++) acc[mb][nb][q] = 0.f;

    const int quad = lane >> 3, li = lane & 7;
    const uint32_t aAddr = sbase +
        (uint32_t)((wm * 32 + (quad & 1) * 8 + li) * APITCH + (quad >> 1) * 16);
    const uint32_t bAddr = sbase + ATILE64_B +
        (uint32_t)((wn * 16 + (quad >> 1) * 8 + li) * APITCH + (quad & 1) * 16);

    for (int i = 0; i < NIT; i++) {
        cp_wait<2>();
        __syncthreads();
        if (i + 3 < NIT)
            cp_stage64(A, B, bm, bn, sbase + ((i + 3) & 3) * STAGE64_B, tid, i + 3);
        cp_commit();

        const uint32_t sa = aAddr + (i & 3) * STAGE64_B;
        const uint32_t sb = bAddr + (i & 3) * STAGE64_B;
#pragma unroll
        for (int kh = 0; kh < 2; kh++) {
            uint32_t a[2][4];
            ldm_x4(a[0][0], a[0][1], a[0][2], a[0][3], sa + kh * 32);
            ldm_x4(a[1][0], a[1][1], a[1][2], a[1][3], sa + kh * 32 + 16 * APITCH);
            uint32_t b[2][2];
            ldm_x4(b[0][0], b[0][1], b[1][0], b[1][1], sb + kh * 32);
#pragma unroll
            for (int mb = 0; mb < 2; mb++)
#pragma unroll
                for (int nb = 0; nb < 2; nb++)
                    mma16816(acc[mb][nb], a[mb][0], a[mb][1], a[mb][2], a[mb][3],
                             b[nb][0], b[nb][1]);
        }
    }

    const int g = lane >> 2, t = lane & 3;
#pragma unroll
    for (int mb = 0; mb < 2; mb++) {
        const int r0 = bm + wm * 32 + mb * 16 + g;
#pragma unroll
        for (int nb = 0; nb < 2; nb++) {
            const int col = bn + wn * 16 + nb * 8 + t * 2;
            const float b0 = bias[col], b1 = bias[col + 1];
            *(__half2*)(Cs + (size_t)r0 * N + col) = __halves2half2(
                __float2half(acc[mb][nb][0] + b0), __float2half(acc[mb][nb][1] + b1));
            *(__half2*)(Cs + (size_t)(r0 + 8) * N + col) = __halves2half2(
                __float2half(acc[mb][nb][2] + b0), __float2half(acc[mb][nb][3] + b1));
        }
    }
}

__global__ void __launch_bounds__(256, 2)
gemm_hmma64(const __half* __restrict__ A, const __half* __restrict__ B,
            const float* __restrict__ bias, __half* __restrict__ Cs, int N)
{
    extern __shared__ char sm[];
    gemm64_body(A, B, bias, Cs, N,
                blockIdx.y * 64, blockIdx.x * 64, smem_u32(sm), threadIdx.x);
}

// GEMM1 (64 CTAs) + gh1 GEMV (384 blocks) fused
__global__ void __launch_bounds__(256, 2)
k_gemm1_gemv(const float* __restrict__ b_emb,
             const float* __restrict__ state, const float* __restrict__ W_hh,
             const float* __restrict__ b_hh)
{
    extern __shared__ char sm[];
    const int blk = blockIdx.x, tid = threadIdx.x;
    if (blk < 64) {
        gemm64_body(g2_table, g2_Wemb, b_emb, g2_emb, H,
                    (blk >> 4) * 64, (blk & 15) * 64, smem_u32(sm), tid);
    } else {
        int n = (blk - 64) * 8 + (tid >> 5);
        int lane = tid & 31;
        const float* w = W_hh + (size_t)n * H;
        float s = 0.f;
#pragma unroll
        for (int k = lane * 4; k < H; k += 128) {
            float4 wv = *(const float4*)(w + k);
            float4 xv = *(const float4*)(state + k);
            s = fmaf(wv.x, xv.x, s); s = fmaf(wv.y, xv.y, s);
            s = fmaf(wv.z, xv.z, s); s = fmaf(wv.w, xv.w, s);
        }
#pragma unroll
        for (int o = 16; o; o >>= 1) s += __shfl_xor_sync(0xffffffffu, s, o);
        if (lane == 0) g_gh1[n] = s + b_hh[n];
    }
}

// ===================== fused fp32 -> fp16 convert =====================
#define CVT_ROWS (256 + 1024 + 3072 + 3072 + 1024 + 1024)
__global__ void __launch_bounds__(256)
cvt_all(const float* __restrict__ s0, const float* __restrict__ s1,
        const float* __restrict__ s2, const float* __restrict__ s3,
        const float* __restrict__ s4, const float* __restrict__ s5,
        __half* __restrict__ d0, __half* __restrict__ d1,
        __half* __restrict__ d2, __half* __restrict__ d3,
        __half* __restrict__ d4, __half* __restrict__ d5)
{
    int row = blockIdx.x;
    const float* src; __half* dst; int r = row;
    if      (r < 256)        { src = s0; dst = d0; }
    else if ((r -= 256)  < 1024) { src = s1; dst = d1; }
    else if ((r -= 1024) < 3072) { src = s2; dst = d2; }
    else if ((r -= 3072) < 3072) { src = s3; dst = d3; }
    else if ((r -= 3072) < 1024) { src = s4; dst = d4; }
    else     { r -= 1024;      src = s5; dst = d5; }

    int c4 = threadIdx.x * 4;
    float4 x = *(const float4*)(src + (size_t)r * H + c4);
    __half* o = dst + (size_t)r * H + c4;
    *(__half2*)(o)     = __halves2half2(__float2half(x.x), __float2half(x.y));
    *(__half2*)(o + 2) = __halves2half2(__float2half(x.z), __float2half(x.w));
}

// ===================== GRU combine =====================
__device__ __forceinline__ float4 ld4h(const __half* p) {
    float2 f0 = __half22float2(*(const __half2*)p);
    float2 f1 = __half22float2(*(const __half2*)(p + 2));
    return make_float4(f0.x, f0.y, f1.x, f1.y);
}
__device__ __forceinline__ float gru1(float ir, float iz, float inn,
                                      float hr, float hz, float hn, float h)
{
    float r = 1.f / (1.f + __expf(-(ir + hr)));
    float z = 1.f / (1.f + __expf(-(iz + hz)));
    float n = tanhf(fmaf(r, hn, inn));
    return fmaf(z, h - n, n);
}
__device__ __forceinline__ float4 gru4_comb(float4 ir, float4 iz, float4 inn,
                                            float4 hr, float4 hz, float4 hn, float4 hv)
{
    float4 o;
    o.x = gru1(ir.x, iz.x, inn.x, hr.x, hz.x, hn.x, hv.x);
    o.y = gru1(ir.y, iz.y, inn.y, hr.y, hz.y, hn.y, hv.y);
    o.z = gru1(ir.z, iz.z, inn.z, hr.z, hz.z, hn.z, hv.z);
    o.w = gru1(ir.w, iz.w, inn.w, hr.w, hz.w, hn.w, hv.w);
    return o;
}
__device__ __forceinline__ void cvt_store(__half* o, float4 v)
{
    *(__half2*)(o)     = __halves2half2(__float2half(v.x), __float2half(v.y));
    *(__half2*)(o + 2) = __halves2half2(__float2half(v.z), __float2half(v.w));
}

// h1 = GRU(gi[v] f16, gh1 f32, state f32) -> fp16 only
__global__ void gru_h1_kernel(const float* __restrict__ state)
{
    int v = blockIdx.x;
    int j = threadIdx.x * 4;
    const __half* gi = g2_gi + (size_t)v * H3;
    float4 o = gru4_comb(ld4h(gi + j), ld4h(gi + H + j), ld4h(gi + 2 * H + j),
                         *(const float4*)(g_gh1 + j),
                         *(const float4*)(g_gh1 + H + j),
                         *(const float4*)(g_gh1 + 2 * H + j),
                         *(const float4*)(state + j));
    cvt_store(g2_h1 + (size_t)v * H + j, o);
}

// all-fp16 GRU step (gi f16, gh f16, h f16)
__device__ __forceinline__ float4 gru4_hhh(const __half* gi, const __half* gh,
                                           const __half* h, int j)
{
    return gru4_comb(ld4h(gi + j), ld4h(gi + H + j), ld4h(gi + 2 * H + j),
                     ld4h(gh + j), ld4h(gh + H + j), ld4h(gh + 2 * H + j),
                     ld4h(h + j));
}

__global__ void gru_step2_all(const int* __restrict__ rel_tokens,
                              const int* __restrict__ attr_tokens)
{
    int blk = blockIdx.x;
    int j = threadIdx.x * 4;
    if (blk < NREL) {
        int t0 = rel_tokens[blk * 3 + 0];
        int t1 = rel_tokens[blk * 3 + 1];
        float4 o = gru4_hhh(g2_gi + (size_t)t1 * H3, g2_gh2 + (size_t)t0 * H3,
                            g2_h1 + (size_t)t0 * H, j);
        cvt_store(g2_h2rel + (size_t)blk * H + j, o);
    } else {
        int n = blk - NREL;
        int t0 = attr_tokens[n * 2 + 0];
        int t1 = attr_tokens[n * 2 + 1];
        float4 o = gru4_hhh(g2_gi + (size_t)t1 * H3, g2_gh2 + (size_t)t0 * H3,
                            g2_h1 + (size_t)t0 * H, j);
        cvt_store(g2_clause + (size_t)(NREL + n) * H + j, o);
    }
}

__global__ void gru_step3_kernel(const int* __restrict__ rel_tokens)
{
    int n  = blockIdx.x;
    int t2 = rel_tokens[n * 3 + 2];
    int j  = threadIdx.x * 4;
    float4 o = gru4_hhh(g2_gi + (size_t)t2 * H3, g2_gh3 + (size_t)n * H3,
                        g2_h2rel + (size_t)n * H, j);
    cvt_store(g2_clause + (size_t)n * H + j, o);
}

// ===================== logits reduce + softmax + eps smoothing =====================
__global__ void softmax_kernel(const float* __restrict__ eps, float* __restrict__ out)
{
    const int N = NCL;
    __shared__ float sl[NCL];
    __shared__ float shm[32], shs[32];
    int tid = threadIdx.x;

    for (int i = tid; i < N; i += 1024) {
        const float4* p = (const float4*)(g_lpart + (size_t)i * 16);
        float4 a = p[0], b = p[1], c = p[2], d = p[3];
        sl[i] = ((a.x + a.y) + (a.z + a.w)) + ((b.x + b.y) + (b.z + b.w))
              + ((c.x + c.y) + (c.z + c.w)) + ((d.x + d.y) + (d.z + d.w));
    }
    __syncthreads();

    float m = -1e30f;
    for (int i = tid; i < N; i += 1024) m = fmaxf(m, sl[i]);
#pragma unroll
    for (int o = 16; o; o >>= 1) m = fmaxf(m, __shfl_xor_sync(0xffffffffu, m, o));
    if ((tid & 31) == 0) shm[tid >> 5] = m;
    __syncthreads();
    if (tid < 32) {
        float v = shm[tid];
#pragma unroll
        for (int o = 16; o; o >>= 1) v = fmaxf(v, __shfl_xor_sync(0xffffffffu, v, o));
        shm[tid] = v;
    }
    __syncthreads();
    float M = shm[0];

    float s = 0.f;
    for (int i = tid; i < N; i += 1024) s += __expf(sl[i] - M);
#pragma unroll
    for (int o = 16; o; o >>= 1) s += __shfl_xor_sync(0xffffffffu, s, o);
    if ((tid & 31) == 0) shs[tid >> 5] = s;
    __syncthreads();
    if (tid < 32) {
        float v = shs[tid];
#pragma unroll
        for (int o = 16; o; o >>= 1) v += __shfl_xor_sync(0xffffffffu, v, o);
        shs[tid] = v;
    }
    __syncthreads();
    float S = shs[0];
    float e = eps[0];
    float inv = (1.f - e) / S;
    float add = e / (float)N;
    for (int i = tid; i < N; i += 1024)
        out[i] = __expf(sl[i] - M) * inv + add;
}

// ===================== launch =====================
extern "C" void kernel_launch(void* const* d_in, const int* in_sizes, int n_in,
                              void* d_out, int out_size)
{
    const float* state       = (const float*)d_in[0];
    const int*   rel_tokens  = (const int*)d_in[1];
    const int*   attr_tokens = (const int*)d_in[2];
    const float* table       = (const float*)d_in[3];
    const float* W_emb       = (const float*)d_in[4];
    const float* b_emb       = (const float*)d_in[5];
    const float* W_ih        = (const float*)d_in[6];
    const float* W_hh        = (const float*)d_in[7];
    const float* b_ih        = (const float*)d_in[8];
    const float* b_hh        = (const float*)d_in[9];
    const float* W1          = (const float*)d_in[10];
    const float* b1          = (const float*)d_in[11];
    const float* W2          = (const float*)d_in[12];
    const float* b2          = (const float*)d_in[13];
    const float* W3          = (const float*)d_in[14];
    const float* eps         = (const float*)d_in[16];
    float* out = (float*)d_out;

    __half *p2_table, *p2_Wemb, *p2_Wih, *p2_Whh, *p2_W1, *p2_W2;
    __half *p2_emb, *p2_h1, *p2_gi, *p2_gh2;
    float *p_lpart;
    cudaGetSymbolAddress((void**)&p2_table,  g2_table);
    cudaGetSymbolAddress((void**)&p2_Wemb,   g2_Wemb);
    cudaGetSymbolAddress((void**)&p2_Wih,    g2_Wih);
    cudaGetSymbolAddress((void**)&p2_Whh,    g2_Whh);
    cudaGetSymbolAddress((void**)&p2_W1,     g2_W1);
    cudaGetSymbolAddress((void**)&p2_W2,     g2_W2);
    cudaGetSymbolAddress((void**)&p2_emb,    g2_emb);
    cudaGetSymbolAddress((void**)&p2_h1,     g2_h1);
    cudaGetSymbolAddress((void**)&p2_gi,     g2_gi);
    cudaGetSymbolAddress((void**)&p2_gh2,    g2_gh2);
    cudaGetSymbolAddress((void**)&p_lpart,   g_lpart);

    cudaFuncSetAttribute(gemm_dual,
                         cudaFuncAttributeMaxDynamicSharedMemorySize, SMEM_DYN_H);
    cudaFuncSetAttribute(gemm_dual2,
                         cudaFuncAttributeMaxDynamicSharedMemorySize, SMEM_DYN_H);
    cudaFuncSetAttribute(gemm_logits_rel,
                         cudaFuncAttributeMaxDynamicSharedMemorySize, SMEM_DYN_H);

    // 0. convert all fp32 operands to fp16
    cvt_all<<<CVT_ROWS, 256>>>(table, W_emb, W_ih, W_hh, W1, W2,
                               p2_table, p2_Wemb, p2_Wih, p2_Whh, p2_W1, p2_W2);
    // 1. GEMM1 (emb) + gh1 GEMV packed
    k_gemm1_gemv<<<448, 256, SMEM_DYN64>>>(b_emb, state, W_hh, b_hh);
    // 2. gi_table[V,3H]
    gemm_hmma64<<<dim3(H3 / 64, V / 64), 256, SMEM_DYN64>>>(
        p2_emb, p2_Wih, b_ih, p2_gi, H3);
    // 3. h1_table (fp16 only)
    gru_h1_kernel<<<V, 256>>>(state);
    // 4. gh2_table[V,3H]
    gemm_hmma64<<<dim3(H3 / 64, V / 64), 256, SMEM_DYN64>>>(
        p2_h1, p2_Whh, b_hh, p2_gh2, H3);
    // 5. merged step-2 (rel + attr), all-fp16
    gru_step2_all<<<NREL + NATT, 256>>>(rel_tokens, attr_tokens);
    // 6. DUAL1: gh3 (768) + x1-attr (256)
    gemm_dual<<<1024, 256, SMEM_DYN_H>>>(b_hh, b1);
    // 7. rel step 3 (fp16 h2rel, fp16 gh3)
    gru_step3_kernel<<<NREL, 256>>>(rel_tokens);
    // 8. DUAL2: x1-rel (256, drains first) + logits-attr (256)
    gemm_dual2<<<512, 256, SMEM_DYN_H>>>(b1, b2, W3, p_lpart);
    // 9. logits-rel (256)
    gemm_logits_rel<<<dim3(8, NREL / 128), 256, SMEM_DYN_H>>>(b2, W3, p_lpart);
    // 10. logits reduce + softmax + smoothing
    softmax_kernel<<<1, 1024>>>(eps, out);
}

// round 11
// speedup vs baseline: 6.8705x; 1.0675x over previous
#include <cuda_runtime.h>
#include <cuda_fp16.h>
#include <math.h>
#include <stdint.h>

#define H    1024
#define H3   3072
#define NREL 4096
#define NATT 4096
#define NCL  8192
#define V    256

// ===================== scratch (device globals; no allocations) =====================
__device__ __align__(256) __half g2_table[V * H];
__device__ __align__(256) __half g2_Wemb[H * H];
__device__ __align__(256) __half g2_Wih[H3 * H];
__device__ __align__(256) __half g2_Whh[H3 * H];
__device__ __align__(256) __half g2_W1[H * H];
__device__ __align__(256) __half g2_W2[H * H];
__device__ __align__(256) __half g2_emb[V * H];
__device__ __align__(256) __half g2_h1[V * H];
__device__ __align__(256) __half g2_h2rel[NREL * H];
__device__ __align__(256) __half g2_clause[NCL * H];
__device__ __align__(256) __half g2_x1[NCL * H];
__device__ __align__(256) __half g2_gi[V * H3];
__device__ __align__(256) __half g2_gh2[V * H3];
__device__ __align__(256) __half g2_gh3[NREL * H3];
__device__ float g_gh1[H3];
__device__ float g_lpart[NCL * 16];

// ===================== PTX helpers =====================
__device__ __forceinline__ uint32_t smem_u32(const void* p) {
    uint32_t a;
    asm("{ .reg .u64 t; cvta.to.shared.u64 t, %1; cvt.u32.u64 %0, t; }" : "=r"(a) : "l"(p));
    return a;
}
__device__ __forceinline__ void cp16(uint32_t dst, const void* src) {
    asm volatile("cp.async.cg.shared.global [%0], [%1], 16;" :: "r"(dst), "l"(src));
}
__device__ __forceinline__ void cp_commit() {
    asm volatile("cp.async.commit_group;" ::: "memory");
}
template <int N>
__device__ __forceinline__ void cp_wait() {
    asm volatile("cp.async.wait_group %0;" :: "n"(N) : "memory");
}
__device__ __forceinline__ void ldm_x4(uint32_t& r0, uint32_t& r1, uint32_t& r2, uint32_t& r3,
                                       uint32_t addr) {
    asm volatile("ldmatrix.sync.aligned.m8n8.x4.shared.b16 {%0,%1,%2,%3}, [%4];"
                 : "=r"(r0), "=r"(r1), "=r"(r2), "=r"(r3) : "r"(addr));
}
__device__ __forceinline__ void mma16816(float* c, uint32_t a0, uint32_t a1, uint32_t a2,
                                         uint32_t a3, uint32_t b0, uint32_t b1) {
    asm volatile(
        "mma.sync.aligned.m16n8k16.row.col.f32.f16.f16.f32 "
        "{%0,%1,%2,%3}, {%4,%5,%6,%7}, {%8,%9}, {%0,%1,%2,%3};"
        : "+f"(c[0]), "+f"(c[1]), "+f"(c[2]), "+f"(c[3])
        : "r"(a0), "r"(a1), "r"(a2), "r"(a3), "r"(b0), "r"(b1));
}
__device__ __forceinline__ float tanh_fast(float x) {
    float y;
    asm("tanh.approx.f32 %0, %1;" : "=f"(y) : "f"(x));
    return y;
}

#define APITCH   80
#define NIT      32

// ===================== shared 128x128 fp16 HMMA body ====================
#define ATILE_B  (128 * APITCH)
#define STAGE_B  (2 * ATILE_B)
#define SMEM_DYN_H (4 * STAGE_B)        // 81920

__device__ __forceinline__ void cp_stage(const __half* __restrict__ A,
                                         const __half* __restrict__ B,
                                         int bm, int bn, uint32_t sbase, int tid,
                                         int it)
{
    const int kk = it * 32;
#pragma unroll
    for (int h = 0; h < 2; h++) {
        int c = tid + h * 256;
        int row = c >> 2, kc = c & 3;
        cp16(sbase + row * APITCH + kc * 16,
             A + (size_t)(bm + row) * H + kk + kc * 8);
    }
#pragma unroll
    for (int h = 0; h < 2; h++) {
        int c = tid + h * 256;
        int row = c >> 2, kc = c & 3;
        cp16(sbase + ATILE_B + row * APITCH + kc * 16,
             B + (size_t)(bn + row) * H + kk + kc * 8);
    }
}

template <bool RELU, bool OUTS, bool LOGITS>
__device__ __forceinline__ void body128(
    const __half* __restrict__ A, const __half* __restrict__ B,
    const float* __restrict__ bias, __half* __restrict__ Cs, int N,
    int bm, int bn,
    const float* __restrict__ w3, float* __restrict__ lpart, int bxLog,
    uint32_t sbase, int tid)
{
    const int lane = tid & 31, w = tid >> 5;
    const int wm = w & 3, wn = w >> 2;

#pragma unroll
    for (int s = 0; s < 3; s++) {
        cp_stage(A, B, bm, bn, sbase + s * STAGE_B, tid, s);
        cp_commit();
    }

    float acc[2][8][4];
#pragma unroll
    for (int mb = 0; mb < 2; mb++)
#pragma unroll
        for (int nb = 0; nb < 8; nb++)
#pragma unroll
            for (int q = 0; q < 4; q++) acc[mb][nb][q] = 0.f;

    const int quad = lane >> 3, li = lane & 7;
    const uint32_t aAddr = sbase +
        (uint32_t)((wm * 32 + (quad & 1) * 8 + li) * APITCH + (quad >> 1) * 16);
    const uint32_t bAddr = sbase + ATILE_B +
        (uint32_t)((wn * 64 + (quad >> 1) * 8 + li) * APITCH + (quad & 1) * 16);

#pragma unroll 4
    for (int i = 0; i < NIT; i++) {
        cp_wait<2>();
        __syncthreads();
        if (i + 3 < NIT)
            cp_stage(A, B, bm, bn, sbase + ((i + 3) & 3) * STAGE_B, tid, i + 3);
        cp_commit();

        const uint32_t sa = aAddr + (i & 3) * STAGE_B;
        const uint32_t sb = bAddr + (i & 3) * STAGE_B;
#pragma unroll
        for (int kh = 0; kh < 2; kh++) {
            uint32_t a[2][4];
            ldm_x4(a[0][0], a[0][1], a[0][2], a[0][3], sa + kh * 32);
            ldm_x4(a[1][0], a[1][1], a[1][2], a[1][3], sa + kh * 32 + 16 * APITCH);
            uint32_t b[8][2];
#pragma unroll
            for (int n2 = 0; n2 < 4; n2++)
                ldm_x4(b[2 * n2][0], b[2 * n2][1], b[2 * n2 + 1][0], b[2 * n2 + 1][1],
                       sb + kh * 32 + n2 * 16 * APITCH);
#pragma unroll
            for (int mb = 0; mb < 2; mb++)
#pragma unroll
                for (int nb = 0; nb < 8; nb++)
                    mma16816(acc[mb][nb], a[mb][0], a[mb][1], a[mb][2], a[mb][3],
                             b[nb][0], b[nb][1]);
        }
    }

    const int g = lane >> 2, t = lane & 3;
    float lsum[2][2] = {{0.f, 0.f}, {0.f, 0.f}};
#pragma unroll
    for (int mb = 0; mb < 2; mb++) {
        const int r0 = bm + wm * 32 + mb * 16 + g;
#pragma unroll
        for (int nb = 0; nb < 8; nb++) {
            const int col = bn + wn * 64 + nb * 8 + t * 2;
            const float b0 = bias[col], b1 = bias[col + 1];
            float v00 = acc[mb][nb][0] + b0, v01 = acc[mb][nb][1] + b1;
            float v10 = acc[mb][nb][2] + b0, v11 = acc[mb][nb][3] + b1;
            if (RELU) {
                v00 = fmaxf(v00, 0.f); v01 = fmaxf(v01, 0.f);
                v10 = fmaxf(v10, 0.f); v11 = fmaxf(v11, 0.f);
            }
            if (OUTS) {
                *(__half2*)(Cs + (size_t)r0 * N + col) =
                    __halves2half2(__float2half(v00), __float2half(v01));
                *(__half2*)(Cs + (size_t)(r0 + 8) * N + col) =
                    __halves2half2(__float2half(v10), __float2half(v11));
            }
            if (LOGITS) {
                const float w0 = w3[col], w1 = w3[col + 1];
                lsum[mb][0] = fmaf(v00, w0, fmaf(v01, w1, lsum[mb][0]));
                lsum[mb][1] = fmaf(v10, w0, fmaf(v11, w1, lsum[mb][1]));
            }
        }
    }
    if (LOGITS) {
#pragma unroll
        for (int mb = 0; mb < 2; mb++)
#pragma unroll
            for (int rr = 0; rr < 2; rr++) {
                float s = lsum[mb][rr];
                s += __shfl_xor_sync(0xffffffffu, s, 1);
                s += __shfl_xor_sync(0xffffffffu, s, 2);
                if (t == 0) {
                    int row = bm + wm * 32 + mb * 16 + g + rr * 8;
                    lpart[(size_t)row * 16 + bxLog * 2 + wn] = s;
                }
            }
    }
}

// DUAL 1: GEMM8 (gh3, 768 CTAs) + GEMM10-attr (x1 attr half, 256 CTAs)
__global__ void __launch_bounds__(256, 2)
gemm_dual(const float* __restrict__ b_hh, const float* __restrict__ b1)
{
    extern __shared__ char sm[];
    const uint32_t sbase = smem_u32(sm);
    const int tid = threadIdx.x, blk = blockIdx.x;
    if (blk < 768) {
        body128<false, true, false>(g2_h2rel, g2_Whh, b_hh, g2_gh3, H3,
                                    (blk / 24) * 128, (blk % 24) * 128,
                                    nullptr, nullptr, 0, sbase, tid);
    } else {
        int t = blk - 768;
        body128<true, true, false>(g2_clause, g2_W1, b1, g2_x1, H,
                                   NREL + (t >> 3) * 128, (t & 7) * 128,
                                   nullptr, nullptr, 0, sbase, tid);
    }
}

// DUAL 2: GEMM10-rel (256, drains first) + GEMM11-attr (logits, 256)
__global__ void __launch_bounds__(256, 2)
gemm_dual2(const float* __restrict__ b1, const float* __restrict__ b2,
           const float* __restrict__ w3, float* __restrict__ lpart)
{
    extern __shared__ char sm[];
    const uint32_t sbase = smem_u32(sm);
    const int tid = threadIdx.x, blk = blockIdx.x;
    if (blk < 256) {
        body128<true, true, false>(g2_clause, g2_W1, b1, g2_x1, H,
                                   (blk >> 3) * 128, (blk & 7) * 128,
                                   nullptr, nullptr, 0, sbase, tid);
    } else {
        int t = blk - 256;
        body128<true, false, true>(g2_x1, g2_W2, b2, nullptr, H,
                                   NREL + (t >> 3) * 128, (t & 7) * 128,
                                   w3, lpart, t & 7, sbase, tid);
    }
}

// GEMM11-rel (logits partials for rel rows, 256 CTAs)
__global__ void __launch_bounds__(256, 2)
gemm_logits_rel(const float* __restrict__ b2, const float* __restrict__ w3,
                float* __restrict__ lpart)
{
    extern __shared__ char sm[];
    body128<true, false, true>(g2_x1, g2_W2, b2, nullptr, H,
                               blockIdx.y * 128, blockIdx.x * 128,
                               w3, lpart, blockIdx.x, smem_u32(sm), threadIdx.x);
}

// ===================== 64x64 fp16 HMMA GEMM ==============
#define ATILE64_B (64 * APITCH)
#define STAGE64_B (2 * ATILE64_B)
#define SMEM_DYN64 (4 * STAGE64_B)       // 40960

__device__ __forceinline__ void cp_stage64(const __half* __restrict__ A,
                                           const __half* __restrict__ B,
                                           int bm, int bn, uint32_t sbase, int tid,
                                           int it)
{
    const int kk = it * 32;
    int row = tid >> 2, kc = tid & 3;
    cp16(sbase + row * APITCH + kc * 16,
         A + (size_t)(bm + row) * H + kk + kc * 8);
    cp16(sbase + ATILE64_B + row * APITCH + kc * 16,
         B + (size_t)(bn + row) * H + kk + kc * 8);
}

__device__ __forceinline__ void gemm64_body(
    const __half* __restrict__ A, const __half* __restrict__ B,
    const float* __restrict__ bias, __half* __restrict__ Cs, int N,
    int bm, int bn, uint32_t sbase, int tid)
{
    const int lane = tid & 31, w = tid >> 5;
    const int wm = w & 1, wn = w >> 1;

#pragma unroll
    for (int s = 0; s < 3; s++) {
        cp_stage64(A, B, bm, bn, sbase + s * STAGE64_B, tid, s);
        cp_commit();
    }

    float acc[2][2][4];
#pragma unroll
    for (int mb = 0; mb < 2; mb++)
#pragma unroll
        for (int nb = 0; nb < 2; nb++)
#pragma unroll
            for (int q = 0; q < 4; q++) acc[mb][nb][q] = 0.f;

    const int quad = lane >> 3, li = lane & 7;
    const uint32_t aAddr = sbase +
        (uint32_t)((wm * 32 + (quad & 1) * 8 + li) * APITCH + (quad >> 1) * 16);
    const uint32_t bAddr = sbase + ATILE64_B +
        (uint32_t)((wn * 16 + (quad >> 1) * 8 + li) * APITCH + (quad & 1) * 16);

#pragma unroll 4
    for (int i = 0; i < NIT; i++) {
        cp_wait<2>();
        __syncthreads();
        if (i + 3 < NIT)
            cp_stage64(A, B, bm, bn, sbase + ((i + 3) & 3) * STAGE64_B, tid, i + 3);
        cp_commit();

        const uint32_t sa = aAddr + (i & 3) * STAGE64_B;
        const uint32_t sb = bAddr + (i & 3) * STAGE64_B;
#pragma unroll
        for (int kh = 0; kh < 2; kh++) {
            uint32_t a[2][4];
            ldm_x4(a[0][0], a[0][1], a[0][2], a[0][3], sa + kh * 32);
            ldm_x4(a[1][0], a[1][1], a[1][2], a[1][3], sa + kh * 32 + 16 * APITCH);
            uint32_t b[2][2];
            ldm_x4(b[0][0], b[0][1], b[1][0], b[1][1], sb + kh * 32);
#pragma unroll
            for (int mb = 0; mb < 2; mb++)
#pragma unroll
                for (int nb = 0; nb < 2; nb++)
                    mma16816(acc[mb][nb], a[mb][0], a[mb][1], a[mb][2], a[mb][3],
                             b[nb][0], b[nb][1]);
        }
    }

    const int g = lane >> 2, t = lane & 3;
#pragma unroll
    for (int mb = 0; mb < 2; mb++) {
        const int r0 = bm + wm * 32 + mb * 16 + g;
#pragma unroll
        for (int nb = 0; nb < 2; nb++) {
            const int col = bn + wn * 16 + nb * 8 + t * 2;
            const float b0 = bias[col], b1 = bias[col + 1];
            *(__half2*)(Cs + (size_t)r0 * N + col) = __halves2half2(
                __float2half(acc[mb][nb][0] + b0), __float2half(acc[mb][nb][1] + b1));
            *(__half2*)(Cs + (size_t)(r0 + 8) * N + col) = __halves2half2(
                __float2half(acc[mb][nb][2] + b0), __float2half(acc[mb][nb][3] + b1));
        }
    }
}

__global__ void __launch_bounds__(256, 2)
gemm_hmma64(const __half* __restrict__ A, const __half* __restrict__ B,
            const float* __restrict__ bias, __half* __restrict__ Cs, int N)
{
    extern __shared__ char sm[];
    gemm64_body(A, B, bias, Cs, N,
                blockIdx.y * 64, blockIdx.x * 64, smem_u32(sm), threadIdx.x);
}

// ===================== cvt_all + gh1 GEMV packed (both smem-free) =====================
#define CVT_ROWS (256 + 1024 + 3072 + 3072 + 1024 + 1024)   // 9472
__global__ void __launch_bounds__(256)
cvt_all(const float* __restrict__ s0, const float* __restrict__ s1,
        const float* __restrict__ s2, const float* __restrict__ s3,
        const float* __restrict__ s4, const float* __restrict__ s5,
        __half* __restrict__ d0, __half* __restrict__ d1,
        __half* __restrict__ d2, __half* __restrict__ d3,
        __half* __restrict__ d4, __half* __restrict__ d5,
        const float* __restrict__ state, const float* __restrict__ b_hh)
{
    int row = blockIdx.x;
    if (row >= CVT_ROWS) {           // gh1 GEMV: 384 blocks x 8 warps
        int n = (row - CVT_ROWS) * 8 + (threadIdx.x >> 5);
        int lane = threadIdx.x & 31;
        const float* w = s3 + (size_t)n * H;   // s3 == W_hh (fp32)
        float s = 0.f;
#pragma unroll
        for (int k = lane * 4; k < H; k += 128) {
            float4 wv = *(const float4*)(w + k);
            float4 xv = *(const float4*)(state + k);
            s = fmaf(wv.x, xv.x, s); s = fmaf(wv.y, xv.y, s);
            s = fmaf(wv.z, xv.z, s); s = fmaf(wv.w, xv.w, s);
        }
#pragma unroll
        for (int o = 16; o; o >>= 1) s += __shfl_xor_sync(0xffffffffu, s, o);
        if (lane == 0) g_gh1[n] = s + b_hh[n];
        return;
    }
    const float* src; __half* dst; int r = row;
    if      (r < 256)        { src = s0; dst = d0; }
    else if ((r -= 256)  < 1024) { src = s1; dst = d1; }
    else if ((r -= 1024) < 3072) { src = s2; dst = d2; }
    else if ((r -= 3072) < 3072) { src = s3; dst = d3; }
    else if ((r -= 3072) < 1024) { src = s4; dst = d4; }
    else     { r -= 1024;      src = s5; dst = d5; }

    int c4 = threadIdx.x * 4;
    float4 x = *(const float4*)(src + (size_t)r * H + c4);
    __half* o = dst + (size_t)r * H + c4;
    *(__half2*)(o)     = __halves2half2(__float2half(x.x), __float2half(x.y));
    *(__half2*)(o + 2) = __halves2half2(__float2half(x.z), __float2half(x.w));
}

// ===================== GRU combine =====================
__device__ __forceinline__ float4 ld4h(const __half* p) {
    float2 f0 = __half22float2(*(const __half2*)p);
    float2 f1 = __half22float2(*(const __half2*)(p + 2));
    return make_float4(f0.x, f0.y, f1.x, f1.y);
}
__device__ __forceinline__ float gru1(float ir, float iz, float inn,
                                      float hr, float hz, float hn, float h)
{
    float r = 1.f / (1.f + __expf(-(ir + hr)));
    float z = 1.f / (1.f + __expf(-(iz + hz)));
    float n = tanh_fast(fmaf(r, hn, inn));
    return fmaf(z, h - n, n);
}
__device__ __forceinline__ float4 gru4_comb(float4 ir, float4 iz, float4 inn,
                                            float4 hr, float4 hz, float4 hn, float4 hv)
{
    float4 o;
    o.x = gru1(ir.x, iz.x, inn.x, hr.x, hz.x, hn.x, hv.x);
    o.y = gru1(ir.y, iz.y, inn.y, hr.y, hz.y, hn.y, hv.y);
    o.z = gru1(ir.z, iz.z, inn.z, hr.z, hz.z, hn.z, hv.z);
    o.w = gru1(ir.w, iz.w, inn.w, hr.w, hz.w, hn.w, hv.w);
    return o;
}
__device__ __forceinline__ void cvt_store(__half* o, float4 v)
{
    *(__half2*)(o)     = __halves2half2(__float2half(v.x), __float2half(v.y));
    *(__half2*)(o + 2) = __halves2half2(__float2half(v.z), __float2half(v.w));
}

__global__ void gru_h1_kernel(const float* __restrict__ state)
{
    int v = blockIdx.x;
    int j = threadIdx.x * 4;
    const __half* gi = g2_gi + (size_t)v * H3;
    float4 o = gru4_comb(ld4h(gi + j), ld4h(gi + H + j), ld4h(gi + 2 * H + j),
                         *(const float4*)(g_gh1 + j),
                         *(const float4*)(g_gh1 + H + j),
                         *(const float4*)(g_gh1 + 2 * H + j),
                         *(const float4*)(state + j));
    cvt_store(g2_h1 + (size_t)v * H + j, o);
}

__device__ __forceinline__ float4 gru4_hhh(const __half* gi, const __half* gh,
                                           const __half* h, int j)
{
    return gru4_comb(ld4h(gi + j), ld4h(gi + H + j), ld4h(gi + 2 * H + j),
                     ld4h(gh + j), ld4h(gh + H + j), ld4h(gh + 2 * H + j),
                     ld4h(h + j));
}

__global__ void gru_step2_all(const int* __restrict__ rel_tokens,
                              const int* __restrict__ attr_tokens)
{
    int blk = blockIdx.x;
    int j = threadIdx.x * 4;
    if (blk < NREL) {
        int t0 = rel_tokens[blk * 3 + 0];
        int t1 = rel_tokens[blk * 3 + 1];
        float4 o = gru4_hhh(g2_gi + (size_t)t1 * H3, g2_gh2 + (size_t)t0 * H3,
                            g2_h1 + (size_t)t0 * H, j);
        cvt_store(g2_h2rel + (size_t)blk * H + j, o);
    } else {
        int n = blk - NREL;
        int t0 = attr_tokens[n * 2 + 0];
        int t1 = attr_tokens[n * 2 + 1];
        float4 o = gru4_hhh(g2_gi + (size_t)t1 * H3, g2_gh2 + (size_t)t0 * H3,
                            g2_h1 + (size_t)t0 * H, j);
        cvt_store(g2_clause + (size_t)(NREL + n) * H + j, o);
    }
}

__global__ void gru_step3_kernel(const int* __restrict__ rel_tokens)
{
    int n  = blockIdx.x;
    int t2 = rel_tokens[n * 3 + 2];
    int j  = threadIdx.x * 4;
    float4 o = gru4_hhh(g2_gi + (size_t)t2 * H3, g2_gh3 + (size_t)n * H3,
                        g2_h2rel + (size_t)n * H, j);
    cvt_store(g2_clause + (size_t)n * H + j, o);
}

// ===================== logits reduce + softmax + eps smoothing =====================
__global__ void softmax_kernel(const float* __restrict__ eps, float* __restrict__ out)
{
    const int N = NCL;
    __shared__ float sl[NCL];
    __shared__ float shm[32], shs[32];
    int tid = threadIdx.x;

    for (int i = tid; i < N; i += 1024) {
        const float4* p = (const float4*)(g_lpart + (size_t)i * 16);
        float4 a = p[0], b = p[1], c = p[2], d = p[3];
        sl[i] = ((a.x + a.y) + (a.z + a.w)) + ((b.x + b.y) + (b.z + b.w))
              + ((c.x + c.y) + (c.z + c.w)) + ((d.x + d.y) + (d.z + d.w));
    }
    __syncthreads();

    float m = -1e30f;
    for (int i = tid; i < N; i += 1024) m = fmaxf(m, sl[i]);
#pragma unroll
    for (int o = 16; o; o >>= 1) m = fmaxf(m, __shfl_xor_sync(0xffffffffu, m, o));
    if ((tid & 31) == 0) shm[tid >> 5] = m;
    __syncthreads();
    if (tid < 32) {
        float v = shm[tid];
#pragma unroll
        for (int o = 16; o; o >>= 1) v = fmaxf(v, __shfl_xor_sync(0xffffffffu, v, o));
        shm[tid] = v;
    }
    __syncthreads();
    float M = shm[0];

    float s = 0.f;
    for (int i = tid; i < N; i += 1024) s += __expf(sl[i] - M);
#pragma unroll
    for (int o = 16; o; o >>= 1) s += __shfl_xor_sync(0xffffffffu, s, o);
    if ((tid & 31) == 0) shs[tid >> 5] = s;
    __syncthreads();
    if (tid < 32) {
        float v = shs[tid];
#pragma unroll
        for (int o = 16; o; o >>= 1) v += __shfl_xor_sync(0xffffffffu, v, o);
        shs[tid] = v;
    }
    __syncthreads();
    float S = shs[0];
    float e = eps[0];
    float inv = (1.f - e) / S;
    float add = e / (float)N;
    for (int i = tid; i < N; i += 1024)
        out[i] = __expf(sl[i] - M) * inv + add;
}

// ===================== launch =====================
extern "C" void kernel_launch(void* const* d_in, const int* in_sizes, int n_in,
                              void* d_out, int out_size)
{
    const float* state       = (const float*)d_in[0];
    const int*   rel_tokens  = (const int*)d_in[1];
    const int*   attr_tokens = (const int*)d_in[2];
    const float* table       = (const float*)d_in[3];
    const float* W_emb       = (const float*)d_in[4];
    const float* b_emb       = (const float*)d_in[5];
    const float* W_ih        = (const float*)d_in[6];
    const float* W_hh        = (const float*)d_in[7];
    const float* b_ih        = (const float*)d_in[8];
    const float* b_hh        = (const float*)d_in[9];
    const float* W1          = (const float*)d_in[10];
    const float* b1          = (const float*)d_in[11];
    const float* W2          = (const float*)d_in[12];
    const float* b2          = (const float*)d_in[13];
    const float* W3          = (const float*)d_in[14];
    const float* eps         = (const float*)d_in[16];
    float* out = (float*)d_out;

    __half *p2_table, *p2_Wemb, *p2_Wih, *p2_Whh, *p2_W1, *p2_W2;
    __half *p2_emb, *p2_h1, *p2_gi, *p2_gh2;
    float *p_lpart;
    cudaGetSymbolAddress((void**)&p2_table,  g2_table);
    cudaGetSymbolAddress((void**)&p2_Wemb,   g2_Wemb);
    cudaGetSymbolAddress((void**)&p2_Wih,    g2_Wih);
    cudaGetSymbolAddress((void**)&p2_Whh,    g2_Whh);
    cudaGetSymbolAddress((void**)&p2_W1,     g2_W1);
    cudaGetSymbolAddress((void**)&p2_W2,     g2_W2);
    cudaGetSymbolAddress((void**)&p2_emb,    g2_emb);
    cudaGetSymbolAddress((void**)&p2_h1,     g2_h1);
    cudaGetSymbolAddress((void**)&p2_gi,     g2_gi);
    cudaGetSymbolAddress((void**)&p2_gh2,    g2_gh2);
    cudaGetSymbolAddress((void**)&p_lpart,   g_lpart);

    cudaFuncSetAttribute(gemm_dual,
                         cudaFuncAttributeMaxDynamicSharedMemorySize, SMEM_DYN_H);
    cudaFuncSetAttribute(gemm_dual2,
                         cudaFuncAttributeMaxDynamicSharedMemorySize, SMEM_DYN_H);
    cudaFuncSetAttribute(gemm_logits_rel,
                         cudaFuncAttributeMaxDynamicSharedMemorySize, SMEM_DYN_H);

    // 0. convert fp32 operands + gh1 GEMV packed (W_hh fp32 read is cvt-independent)
    cvt_all<<<CVT_ROWS + 384, 256>>>(table, W_emb, W_ih, W_hh, W1, W2,
                                     p2_table, p2_Wemb, p2_Wih, p2_Whh, p2_W1, p2_W2,
                                     state, b_hh);
    // 1. GEMM1: emb = table @ Wemb^T + b_emb
    gemm_hmma64<<<dim3(H / 64, V / 64), 256, SMEM_DYN64>>>(
        p2_table, p2_Wemb, b_emb, p2_emb, H);
    // 2. gi_table[V,3H]
    gemm_hmma64<<<dim3(H3 / 64, V / 64), 256, SMEM_DYN64>>>(
        p2_emb, p2_Wih, b_ih, p2_gi, H3);
    // 3. h1_table (fp16 only)
    gru_h1_kernel<<<V, 256>>>(state);
    // 4. gh2_table[V,3H]
    gemm_hmma64<<<dim3(H3 / 64, V / 64), 256, SMEM_DYN64>>>(
        p2_h1, p2_Whh, b_hh, p2_gh2, H3);
    // 5. merged step-2 (rel + attr), all-fp16
    gru_step2_all<<<NREL + NATT, 256>>>(rel_tokens, attr_tokens);
    // 6. DUAL1: gh3 (768) + x1-attr (256)
    gemm_dual<<<1024, 256, SMEM_DYN_H>>>(b_hh, b1);
    // 7. rel step 3
    gru_step3_kernel<<<NREL, 256>>>(rel_tokens);
    // 8. DUAL2: x1-rel (256, drains first) + logits-attr (256)
    gemm_dual2<<<512, 256, SMEM_DYN_H>>>(b1, b2, W3, p_lpart);
    // 9. logits-rel (256)
    gemm_logits_rel<<<dim3(8, NREL / 128), 256, SMEM_DYN_H>>>(b2, W3, p_lpart);
    // 10. logits reduce + softmax + smoothing
    softmax_kernel<<<1, 1024>>>(eps, out);
}

// round 12
// speedup vs baseline: 6.9160x; 1.0066x over previous
#include <cuda_runtime.h>
#include <cuda_fp16.h>
#include <math.h>
#include <stdint.h>

#define H    1024
#define H3   3072
#define NREL 4096
#define NATT 4096
#define NCL  8192
#define V    256

// ===================== scratch (device globals; no allocations) =====================
__device__ __align__(256) __half g2_table[V * H];
__device__ __align__(256) __half g2_Wemb[H * H];
__device__ __align__(256) __half g2_Wih[H3 * H];
__device__ __align__(256) __half g2_Whh[H3 * H];
__device__ __align__(256) __half g2_W1[H * H];
__device__ __align__(256) __half g2_W2[H * H];
__device__ __align__(256) __half g2_emb[V * H];
__device__ __align__(256) __half g2_h1[V * H];
__device__ __align__(256) __half g2_h2rel[NREL * H];
__device__ __align__(256) __half g2_clause[NCL * H];
__device__ __align__(256) __half g2_x1[NCL * H];
__device__ __align__(256) __half g2_gi[V * H3];
__device__ __align__(256) __half g2_gh2[V * H3];
__device__ __align__(256) __half g2_gh3[NREL * H3];
__device__ float g_gh1[H3];
__device__ float g_lpart[NCL * 16];

// ===================== PTX helpers =====================
__device__ __forceinline__ uint32_t smem_u32(const void* p) {
    uint32_t a;
    asm("{ .reg .u64 t; cvta.to.shared.u64 t, %1; cvt.u32.u64 %0, t; }" : "=r"(a) : "l"(p));
    return a;
}
__device__ __forceinline__ void cp16(uint32_t dst, const void* src) {
    asm volatile("cp.async.cg.shared.global [%0], [%1], 16;" :: "r"(dst), "l"(src));
}
__device__ __forceinline__ void cp_commit() {
    asm volatile("cp.async.commit_group;" ::: "memory");
}
template <int N>
__device__ __forceinline__ void cp_wait() {
    asm volatile("cp.async.wait_group %0;" :: "n"(N) : "memory");
}
__device__ __forceinline__ void ldm_x4(uint32_t& r0, uint32_t& r1, uint32_t& r2, uint32_t& r3,
                                       uint32_t addr) {
    asm volatile("ldmatrix.sync.aligned.m8n8.x4.shared.b16 {%0,%1,%2,%3}, [%4];"
                 : "=r"(r0), "=r"(r1), "=r"(r2), "=r"(r3) : "r"(addr));
}
__device__ __forceinline__ void mma16816(float* c, uint32_t a0, uint32_t a1, uint32_t a2,
                                         uint32_t a3, uint32_t b0, uint32_t b1) {
    asm volatile(
        "mma.sync.aligned.m16n8k16.row.col.f32.f16.f16.f32 "
        "{%0,%1,%2,%3}, {%4,%5,%6,%7}, {%8,%9}, {%0,%1,%2,%3};"
        : "+f"(c[0]), "+f"(c[1]), "+f"(c[2]), "+f"(c[3])
        : "r"(a0), "r"(a1), "r"(a2), "r"(a3), "r"(b0), "r"(b1));
}
__device__ __forceinline__ float tanh_fast(float x) {
    float y;
    asm("tanh.approx.f32 %0, %1;" : "=f"(y) : "f"(x));
    return y;
}

// fp32 row -> fp16 row (256 threads, 4 elems each)
__device__ __forceinline__ void cvt_row(const float* __restrict__ src,
                                        __half* __restrict__ dst, int r, int tid)
{
    int c4 = tid * 4;
    float4 x = *(const float4*)(src + (size_t)r * H + c4);
    __half* o = dst + (size_t)r * H + c4;
    *(__half2*)(o)     = __halves2half2(__float2half(x.x), __float2half(x.y));
    *(__half2*)(o + 2) = __halves2half2(__float2half(x.z), __float2half(x.w));
}

#define APITCH   80
#define NIT      32

// ===================== shared 128x128 fp16 HMMA body ====================
#define ATILE_B  (128 * APITCH)
#define STAGE_B  (2 * ATILE_B)
#define SMEM_DYN_H (4 * STAGE_B)        // 81920

__device__ __forceinline__ void cp_stage(const __half* __restrict__ A,
                                         const __half* __restrict__ B,
                                         int bm, int bn, uint32_t sbase, int tid,
                                         int it)
{
    const int kk = it * 32;
#pragma unroll
    for (int h = 0; h < 2; h++) {
        int c = tid + h * 256;
        int row = c >> 2, kc = c & 3;
        cp16(sbase + row * APITCH + kc * 16,
             A + (size_t)(bm + row) * H + kk + kc * 8);
    }
#pragma unroll
    for (int h = 0; h < 2; h++) {
        int c = tid + h * 256;
        int row = c >> 2, kc = c & 3;
        cp16(sbase + ATILE_B + row * APITCH + kc * 16,
             B + (size_t)(bn + row) * H + kk + kc * 8);
    }
}

template <bool RELU, bool OUTS, bool LOGITS>
__device__ __forceinline__ void body128(
    const __half* __restrict__ A, const __half* __restrict__ B,
    const float* __restrict__ bias, __half* __restrict__ Cs, int N,
    int bm, int bn,
    const float* __restrict__ w3, float* __restrict__ lpart, int bxLog,
    uint32_t sbase, int tid)
{
    const int lane = tid & 31, w = tid >> 5;
    const int wm = w & 3, wn = w >> 2;

#pragma unroll
    for (int s = 0; s < 3; s++) {
        cp_stage(A, B, bm, bn, sbase + s * STAGE_B, tid, s);
        cp_commit();
    }

    float acc[2][8][4];
#pragma unroll
    for (int mb = 0; mb < 2; mb++)
#pragma unroll
        for (int nb = 0; nb < 8; nb++)
#pragma unroll
            for (int q = 0; q < 4; q++) acc[mb][nb][q] = 0.f;

    const int quad = lane >> 3, li = lane & 7;
    const uint32_t aAddr = sbase +
        (uint32_t)((wm * 32 + (quad & 1) * 8 + li) * APITCH + (quad >> 1) * 16);
    const uint32_t bAddr = sbase + ATILE_B +
        (uint32_t)((wn * 64 + (quad >> 1) * 8 + li) * APITCH + (quad & 1) * 16);

#pragma unroll 4
    for (int i = 0; i < NIT; i++) {
        cp_wait<2>();
        __syncthreads();
        if (i + 3 < NIT)
            cp_stage(A, B, bm, bn, sbase + ((i + 3) & 3) * STAGE_B, tid, i + 3);
        cp_commit();

        const uint32_t sa = aAddr + (i & 3) * STAGE_B;
        const uint32_t sb = bAddr + (i & 3) * STAGE_B;
#pragma unroll
        for (int kh = 0; kh < 2; kh++) {
            uint32_t a[2][4];
            ldm_x4(a[0][0], a[0][1], a[0][2], a[0][3], sa + kh * 32);
            ldm_x4(a[1][0], a[1][1], a[1][2], a[1][3], sa + kh * 32 + 16 * APITCH);
            uint32_t b[8][2];
#pragma unroll
            for (int n2 = 0; n2 < 4; n2++)
                ldm_x4(b[2 * n2][0], b[2 * n2][1], b[2 * n2 + 1][0], b[2 * n2 + 1][1],
                       sb + kh * 32 + n2 * 16 * APITCH);
#pragma unroll
            for (int mb = 0; mb < 2; mb++)
#pragma unroll
                for (int nb = 0; nb < 8; nb++)
                    mma16816(acc[mb][nb], a[mb][0], a[mb][1], a[mb][2], a[mb][3],
                             b[nb][0], b[nb][1]);
        }
    }

    const int g = lane >> 2, t = lane & 3;
    float lsum[2][2] = {{0.f, 0.f}, {0.f, 0.f}};
#pragma unroll
    for (int mb = 0; mb < 2; mb++) {
        const int r0 = bm + wm * 32 + mb * 16 + g;
#pragma unroll
        for (int nb = 0; nb < 8; nb++) {
            const int col = bn + wn * 64 + nb * 8 + t * 2;
            const float b0 = bias[col], b1 = bias[col + 1];
            float v00 = acc[mb][nb][0] + b0, v01 = acc[mb][nb][1] + b1;
            float v10 = acc[mb][nb][2] + b0, v11 = acc[mb][nb][3] + b1;
            if (RELU) {
                v00 = fmaxf(v00, 0.f); v01 = fmaxf(v01, 0.f);
                v10 = fmaxf(v10, 0.f); v11 = fmaxf(v11, 0.f);
            }
            if (OUTS) {
                *(__half2*)(Cs + (size_t)r0 * N + col) =
                    __halves2half2(__float2half(v00), __float2half(v01));
                *(__half2*)(Cs + (size_t)(r0 + 8) * N + col) =
                    __halves2half2(__float2half(v10), __float2half(v11));
            }
            if (LOGITS) {
                const float w0 = w3[col], w1 = w3[col + 1];
                lsum[mb][0] = fmaf(v00, w0, fmaf(v01, w1, lsum[mb][0]));
                lsum[mb][1] = fmaf(v10, w0, fmaf(v11, w1, lsum[mb][1]));
            }
        }
    }
    if (LOGITS) {
#pragma unroll
        for (int mb = 0; mb < 2; mb++)
#pragma unroll
            for (int rr = 0; rr < 2; rr++) {
                float s = lsum[mb][rr];
                s += __shfl_xor_sync(0xffffffffu, s, 1);
                s += __shfl_xor_sync(0xffffffffu, s, 2);
                if (t == 0) {
                    int row = bm + wm * 32 + mb * 16 + g + rr * 8;
                    lpart[(size_t)row * 16 + bxLog * 2 + wn] = s;
                }
            }
    }
}

// DUAL 1: GEMM8 (gh3, 768 CTAs) + GEMM10-attr (256 CTAs)
__global__ void __launch_bounds__(256, 2)
gemm_dual(const float* __restrict__ b_hh, const float* __restrict__ b1)
{
    extern __shared__ char sm[];
    const uint32_t sbase = smem_u32(sm);
    const int tid = threadIdx.x, blk = blockIdx.x;
    if (blk < 768) {
        body128<false, true, false>(g2_h2rel, g2_Whh, b_hh, g2_gh3, H3,
                                    (blk / 24) * 128, (blk % 24) * 128,
                                    nullptr, nullptr, 0, sbase, tid);
    } else {
        int t = blk - 768;
        body128<true, true, false>(g2_clause, g2_W1, b1, g2_x1, H,
                                   NREL + (t >> 3) * 128, (t & 7) * 128,
                                   nullptr, nullptr, 0, sbase, tid);
    }
}

// DUAL 2: GEMM10-rel (256, drains first) + GEMM11-attr (logits, 256)
__global__ void __launch_bounds__(256, 2)
gemm_dual2(const float* __restrict__ b1, const float* __restrict__ b2,
           const float* __restrict__ w3, float* __restrict__ lpart)
{
    extern __shared__ char sm[];
    const uint32_t sbase = smem_u32(sm);
    const int tid = threadIdx.x, blk = blockIdx.x;
    if (blk < 256) {
        body128<true, true, false>(g2_clause, g2_W1, b1, g2_x1, H,
                                   (blk >> 3) * 128, (blk & 7) * 128,
                                   nullptr, nullptr, 0, sbase, tid);
    } else {
        int t = blk - 256;
        body128<true, false, true>(g2_x1, g2_W2, b2, nullptr, H,
                                   NREL + (t >> 3) * 128, (t & 7) * 128,
                                   w3, lpart, t & 7, sbase, tid);
    }
}

// GEMM11-rel (logits partials for rel rows, 256 CTAs)
__global__ void __launch_bounds__(256, 2)
gemm_logits_rel(const float* __restrict__ b2, const float* __restrict__ w3,
                float* __restrict__ lpart)
{
    extern __shared__ char sm[];
    body128<true, false, true>(g2_x1, g2_W2, b2, nullptr, H,
                               blockIdx.y * 128, blockIdx.x * 128,
                               w3, lpart, blockIdx.x, smem_u32(sm), threadIdx.x);
}

// ===================== 64x64 fp16 HMMA GEMM ==============
#define ATILE64_B (64 * APITCH)
#define STAGE64_B (2 * ATILE64_B)
#define SMEM_DYN64 (4 * STAGE64_B)       // 40960

__device__ __forceinline__ void cp_stage64(const __half* __restrict__ A,
                                           const __half* __restrict__ B,
                                           int bm, int bn, uint32_t sbase, int tid,
                                           int it)
{
    const int kk = it * 32;
    int row = tid >> 2, kc = tid & 3;
    cp16(sbase + row * APITCH + kc * 16,
         A + (size_t)(bm + row) * H + kk + kc * 8);
    cp16(sbase + ATILE64_B + row * APITCH + kc * 16,
         B + (size_t)(bn + row) * H + kk + kc * 8);
}

__device__ __forceinline__ void gemm64_body(
    const __half* __restrict__ A, const __half* __restrict__ B,
    const float* __restrict__ bias, __half* __restrict__ Cs, int N,
    int bm, int bn, uint32_t sbase, int tid)
{
    const int lane = tid & 31, w = tid >> 5;
    const int wm = w & 1, wn = w >> 1;

#pragma unroll
    for (int s = 0; s < 3; s++) {
        cp_stage64(A, B, bm, bn, sbase + s * STAGE64_B, tid, s);
        cp_commit();
    }

    float acc[2][2][4];
#pragma unroll
    for (int mb = 0; mb < 2; mb++)
#pragma unroll
        for (int nb = 0; nb < 2; nb++)
#pragma unroll
            for (int q = 0; q < 4; q++) acc[mb][nb][q] = 0.f;

    const int quad = lane >> 3, li = lane & 7;
    const uint32_t aAddr = sbase +
        (uint32_t)((wm * 32 + (quad & 1) * 8 + li) * APITCH + (quad >> 1) * 16);
    const uint32_t bAddr = sbase + ATILE64_B +
        (uint32_t)((wn * 16 + (quad >> 1) * 8 + li) * APITCH + (quad & 1) * 16);

#pragma unroll 4
    for (int i = 0; i < NIT; i++) {
        cp_wait<2>();
        __syncthreads();
        if (i + 3 < NIT)
            cp_stage64(A, B, bm, bn, sbase + ((i + 3) & 3) * STAGE64_B, tid, i + 3);
        cp_commit();

        const uint32_t sa = aAddr + (i & 3) * STAGE64_B;
        const uint32_t sb = bAddr + (i & 3) * STAGE64_B;
#pragma unroll
        for (int kh = 0; kh < 2; kh++) {
            uint32_t a[2][4];
            ldm_x4(a[0][0], a[0][1], a[0][2], a[0][3], sa + kh * 32);
            ldm_x4(a[1][0], a[1][1], a[1][2], a[1][3], sa + kh * 32 + 16 * APITCH);
            uint32_t b[2][2];
            ldm_x4(b[0][0], b[0][1], b[1][0], b[1][1], sb + kh * 32);
#pragma unroll
            for (int mb = 0; mb < 2; mb++)
#pragma unroll
                for (int nb = 0; nb < 2; nb++)
                    mma16816(acc[mb][nb], a[mb][0], a[mb][1], a[mb][2], a[mb][3],
                             b[nb][0], b[nb][1]);
        }
    }

    const int g = lane >> 2, t = lane & 3;
#pragma unroll
    for (int mb = 0; mb < 2; mb++) {
        const int r0 = bm + wm * 32 + mb * 16 + g;
#pragma unroll
        for (int nb = 0; nb < 2; nb++) {
            const int col = bn + wn * 16 + nb * 8 + t * 2;
            const float b0 = bias[col], b1 = bias[col + 1];
            *(__half2*)(Cs + (size_t)r0 * N + col) = __halves2half2(
                __float2half(acc[mb][nb][0] + b0), __float2half(acc[mb][nb][1] + b1));
            *(__half2*)(Cs + (size_t)(r0 + 8) * N + col) = __halves2half2(
                __float2half(acc[mb][nb][2] + b0), __float2half(acc[mb][nb][3] + b1));
        }
    }
}

// GEMM1 (64 CTAs) + convert W_hh (3072 rows) packed
__global__ void __launch_bounds__(256, 2)
gemm1_cvtWhh(const float* __restrict__ b_emb, const float* __restrict__ W_hh)
{
    extern __shared__ char sm[];
    const int blk = blockIdx.x, tid = threadIdx.x;
    if (blk < 64) {
        gemm64_body(g2_table, g2_Wemb, b_emb, g2_emb, H,
                    (blk >> 4) * 64, (blk & 15) * 64, smem_u32(sm), tid);
    } else {
        cvt_row(W_hh, g2_Whh, blk - 64, tid);
    }
}

// GEMM2 (192 CTAs) + convert W1, W2 (2048 rows) packed
__global__ void __launch_bounds__(256, 2)
gemm2_cvtW12(const float* __restrict__ b_ih,
             const float* __restrict__ W1, const float* __restrict__ W2)
{
    extern __shared__ char sm[];
    const int blk = blockIdx.x, tid = threadIdx.x;
    if (blk < 192) {        // gi = emb @ Wih^T + b_ih, grid 48 x 4
        gemm64_body(g2_emb, g2_Wih, b_ih, g2_gi, H3,
                    (blk / 48) * 64, (blk % 48) * 64, smem_u32(sm), tid);
    } else if (blk < 192 + 1024) {
        cvt_row(W1, g2_W1, blk - 192, tid);
    } else {
        cvt_row(W2, g2_W2, blk - 192 - 1024, tid);
    }
}

// GEMM4 (gh2, 192 CTAs)
__global__ void __launch_bounds__(256, 2)
gemm_hmma64(const __half* __restrict__ A, const __half* __restrict__ B,
            const float* __restrict__ bias, __half* __restrict__ Cs, int N)
{
    extern __shared__ char sm[];
    gemm64_body(A, B, bias, Cs, N,
                blockIdx.y * 64, blockIdx.x * 64, smem_u32(sm), threadIdx.x);
}

// ===================== launch 0: convert table/Wemb/Wih + gh1 GEMV =====================
#define CVT0_ROWS (256 + 1024 + 3072)   // 4352
__global__ void __launch_bounds__(256)
cvt_phase0(const float* __restrict__ table, const float* __restrict__ W_emb,
           const float* __restrict__ W_ih,
           const float* __restrict__ state, const float* __restrict__ W_hh,
           const float* __restrict__ b_hh)
{
    int row = blockIdx.x;
    int tid = threadIdx.x;
    if (row >= CVT0_ROWS) {          // gh1 GEMV: 384 blocks x 8 warps
        int n = (row - CVT0_ROWS) * 8 + (tid >> 5);
        int lane = tid & 31;
        const float* w = W_hh + (size_t)n * H;
        float s = 0.f;
#pragma unroll
        for (int k = lane * 4; k < H; k += 128) {
            float4 wv = *(const float4*)(w + k);
            float4 xv = *(const float4*)(state + k);
            s = fmaf(wv.x, xv.x, s); s = fmaf(wv.y, xv.y, s);
            s = fmaf(wv.z, xv.z, s); s = fmaf(wv.w, xv.w, s);
        }
#pragma unroll
        for (int o = 16; o; o >>= 1) s += __shfl_xor_sync(0xffffffffu, s, o);
        if (lane == 0) g_gh1[n] = s + b_hh[n];
        return;
    }
    int r = row;
    if      (r < 256)            cvt_row(table, g2_table, r, tid);
    else if ((r -= 256) < 1024)  cvt_row(W_emb, g2_Wemb, r, tid);
    else                          cvt_row(W_ih, g2_Wih, r - 1024, tid);
}

// ===================== GRU combine =====================
__device__ __forceinline__ float4 ld4h(const __half* p) {
    float2 f0 = __half22float2(*(const __half2*)p);
    float2 f1 = __half22float2(*(const __half2*)(p + 2));
    return make_float4(f0.x, f0.y, f1.x, f1.y);
}
__device__ __forceinline__ float gru1(float ir, float iz, float inn,
                                      float hr, float hz, float hn, float h)
{
    float r = 1.f / (1.f + __expf(-(ir + hr)));
    float z = 1.f / (1.f + __expf(-(iz + hz)));
    float n = tanh_fast(fmaf(r, hn, inn));
    return fmaf(z, h - n, n);
}
__device__ __forceinline__ float4 gru4_comb(float4 ir, float4 iz, float4 inn,
                                            float4 hr, float4 hz, float4 hn, float4 hv)
{
    float4 o;
    o.x = gru1(ir.x, iz.x, inn.x, hr.x, hz.x, hn.x, hv.x);
    o.y = gru1(ir.y, iz.y, inn.y, hr.y, hz.y, hn.y, hv.y);
    o.z = gru1(ir.z, iz.z, inn.z, hr.z, hz.z, hn.z, hv.z);
    o.w = gru1(ir.w, iz.w, inn.w, hr.w, hz.w, hn.w, hv.w);
    return o;
}
__device__ __forceinline__ void cvt_store(__half* o, float4 v)
{
    *(__half2*)(o)     = __halves2half2(__float2half(v.x), __float2half(v.y));
    *(__half2*)(o + 2) = __halves2half2(__float2half(v.z), __float2half(v.w));
}

__global__ void gru_h1_kernel(const float* __restrict__ state)
{
    int v = blockIdx.x;
    int j = threadIdx.x * 4;
    const __half* gi = g2_gi + (size_t)v * H3;
    float4 o = gru4_comb(ld4h(gi + j), ld4h(gi + H + j), ld4h(gi + 2 * H + j),
                         *(const float4*)(g_gh1 + j),
                         *(const float4*)(g_gh1 + H + j),
                         *(const float4*)(g_gh1 + 2 * H + j),
                         *(const float4*)(state + j));
    cvt_store(g2_h1 + (size_t)v * H + j, o);
}

__device__ __forceinline__ float4 gru4_hhh(const __half* gi, const __half* gh,
                                           const __half* h, int j)
{
    return gru4_comb(ld4h(gi + j), ld4h(gi + H + j), ld4h(gi + 2 * H + j),
                     ld4h(gh + j), ld4h(gh + H + j), ld4h(gh + 2 * H + j),
                     ld4h(h + j));
}

__global__ void gru_step2_all(const int* __restrict__ rel_tokens,
                              const int* __restrict__ attr_tokens)
{
    int blk = blockIdx.x;
    int j = threadIdx.x * 4;
    if (blk < NREL) {
        int t0 = rel_tokens[blk * 3 + 0];
        int t1 = rel_tokens[blk * 3 + 1];
        float4 o = gru4_hhh(g2_gi + (size_t)t1 * H3, g2_gh2 + (size_t)t0 * H3,
                            g2_h1 + (size_t)t0 * H, j);
        cvt_store(g2_h2rel + (size_t)blk * H + j, o);
    } else {
        int n = blk - NREL;
        int t0 = attr_tokens[n * 2 + 0];
        int t1 = attr_tokens[n * 2 + 1];
        float4 o = gru4_hhh(g2_gi + (size_t)t1 * H3, g2_gh2 + (size_t)t0 * H3,
                            g2_h1 + (size_t)t0 * H, j);
        cvt_store(g2_clause + (size_t)(NREL + n) * H + j, o);
    }
}

__global__ void gru_step3_kernel(const int* __restrict__ rel_tokens)
{
    int n  = blockIdx.x;
    int t2 = rel_tokens[n * 3 + 2];
    int j  = threadIdx.x * 4;
    float4 o = gru4_hhh(g2_gi + (size_t)t2 * H3, g2_gh3 + (size_t)n * H3,
                        g2_h2rel + (size_t)n * H, j);
    cvt_store(g2_clause + (size_t)n * H + j, o);
}

// ===================== logits reduce + softmax + eps smoothing =====================
__global__ void softmax_kernel(const float* __restrict__ eps, float* __restrict__ out)
{
    const int N = NCL;
    __shared__ float sl[NCL];
    __shared__ float shm[32], shs[32];
    int tid = threadIdx.x;

    for (int i = tid; i < N; i += 1024) {
        const float4* p = (const float4*)(g_lpart + (size_t)i * 16);
        float4 a = p[0], b = p[1], c = p[2], d = p[3];
        sl[i] = ((a.x + a.y) + (a.z + a.w)) + ((b.x + b.y) + (b.z + b.w))
              + ((c.x + c.y) + (c.z + c.w)) + ((d.x + d.y) + (d.z + d.w));
    }
    __syncthreads();

    float m = -1e30f;
    for (int i = tid; i < N; i += 1024) m = fmaxf(m, sl[i]);
#pragma unroll
    for (int o = 16; o; o >>= 1) m = fmaxf(m, __shfl_xor_sync(0xffffffffu, m, o));
    if ((tid & 31) == 0) shm[tid >> 5] = m;
    __syncthreads();
    if (tid < 32) {
        float v = shm[tid];
#pragma unroll
        for (int o = 16; o; o >>= 1) v = fmaxf(v, __shfl_xor_sync(0xffffffffu, v, o));
        shm[tid] = v;
    }
    __syncthreads();
    float M = shm[0];

    float s = 0.f;
    for (int i = tid; i < N; i += 1024) s += __expf(sl[i] - M);
#pragma unroll
    for (int o = 16; o; o >>= 1) s += __shfl_xor_sync(0xffffffffu, s, o);
    if ((tid & 31) == 0) shs[tid >> 5] = s;
    __syncthreads();
    if (tid < 32) {
        float v = shs[tid];
#pragma unroll
        for (int o = 16; o; o >>= 1) v += __shfl_xor_sync(0xffffffffu, v, o);
        shs[tid] = v;
    }
    __syncthreads();
    float S = shs[0];
    float e = eps[0];
    float inv = (1.f - e) / S;
    float add = e / (float)N;
    for (int i = tid; i < N; i += 1024)
        out[i] = __expf(sl[i] - M) * inv + add;
}

// ===================== launch =====================
extern "C" void kernel_launch(void* const* d_in, const int* in_sizes, int n_in,
                              void* d_out, int out_size)
{
    const float* state       = (const float*)d_in[0];
    const int*   rel_tokens  = (const int*)d_in[1];
    const int*   attr_tokens = (const int*)d_in[2];
    const float* table       = (const float*)d_in[3];
    const float* W_emb       = (const float*)d_in[4];
    const float* b_emb       = (const float*)d_in[5];
    const float* W_ih        = (const float*)d_in[6];
    const float* W_hh        = (const float*)d_in[7];
    const float* b_ih        = (const float*)d_in[8];
    const float* b_hh        = (const float*)d_in[9];
    const float* W1          = (const float*)d_in[10];
    const float* b1          = (const float*)d_in[11];
    const float* W2          = (const float*)d_in[12];
    const float* b2          = (const float*)d_in[13];
    const float* W3          = (const float*)d_in[14];
    const float* eps         = (const float*)d_in[16];
    float* out = (float*)d_out;

    __half *p2_h1, *p2_Whh, *p2_gh2;
    float *p_lpart;
    cudaGetSymbolAddress((void**)&p2_h1,   g2_h1);
    cudaGetSymbolAddress((void**)&p2_Whh,  g2_Whh);
    cudaGetSymbolAddress((void**)&p2_gh2,  g2_gh2);
    cudaGetSymbolAddress((void**)&p_lpart, g_lpart);

    cudaFuncSetAttribute(gemm_dual,
                         cudaFuncAttributeMaxDynamicSharedMemorySize, SMEM_DYN_H);
    cudaFuncSetAttribute(gemm_dual2,
                         cudaFuncAttributeMaxDynamicSharedMemorySize, SMEM_DYN_H);
    cudaFuncSetAttribute(gemm_logits_rel,
                         cudaFuncAttributeMaxDynamicSharedMemorySize, SMEM_DYN_H);

    // 0. convert table/Wemb/Wih + gh1 GEMV (W_hh read in fp32, independent)
    cvt_phase0<<<CVT0_ROWS + 384, 256>>>(table, W_emb, W_ih, state, W_hh, b_hh);
    // 1. GEMM1 (emb, 64 CTAs) + cvt W_hh (3072 rows) packed into the idle chip
    gemm1_cvtWhh<<<64 + 3072, 256, SMEM_DYN64>>>(b_emb, W_hh);
    // 2. GEMM2 (gi, 192 CTAs) + cvt W1/W2 (2048 rows) packed
    gemm2_cvtW12<<<192 + 2048, 256, SMEM_DYN64>>>(b_ih, W1, W2);
    // 3. h1_table (fp16 only)
    gru_h1_kernel<<<V, 256>>>(state);
    // 4. gh2_table[V,3H]
    gemm_hmma64<<<dim3(H3 / 64, V / 64), 256, SMEM_DYN64>>>(
        p2_h1, p2_Whh, b_hh, p2_gh2, H3);
    // 5. merged step-2 (rel + attr), all-fp16
    gru_step2_all<<<NREL + NATT, 256>>>(rel_tokens, attr_tokens);
    // 6. DUAL1: gh3 (768) + x1-attr (256)
    gemm_dual<<<1024, 256, SMEM_DYN_H>>>(b_hh, b1);
    // 7. rel step 3
    gru_step3_kernel<<<NREL, 256>>>(rel_tokens);
    // 8. DUAL2: x1-rel (256, drains first) + logits-attr (256)
    gemm_dual2<<<512, 256, SMEM_DYN_H>>>(b1, b2, W3, p_lpart);
    // 9. logits-rel (256)
    gemm_logits_rel<<<dim3(8, NREL / 128), 256, SMEM_DYN_H>>>(b2, W3, p_lpart);
    // 10. logits reduce + softmax + smoothing
    softmax_kernel<<<1, 1024>>>(eps, out);
}